// round 7
// baseline (speedup 1.0000x reference)
#include <cuda_runtime.h>
#include <cstdint>
#include <math.h>

#define FULLMASK 0xFFFFFFFFu

#define N_TOK 25600
#define C_DIM 256
#define WLEN  512
#define MW    51200     // 100 windows * 512
#define HEADS 8
#define DHEAD 32
#define HIDD  512

// ---------------- scratch (static device globals; no allocations) ----------
static __device__ float g_xin[N_TOK * C_DIM];
static __device__ float g_qkv[MW * 768];      // per-token QKV (25600*768 used); later aliased as projbuf
static __device__ float g_attn[MW * C_DIM];
static __device__ float g_x1[N_TOK * C_DIM];
static __device__ float g_hbuf[N_TOK * HIDD];
static __device__ float g_bnpart[2 * 200 * HIDD];
static __device__ float g_scale[HIDD];
static __device__ float g_beta[HIDD];
static __device__ float g_maskf[MW];
static __device__ int   g_cnt[N_TOK];
static __device__ int   g_inv[2 * N_TOK];
// tf32-rounded weight copies
static __device__ float g_wq[768 * 256];
static __device__ float g_wp[256 * 256];
static __device__ float g_w1[512 * 256];
static __device__ float g_w2[256 * 512];

// ---------------- helpers ---------------------------------------------------
__device__ __forceinline__ float to_tf32(float x) {
    unsigned r;
    asm("cvt.rna.tf32.f32 %0, %1;" : "=r"(r) : "f"(x));
    return __uint_as_float(r);
}
__device__ __forceinline__ float ex2(float x) {
    float r;
    asm("ex2.approx.f32 %0, %1;" : "=f"(r) : "f"(x));
    return r;
}
__device__ __forceinline__ void ldsm4(uint32_t* r, uint32_t addr) {
    asm volatile("ldmatrix.sync.aligned.m8n8.x4.shared.b16 {%0,%1,%2,%3}, [%4];"
                 : "=r"(r[0]), "=r"(r[1]), "=r"(r[2]), "=r"(r[3]) : "r"(addr));
}
__device__ __forceinline__ void ldsm2(uint32_t* r, uint32_t addr) {
    asm volatile("ldmatrix.sync.aligned.m8n8.x2.shared.b16 {%0,%1}, [%2];"
                 : "=r"(r[0]), "=r"(r[1]) : "r"(addr));
}
__device__ __forceinline__ void mma_tf32(float* c, const uint32_t* a, const uint32_t* b) {
    asm volatile(
        "mma.sync.aligned.m16n8k8.row.col.f32.tf32.tf32.f32 "
        "{%0,%1,%2,%3}, {%4,%5,%6,%7}, {%8,%9}, {%0,%1,%2,%3};"
        : "+f"(c[0]), "+f"(c[1]), "+f"(c[2]), "+f"(c[3])
        : "r"(a[0]), "r"(a[1]), "r"(a[2]), "r"(a[3]), "r"(b[0]), "r"(b[1]));
}
__device__ __forceinline__ void cp16(uint32_t smem, const void* g) {
    asm volatile("cp.async.cg.shared.global [%0], [%1], 16;" :: "r"(smem), "l"(g));
}

// ---------------- mask + inverse index from win_idx ------------------------
__global__ void mask_count_kernel(const int* __restrict__ win_idx,
                                  float* __restrict__ maskf,
                                  int* __restrict__ cnt,
                                  int* __restrict__ inv) {
    int r = blockIdx.x * 256 + threadIdx.x;
    if (r >= MW) return;
    int w = r & (WLEN - 1);
    bool valid = (w == 0 || win_idx[r] != win_idx[r - 1]);
    maskf[r] = valid ? 1.0f : 0.0f;
    if (valid) {
        int tok = win_idx[r];
        int slot = atomicAdd(&cnt[tok], 1);
        if (slot < 2) inv[tok * 2 + slot] = r;
    }
}

// ---------------- merged tf32 rounding of all 4 weights --------------------
__global__ void cvt_all_kernel(const float* __restrict__ s0, float* __restrict__ d0,
                               const float* __restrict__ s1, float* __restrict__ d1,
                               const float* __restrict__ s2, float* __restrict__ d2,
                               const float* __restrict__ s3, float* __restrict__ d3) {
    int i = blockIdx.x * 256 + threadIdx.x;   // 524288 total
    if (i < 196608)      d0[i] = to_tf32(s0[i]);
    else if (i < 262144) d1[i - 196608] = to_tf32(s1[i - 196608]);
    else if (i < 393216) d2[i - 262144] = to_tf32(s2[i - 262144]);
    else                 d3[i - 393216] = to_tf32(s3[i - 393216]);
}

// ---------------- LayerNorm over C=256 (tf32-rounded output) ---------------
__global__ __launch_bounds__(256) void ln_kernel(const float* __restrict__ in,
                                                 const float* __restrict__ w,
                                                 const float* __restrict__ b,
                                                 float* __restrict__ out,
                                                 int rows) {
    int warp = threadIdx.x >> 5, lane = threadIdx.x & 31;
    int row = blockIdx.x * 8 + warp;
    if (row >= rows) return;
    const float4* p = (const float4*)(in + (size_t)row * C_DIM);
    float4 v0 = p[lane * 2], v1 = p[lane * 2 + 1];
    float s = v0.x + v0.y + v0.z + v0.w + v1.x + v1.y + v1.z + v1.w;
    #pragma unroll
    for (int off = 16; off; off >>= 1) s += __shfl_xor_sync(FULLMASK, s, off);
    float mu = s * (1.0f / 256.0f);
    float d0 = v0.x - mu, d1 = v0.y - mu, d2 = v0.z - mu, d3 = v0.w - mu;
    float d4 = v1.x - mu, d5 = v1.y - mu, d6 = v1.z - mu, d7 = v1.w - mu;
    float s2 = d0*d0 + d1*d1 + d2*d2 + d3*d3 + d4*d4 + d5*d5 + d6*d6 + d7*d7;
    #pragma unroll
    for (int off = 16; off; off >>= 1) s2 += __shfl_xor_sync(FULLMASK, s2, off);
    float rs = rsqrtf(s2 * (1.0f / 256.0f) + 1e-5f);
    float4 w0 = ((const float4*)w)[lane * 2], w1 = ((const float4*)w)[lane * 2 + 1];
    float4 b0 = ((const float4*)b)[lane * 2], b1 = ((const float4*)b)[lane * 2 + 1];
    float4 o0, o1;
    o0.x = to_tf32(d0 * rs * w0.x + b0.x); o0.y = to_tf32(d1 * rs * w0.y + b0.y);
    o0.z = to_tf32(d2 * rs * w0.z + b0.z); o0.w = to_tf32(d3 * rs * w0.w + b0.w);
    o1.x = to_tf32(d4 * rs * w1.x + b1.x); o1.y = to_tf32(d5 * rs * w1.y + b1.y);
    o1.z = to_tf32(d6 * rs * w1.z + b1.z); o1.w = to_tf32(d7 * rs * w1.w + b1.w);
    float4* q = (float4*)(out + (size_t)row * C_DIM);
    q[lane * 2] = o0; q[lane * 2 + 1] = o1;
}

// ---------------- gather proj + x1 + LayerNorm2 (fused) --------------------
__global__ __launch_bounds__(256) void x1ln2_kernel(
    const float* __restrict__ x, const float* __restrict__ projbuf,
    const int* __restrict__ cnt, const int* __restrict__ inv,
    const float* __restrict__ w, const float* __restrict__ b,
    float* __restrict__ x1, float* __restrict__ out) {
    int warp = threadIdx.x >> 5, lane = threadIdx.x & 31;
    int row = blockIdx.x * 8 + warp;
    int c = cnt[row];
    const float4* xp = (const float4*)(x + (size_t)row * C_DIM);
    float4 v0 = xp[lane * 2], v1 = xp[lane * 2 + 1];
    float4 y0 = make_float4(0.f, 0.f, 0.f, 0.f), y1 = y0;
    if (c >= 1) {
        const float4* p = (const float4*)(projbuf + (size_t)inv[row * 2] * C_DIM);
        y0 = p[lane * 2]; y1 = p[lane * 2 + 1];
    }
    if (c >= 2) {
        const float4* p = (const float4*)(projbuf + (size_t)inv[row * 2 + 1] * C_DIM);
        float4 a = p[lane * 2], bq = p[lane * 2 + 1];
        y0.x += a.x; y0.y += a.y; y0.z += a.z; y0.w += a.w;
        y1.x += bq.x; y1.y += bq.y; y1.z += bq.z; y1.w += bq.w;
    }
    float ic = 1.0f / fmaxf((float)c, 1.0f);
    v0.x += y0.x * ic; v0.y += y0.y * ic; v0.z += y0.z * ic; v0.w += y0.w * ic;
    v1.x += y1.x * ic; v1.y += y1.y * ic; v1.z += y1.z * ic; v1.w += y1.w * ic;
    float4* xq = (float4*)(x1 + (size_t)row * C_DIM);
    xq[lane * 2] = v0; xq[lane * 2 + 1] = v1;
    float s = v0.x + v0.y + v0.z + v0.w + v1.x + v1.y + v1.z + v1.w;
    #pragma unroll
    for (int off = 16; off; off >>= 1) s += __shfl_xor_sync(FULLMASK, s, off);
    float mu = s * (1.0f / 256.0f);
    float d0 = v0.x - mu, d1 = v0.y - mu, d2 = v0.z - mu, d3 = v0.w - mu;
    float d4 = v1.x - mu, d5 = v1.y - mu, d6 = v1.z - mu, d7 = v1.w - mu;
    float s2 = d0*d0 + d1*d1 + d2*d2 + d3*d3 + d4*d4 + d5*d5 + d6*d6 + d7*d7;
    #pragma unroll
    for (int off = 16; off; off >>= 1) s2 += __shfl_xor_sync(FULLMASK, s2, off);
    float rs = rsqrtf(s2 * (1.0f / 256.0f) + 1e-5f);
    float4 w0 = ((const float4*)w)[lane * 2], w1 = ((const float4*)w)[lane * 2 + 1];
    float4 b0 = ((const float4*)b)[lane * 2], b1 = ((const float4*)b)[lane * 2 + 1];
    float4 o0, o1;
    o0.x = to_tf32(d0 * rs * w0.x + b0.x); o0.y = to_tf32(d1 * rs * w0.y + b0.y);
    o0.z = to_tf32(d2 * rs * w0.z + b0.z); o0.w = to_tf32(d3 * rs * w0.w + b0.w);
    o1.x = to_tf32(d4 * rs * w1.x + b1.x); o1.y = to_tf32(d5 * rs * w1.y + b1.y);
    o1.z = to_tf32(d6 * rs * w1.z + b1.z); o1.w = to_tf32(d7 * rs * w1.w + b1.w);
    float4* q = (float4*)(out + (size_t)row * C_DIM);
    q[lane * 2] = o0; q[lane * 2 + 1] = o1;
}

// ---------------- tf32 tensor-core NT GEMM ---------------------------------
// MODE 0: QKV  (per-token, no bias, tf32-rounded store)
// MODE 1: PROJ (bias, *mask, plain store to projbuf)
// MODE 2: FFN1 (bias, store)
// MODE 3: FFN2 (bias + residual, store)
#define GP 36
#define BUFW 9216
template <int MODE, int NC, int KD>
__global__ __launch_bounds__(256) void mma_gemm(
    const float* __restrict__ A, const float* __restrict__ Bw,
    const float* __restrict__ bias, const int* __restrict__ gidx,
    const float* __restrict__ maskf, const float* __restrict__ resid,
    float* __restrict__ Cout) {
    extern __shared__ float sm[];
    uint32_t smem_u32 = (uint32_t)__cvta_generic_to_shared(sm);
    const int tid = threadIdx.x, lane = tid & 31, warp = tid >> 5;
    const int wm = warp >> 2, wn = warp & 3;
    const int bm = blockIdx.y * 128, bn = blockIdx.x * 128;

    const int lrow = tid & 127;
    const bool isA = tid < 128;
    const float* gbase;
    if (isA) gbase = A + (size_t)(bm + lrow) * KD;
    else     gbase = Bw + (size_t)(bn + lrow) * KD;
    const uint32_t sdst = smem_u32 + (uint32_t)(((isA ? 0 : 4608) + lrow * GP) * 4);

    const int lr8 = lane & 7, sub = lane >> 3, lb = lane & 15;
    const uint32_t a_off = smem_u32 +
        (uint32_t)(((wm * 64 + (sub & 1) * 8 + lr8) * GP + (sub >> 1) * 4) * 4);
    const uint32_t b_off = smem_u32 +
        (uint32_t)((4608 + (wn * 32 + (lb & 7)) * GP + (lb >> 3) * 4) * 4);

    float acc[4][4][4];
    #pragma unroll
    for (int i = 0; i < 4; i++)
        #pragma unroll
        for (int j = 0; j < 4; j++)
            #pragma unroll
            for (int r = 0; r < 4; r++) acc[i][j][r] = 0.f;

    const int T = KD / 32;
    {
        const float* g = gbase;
        #pragma unroll
        for (int i = 0; i < 8; i++) cp16(sdst + i * 16, g + i * 4);
        asm volatile("cp.async.commit_group;");
    }
    for (int t = 0; t < T; t++) {
        if (t + 1 < T) {
            const float* g = gbase + (t + 1) * 32;
            uint32_t d = sdst + (uint32_t)(((t + 1) & 1) * BUFW * 4);
            #pragma unroll
            for (int i = 0; i < 8; i++) cp16(d + i * 16, g + i * 4);
            asm volatile("cp.async.commit_group;");
            asm volatile("cp.async.wait_group 1;");
        } else {
            asm volatile("cp.async.wait_group 0;");
        }
        __syncthreads();
        const uint32_t boff = (uint32_t)((t & 1) * BUFW * 4);
        #pragma unroll
        for (int ks = 0; ks < 4; ks++) {
            uint32_t a[4][4], b[4][2];
            #pragma unroll
            for (int i = 0; i < 4; i++)
                ldsm4(a[i], a_off + boff + i * 2304 + ks * 32);
            #pragma unroll
            for (int j = 0; j < 4; j++)
                ldsm2(b[j], b_off + boff + j * 1152 + ks * 32);
            #pragma unroll
            for (int i = 0; i < 4; i++)
                #pragma unroll
                for (int j = 0; j < 4; j++)
                    mma_tf32(acc[i][j], a[i], b[j]);
        }
        __syncthreads();
    }

    const int er = bm + wm * 64 + (lane >> 2);
    const int ec = bn + wn * 32 + (lane & 3) * 2;
    #pragma unroll
    for (int i = 0; i < 4; i++) {
        const int r0 = er + i * 16, r1 = r0 + 8;
        float mk0 = 0.f, mk1 = 0.f;
        if (MODE == 1) { mk0 = maskf[r0]; mk1 = maskf[r1]; }
        #pragma unroll
        for (int j = 0; j < 4; j++) {
            const int c = ec + j * 8;
            float v0 = acc[i][j][0], v1 = acc[i][j][1];
            float v2 = acc[i][j][2], v3 = acc[i][j][3];
            if (MODE == 0) {
                *(float2*)&Cout[(size_t)r0 * NC + c] =
                    make_float2(to_tf32(v0), to_tf32(v1));
                *(float2*)&Cout[(size_t)r1 * NC + c] =
                    make_float2(to_tf32(v2), to_tf32(v3));
            } else if (MODE == 1) {
                float b0 = bias[c], b1 = bias[c + 1];
                *(float2*)&Cout[(size_t)r0 * NC + c] =
                    make_float2((v0 + b0) * mk0, (v1 + b1) * mk0);
                *(float2*)&Cout[(size_t)r1 * NC + c] =
                    make_float2((v2 + b0) * mk1, (v3 + b1) * mk1);
            } else if (MODE == 2) {
                float b0 = bias[c], b1 = bias[c + 1];
                *(float2*)&Cout[(size_t)r0 * NC + c] = make_float2(v0 + b0, v1 + b1);
                *(float2*)&Cout[(size_t)r1 * NC + c] = make_float2(v2 + b0, v3 + b1);
            } else {
                float b0 = bias[c], b1 = bias[c + 1];
                float2 x0 = *(const float2*)&resid[(size_t)r0 * 256 + c];
                float2 x1v = *(const float2*)&resid[(size_t)r1 * 256 + c];
                *(float2*)&Cout[(size_t)r0 * NC + c] =
                    make_float2(v0 + b0 + x0.x, v1 + b1 + x0.y);
                *(float2*)&Cout[(size_t)r1 * NC + c] =
                    make_float2(v2 + b0 + x1v.x, v3 + b1 + x1v.y);
            }
        }
    }
}

// ---------------- tensor-core flash attention (no-max softmax) -------------
// QKV is now per-token; window rows are gathered through a smem idx table.
#define ATP 36
#define AT_KOFF (512 + 8 * 2304)
#define AT_SMEMW (AT_KOFF + 4 * 1152 + 512)   // + idx[512]
__global__ __launch_bounds__(256, 1) void attn_mma_kernel(
    const float* __restrict__ qkv, const int* __restrict__ win_idx,
    const float* __restrict__ maskf, float* __restrict__ attn) {
    extern __shared__ float sm[];
    const uint32_t smb = (uint32_t)__cvta_generic_to_shared(sm);
    const int m = blockIdx.x >> 3, h = blockIdx.x & 7;
    const int tid = threadIdx.x, lane = tid & 31, wp = tid >> 5;
    const int lr8 = lane & 7, sub = lane >> 3, lb = lane & 15;

    float* maskA = sm;
    float* Qw = sm + 512 + wp * 2304;
    int* idxs = (int*)(sm + AT_KOFF + 4 * 1152);

    // stage window indices + additive mask
    idxs[tid]       = win_idx[m * 512 + tid];
    idxs[tid + 256] = win_idx[m * 512 + tid + 256];
    for (int w = tid; w < 512; w += 256)
        maskA[w] = (maskf[m * 512 + w] != 0.f) ? 0.f : -1e30f;
    __syncthreads();

    const float* qbase = qkv + h * 32;

    // stage warp's 64 Q rows (gathered)
    for (int i = lane; i < 512; i += 32) {
        int row = i >> 3, c4 = (i & 7) * 4;
        int tok = idxs[wp * 64 + row];
        float4 v = *(const float4*)(qbase + (size_t)tok * 768 + c4);
        *(float4*)&Qw[row * ATP + c4] = v;
    }
    __syncwarp();
    uint32_t qf[4][4][4];
    {
        uint32_t qb = smb + (uint32_t)((512 + wp * 2304) * 4) +
                      (uint32_t)((((sub & 1) * 8 + lr8) * ATP + (sub >> 1) * 4) * 4);
        #pragma unroll
        for (int i = 0; i < 4; i++)
            #pragma unroll
            for (int ks = 0; ks < 4; ks++)
                ldsm4(qf[i][ks], qb + (uint32_t)(i * 16 * ATP * 4 + ks * 32));
    }
    __syncwarp();

    // prologue: K(0), Vt(0) (gathered)
    {
        int row = tid >> 3, c4 = (tid & 7) * 4;
        int tok = idxs[row];
        float4 kv = *(const float4*)(qbase + (size_t)tok * 768 + 256 + c4);
        *(float4*)&sm[AT_KOFF + row * ATP + c4] = kv;
        float4 vv = *(const float4*)(qbase + (size_t)tok * 768 + 512 + c4);
        sm[AT_KOFF + 2304 + (c4 + 0) * ATP + row] = vv.x;
        sm[AT_KOFF + 2304 + (c4 + 1) * ATP + row] = vv.y;
        sm[AT_KOFF + 2304 + (c4 + 2) * ATP + row] = vv.z;
        sm[AT_KOFF + 2304 + (c4 + 3) * ATP + row] = vv.w;
    }
    __syncthreads();

    float o[4][4][4];
    #pragma unroll
    for (int i = 0; i < 4; i++)
        #pragma unroll
        for (int j = 0; j < 4; j++)
            #pragma unroll
            for (int c = 0; c < 4; c++) o[i][j][c] = 0.f;
    float Ls[4][2];
    #pragma unroll
    for (int i = 0; i < 4; i++) { Ls[i][0] = 0.f; Ls[i][1] = 0.f; }
    const float SCL2 = 0.25503485900582243f;   // log2(e)/sqrt(32)
    const int ldrow = tid >> 3, ldc4 = (tid & 7) * 4;

    for (int kt = 0; kt < 16; kt++) {
        const int cb = kt & 1;
        float4 vpre;
        if (kt < 15) {
            int tok = idxs[(kt + 1) * 32 + ldrow];
            uint32_t d = smb + (uint32_t)((AT_KOFF + (1 - cb) * 1152 +
                                           ldrow * ATP + ldc4) * 4);
            cp16(d, qbase + (size_t)tok * 768 + 256 + ldc4);
            asm volatile("cp.async.commit_group;");
            vpre = *(const float4*)(qbase + (size_t)tok * 768 + 512 + ldc4);
        }

        // ---- S = Q . K^T ----
        float s[4][4][4];
        #pragma unroll
        for (int i = 0; i < 4; i++)
            #pragma unroll
            for (int j = 0; j < 4; j++)
                #pragma unroll
                for (int c = 0; c < 4; c++) s[i][j][c] = 0.f;
        {
            uint32_t kb = smb + (uint32_t)((AT_KOFF + cb * 1152) * 4) +
                          (uint32_t)(((lb & 7) * ATP + (lb >> 3) * 4) * 4);
            #pragma unroll
            for (int ks = 0; ks < 4; ks++) {
                uint32_t bf[4][2];
                #pragma unroll
                for (int j = 0; j < 4; j++)
                    ldsm2(bf[j], kb + (uint32_t)(j * 8 * ATP * 4 + ks * 32));
                #pragma unroll
                for (int i = 0; i < 4; i++)
                    #pragma unroll
                    for (int j = 0; j < 4; j++)
                        mma_tf32(s[i][j], qf[i][ks], bf[j]);
            }
        }

        // ---- p = 2^(s*SCL2 + mask), accumulate row sums in registers ----
        float mk[4][2];
        #pragma unroll
        for (int j = 0; j < 4; j++) {
            float2 mm = *(const float2*)&maskA[kt * 32 + j * 8 + 2 * (lane & 3)];
            mk[j][0] = mm.x; mk[j][1] = mm.y;
        }
        #pragma unroll
        for (int i = 0; i < 4; i++)
            #pragma unroll
            for (int j = 0; j < 4; j++)
                #pragma unroll
                for (int c = 0; c < 4; c++) {
                    float p = ex2(s[i][j][c] * SCL2 + mk[j][c & 1]);
                    s[i][j][c] = p;
                    Ls[i][c >> 1] += p;
                }

        // ---- store P (tf32-rounded) into warp-private buffer ----
        {
            int r = lane >> 2, q2 = 2 * (lane & 3);
            #pragma unroll
            for (int i = 0; i < 4; i++)
                #pragma unroll
                for (int j = 0; j < 4; j++) {
                    *(float2*)&Qw[(i * 16 + r) * ATP + j * 8 + q2] =
                        make_float2(to_tf32(s[i][j][0]), to_tf32(s[i][j][1]));
                    *(float2*)&Qw[(i * 16 + r + 8) * ATP + j * 8 + q2] =
                        make_float2(to_tf32(s[i][j][2]), to_tf32(s[i][j][3]));
                }
        }
        __syncwarp();

        // ---- O += P . V ----
        {
            uint32_t pb = smb + (uint32_t)((512 + wp * 2304) * 4) +
                          (uint32_t)((((sub & 1) * 8 + lr8) * ATP + (sub >> 1) * 4) * 4);
            uint32_t vb = smb + (uint32_t)((AT_KOFF + 2304 + cb * 1152) * 4) +
                          (uint32_t)(((lb & 7) * ATP + (lb >> 3) * 4) * 4);
            #pragma unroll
            for (int ks = 0; ks < 4; ks++) {
                uint32_t pf[4][4], vf[4][2];
                #pragma unroll
                for (int i = 0; i < 4; i++)
                    ldsm4(pf[i], pb + (uint32_t)(i * 16 * ATP * 4 + ks * 32));
                #pragma unroll
                for (int jd = 0; jd < 4; jd++)
                    ldsm2(vf[jd], vb + (uint32_t)(jd * 8 * ATP * 4 + ks * 32));
                #pragma unroll
                for (int i = 0; i < 4; i++)
                    #pragma unroll
                    for (int jd = 0; jd < 4; jd++)
                        mma_tf32(o[i][jd], pf[i], vf[jd]);
            }
        }
        __syncwarp();

        if (kt < 15) {
            float* vt = &sm[AT_KOFF + 2304 + (1 - cb) * 1152];
            vt[(ldc4 + 0) * ATP + ldrow] = vpre.x;
            vt[(ldc4 + 1) * ATP + ldrow] = vpre.y;
            vt[(ldc4 + 2) * ATP + ldrow] = vpre.z;
            vt[(ldc4 + 3) * ATP + ldrow] = vpre.w;
            asm volatile("cp.async.wait_group 0;");
        }
        __syncthreads();
    }

    // ---- final row-sum reduction + normalize + writeout ----
    #pragma unroll
    for (int i = 0; i < 4; i++)
        #pragma unroll
        for (int rh = 0; rh < 2; rh++) {
            float v = Ls[i][rh];
            v += __shfl_xor_sync(FULLMASK, v, 1);
            v += __shfl_xor_sync(FULLMASK, v, 2);
            Ls[i][rh] = v;
        }
    {
        int r = lane >> 2, q2 = 2 * (lane & 3);
        #pragma unroll
        for (int i = 0; i < 4; i++) {
            float inv0 = 1.f / Ls[i][0], inv1 = 1.f / Ls[i][1];
            int row0 = m * 512 + wp * 64 + i * 16 + r;
            #pragma unroll
            for (int jd = 0; jd < 4; jd++) {
                int col = h * 32 + jd * 8 + q2;
                *(float2*)&attn[(size_t)row0 * 256 + col] =
                    make_float2(to_tf32(o[i][jd][0] * inv0), to_tf32(o[i][jd][1] * inv0));
                *(float2*)&attn[(size_t)(row0 + 8) * 256 + col] =
                    make_float2(to_tf32(o[i][jd][2] * inv1), to_tf32(o[i][jd][3] * inv1));
            }
        }
    }
}

// ---------------- BatchNorm stats (two-pass, deterministic) ----------------
__global__ void bn_part_kernel(const float* __restrict__ h, float* __restrict__ part) {
    int col = threadIdx.x;
    int b = blockIdx.x;
    float s = 0.f, s2 = 0.f;
    const float* p = h + (size_t)b * 128 * HIDD + col;
    #pragma unroll 4
    for (int r = 0; r < 128; r++) {
        float v = p[(size_t)r * HIDD];
        s += v; s2 += v * v;
    }
    part[b * HIDD + col] = s;
    part[200 * HIDD + b * HIDD + col] = s2;
}

__global__ void bn_final_kernel(const float* __restrict__ part,
                                const float* __restrict__ bn_w,
                                const float* __restrict__ bn_b,
                                float* __restrict__ scale, float* __restrict__ beta) {
    int col = blockIdx.x * 256 + threadIdx.x;
    float s = 0.f, s2 = 0.f;
    for (int b = 0; b < 200; b++) {
        s += part[b * HIDD + col];
        s2 += part[200 * HIDD + b * HIDD + col];
    }
    float mu = s * (1.0f / 25600.0f);
    float var = s2 * (1.0f / 25600.0f) - mu * mu;
    float sc = bn_w[col] * rsqrtf(var + 1e-5f);
    scale[col] = sc;
    beta[col] = bn_b[col] - mu * sc;
}

// ---------------- apply BN+ReLU in place (float4, tf32-rounded) ------------
__global__ void bn_apply_kernel(float* __restrict__ h,
                                const float* __restrict__ scale,
                                const float* __restrict__ beta) {
    int i = blockIdx.x * 256 + threadIdx.x;    // float4 index
    int c = (i * 4) & (HIDD - 1);
    float4 v = ((float4*)h)[i];
    float4 sc = *(const float4*)&scale[c];
    float4 be = *(const float4*)&beta[c];
    v.x = to_tf32(fmaxf(0.f, v.x * sc.x + be.x));
    v.y = to_tf32(fmaxf(0.f, v.y * sc.y + be.y));
    v.z = to_tf32(fmaxf(0.f, v.z * sc.z + be.z));
    v.w = to_tf32(fmaxf(0.f, v.w * sc.w + be.w));
    ((float4*)h)[i] = v;
}

// ---------------- launch ----------------------------------------------------
extern "C" void kernel_launch(void* const* d_in, const int* in_sizes, int n_in,
                              void* d_out, int out_size) {
    (void)in_sizes; (void)n_in; (void)out_size;
    const float* x      = (const float*)d_in[0];
    const int*   widx   = (const int*)d_in[1];
    const float* ln1_w  = (const float*)d_in[3];
    const float* ln1_b  = (const float*)d_in[4];
    const float* w_qkv  = (const float*)d_in[5];
    const float* w_proj = (const float*)d_in[6];
    const float* b_proj = (const float*)d_in[7];
    const float* ln2_w  = (const float*)d_in[8];
    const float* ln2_b  = (const float*)d_in[9];
    const float* w1     = (const float*)d_in[10];
    const float* b1     = (const float*)d_in[11];
    const float* bn_w   = (const float*)d_in[12];
    const float* bn_b   = (const float*)d_in[13];
    const float* w2     = (const float*)d_in[14];
    const float* b2     = (const float*)d_in[15];
    float* out = (float*)d_out;

    float *xin, *qkv, *attn, *x1, *hbuf, *part, *scale, *beta, *maskf;
    float *wq, *wp, *tw1, *tw2;
    int *cnt, *inv;
    cudaGetSymbolAddress((void**)&xin,    g_xin);
    cudaGetSymbolAddress((void**)&qkv,    g_qkv);
    cudaGetSymbolAddress((void**)&attn,   g_attn);
    cudaGetSymbolAddress((void**)&x1,     g_x1);
    cudaGetSymbolAddress((void**)&hbuf,   g_hbuf);
    cudaGetSymbolAddress((void**)&part,   g_bnpart);
    cudaGetSymbolAddress((void**)&scale,  g_scale);
    cudaGetSymbolAddress((void**)&beta,   g_beta);
    cudaGetSymbolAddress((void**)&maskf,  g_maskf);
    cudaGetSymbolAddress((void**)&cnt,    g_cnt);
    cudaGetSymbolAddress((void**)&inv,    g_inv);
    cudaGetSymbolAddress((void**)&wq,     g_wq);
    cudaGetSymbolAddress((void**)&wp,     g_wp);
    cudaGetSymbolAddress((void**)&tw1,    g_w1);
    cudaGetSymbolAddress((void**)&tw2,    g_w2);
    // projbuf aliases the tail of g_qkv: per-token qkv uses only the first
    // 25600*768 floats; projbuf needs MW*256 — place it after the live region.
    float* projbuf = qkv + (size_t)N_TOK * 768;

    const int gemm_smem = 2 * BUFW * (int)sizeof(float);
    cudaFuncSetAttribute(mma_gemm<0, 768, 256>,
                         cudaFuncAttributeMaxDynamicSharedMemorySize, gemm_smem);
    cudaFuncSetAttribute(mma_gemm<1, 256, 256>,
                         cudaFuncAttributeMaxDynamicSharedMemorySize, gemm_smem);
    cudaFuncSetAttribute(mma_gemm<2, 512, 256>,
                         cudaFuncAttributeMaxDynamicSharedMemorySize, gemm_smem);
    cudaFuncSetAttribute(mma_gemm<3, 256, 512>,
                         cudaFuncAttributeMaxDynamicSharedMemorySize, gemm_smem);
    const int attn_smem = AT_SMEMW * (int)sizeof(float);
    cudaFuncSetAttribute(attn_mma_kernel,
                         cudaFuncAttributeMaxDynamicSharedMemorySize, attn_smem);

    cudaMemsetAsync(cnt, 0, N_TOK * sizeof(int));

    cvt_all_kernel<<<2048, 256>>>(w_qkv, wq, w_proj, wp, w1, tw1, w2, tw2);
    mask_count_kernel<<<MW / 256, 256>>>(widx, maskf, cnt, inv);
    ln_kernel<<<N_TOK / 8, 256>>>(x, ln1_w, ln1_b, xin, N_TOK);

    // per-token QKV: M = N_TOK (deduped; windows overlap 50%)
    mma_gemm<0, 768, 256><<<dim3(6, 200), 256, gemm_smem>>>(
        xin, wq, nullptr, nullptr, nullptr, nullptr, qkv);

    attn_mma_kernel<<<100 * HEADS, 256, attn_smem>>>(qkv, widx, maskf, attn);

    mma_gemm<1, 256, 256><<<dim3(2, 400), 256, gemm_smem>>>(
        attn, wp, b_proj, nullptr, maskf, nullptr, projbuf);

    x1ln2_kernel<<<N_TOK / 8, 256>>>(x, projbuf, cnt, inv, ln2_w, ln2_b, x1, xin);

    mma_gemm<2, 512, 256><<<dim3(4, 200), 256, gemm_smem>>>(
        xin, tw1, b1, nullptr, nullptr, nullptr, hbuf);

    bn_part_kernel<<<200, HIDD>>>(hbuf, part);
    bn_final_kernel<<<2, 256>>>(part, bn_w, bn_b, scale, beta);
    bn_apply_kernel<<<N_TOK * HIDD / 1024, 256>>>(hbuf, scale, beta);

    mma_gemm<3, 256, 512><<<dim3(2, 200), 256, gemm_smem>>>(
        hbuf, tw2, b2, nullptr, nullptr, x1, out);
}

// round 8
// speedup vs baseline: 1.3010x; 1.3010x over previous
#include <cuda_runtime.h>
#include <cstdint>
#include <math.h>

#define FULLMASK 0xFFFFFFFFu

#define N_TOK 25600
#define C_DIM 256
#define WLEN  512
#define MW    51200     // 100 windows * 512
#define HEADS 8
#define DHEAD 32
#define HIDD  512

// ---------------- scratch (static device globals; no allocations) ----------
static __device__ float g_xin[N_TOK * C_DIM];
static __device__ float g_qkv[MW * 768];      // QKV; later aliased as projbuf
static __device__ float g_attn[MW * C_DIM];
static __device__ float g_x1[N_TOK * C_DIM];
static __device__ float g_hbuf[N_TOK * HIDD];
static __device__ float g_bnpart[2 * 200 * HIDD];
static __device__ float g_scale[HIDD];
static __device__ float g_beta[HIDD];
static __device__ float g_maskf[MW];
static __device__ int   g_cnt[N_TOK];
static __device__ int   g_inv[2 * N_TOK];
// tf32-rounded weight copies
static __device__ float g_wq[768 * 256];
static __device__ float g_wp[256 * 256];
static __device__ float g_w1[512 * 256];
static __device__ float g_w2[256 * 512];

// ---------------- helpers ---------------------------------------------------
__device__ __forceinline__ float to_tf32(float x) {
    unsigned r;
    asm("cvt.rna.tf32.f32 %0, %1;" : "=r"(r) : "f"(x));
    return __uint_as_float(r);
}
__device__ __forceinline__ float ex2(float x) {
    float r;
    asm("ex2.approx.f32 %0, %1;" : "=f"(r) : "f"(x));
    return r;
}
__device__ __forceinline__ void ldsm4(uint32_t* r, uint32_t addr) {
    asm volatile("ldmatrix.sync.aligned.m8n8.x4.shared.b16 {%0,%1,%2,%3}, [%4];"
                 : "=r"(r[0]), "=r"(r[1]), "=r"(r[2]), "=r"(r[3]) : "r"(addr));
}
__device__ __forceinline__ void ldsm2(uint32_t* r, uint32_t addr) {
    asm volatile("ldmatrix.sync.aligned.m8n8.x2.shared.b16 {%0,%1}, [%2];"
                 : "=r"(r[0]), "=r"(r[1]) : "r"(addr));
}
__device__ __forceinline__ void mma_tf32(float* c, const uint32_t* a, const uint32_t* b) {
    asm volatile(
        "mma.sync.aligned.m16n8k8.row.col.f32.tf32.tf32.f32 "
        "{%0,%1,%2,%3}, {%4,%5,%6,%7}, {%8,%9}, {%0,%1,%2,%3};"
        : "+f"(c[0]), "+f"(c[1]), "+f"(c[2]), "+f"(c[3])
        : "r"(a[0]), "r"(a[1]), "r"(a[2]), "r"(a[3]), "r"(b[0]), "r"(b[1]));
}
__device__ __forceinline__ void cp16(uint32_t smem, const void* g) {
    asm volatile("cp.async.cg.shared.global [%0], [%1], 16;" :: "r"(smem), "l"(g));
}

// ---------------- mask + inverse index from win_idx ------------------------
__global__ void mask_count_kernel(const int* __restrict__ win_idx,
                                  float* __restrict__ maskf,
                                  int* __restrict__ cnt,
                                  int* __restrict__ inv) {
    int r = blockIdx.x * 256 + threadIdx.x;
    if (r >= MW) return;
    int w = r & (WLEN - 1);
    bool valid = (w == 0 || win_idx[r] != win_idx[r - 1]);
    maskf[r] = valid ? 1.0f : 0.0f;
    if (valid) {
        int tok = win_idx[r];
        int slot = atomicAdd(&cnt[tok], 1);
        if (slot < 2) inv[tok * 2 + slot] = r;
    }
}

// ---------------- merged tf32 rounding of all 4 weights --------------------
__global__ void cvt_all_kernel(const float* __restrict__ s0, float* __restrict__ d0,
                               const float* __restrict__ s1, float* __restrict__ d1,
                               const float* __restrict__ s2, float* __restrict__ d2,
                               const float* __restrict__ s3, float* __restrict__ d3) {
    int i = blockIdx.x * 256 + threadIdx.x;   // 524288 total
    if (i < 196608)      d0[i] = to_tf32(s0[i]);
    else if (i < 262144) d1[i - 196608] = to_tf32(s1[i - 196608]);
    else if (i < 393216) d2[i - 262144] = to_tf32(s2[i - 262144]);
    else                 d3[i - 393216] = to_tf32(s3[i - 393216]);
}

// ---------------- LayerNorm over C=256 (tf32-rounded output) ---------------
__global__ __launch_bounds__(256) void ln_kernel(const float* __restrict__ in,
                                                 const float* __restrict__ w,
                                                 const float* __restrict__ b,
                                                 float* __restrict__ out,
                                                 int rows) {
    int warp = threadIdx.x >> 5, lane = threadIdx.x & 31;
    int row = blockIdx.x * 8 + warp;
    if (row >= rows) return;
    const float4* p = (const float4*)(in + (size_t)row * C_DIM);
    float4 v0 = p[lane * 2], v1 = p[lane * 2 + 1];
    float s = v0.x + v0.y + v0.z + v0.w + v1.x + v1.y + v1.z + v1.w;
    #pragma unroll
    for (int off = 16; off; off >>= 1) s += __shfl_xor_sync(FULLMASK, s, off);
    float mu = s * (1.0f / 256.0f);
    float d0 = v0.x - mu, d1 = v0.y - mu, d2 = v0.z - mu, d3 = v0.w - mu;
    float d4 = v1.x - mu, d5 = v1.y - mu, d6 = v1.z - mu, d7 = v1.w - mu;
    float s2 = d0*d0 + d1*d1 + d2*d2 + d3*d3 + d4*d4 + d5*d5 + d6*d6 + d7*d7;
    #pragma unroll
    for (int off = 16; off; off >>= 1) s2 += __shfl_xor_sync(FULLMASK, s2, off);
    float rs = rsqrtf(s2 * (1.0f / 256.0f) + 1e-5f);
    float4 w0 = ((const float4*)w)[lane * 2], w1 = ((const float4*)w)[lane * 2 + 1];
    float4 b0 = ((const float4*)b)[lane * 2], b1 = ((const float4*)b)[lane * 2 + 1];
    float4 o0, o1;
    o0.x = to_tf32(d0 * rs * w0.x + b0.x); o0.y = to_tf32(d1 * rs * w0.y + b0.y);
    o0.z = to_tf32(d2 * rs * w0.z + b0.z); o0.w = to_tf32(d3 * rs * w0.w + b0.w);
    o1.x = to_tf32(d4 * rs * w1.x + b1.x); o1.y = to_tf32(d5 * rs * w1.y + b1.y);
    o1.z = to_tf32(d6 * rs * w1.z + b1.z); o1.w = to_tf32(d7 * rs * w1.w + b1.w);
    float4* q = (float4*)(out + (size_t)row * C_DIM);
    q[lane * 2] = o0; q[lane * 2 + 1] = o1;
}

// ---------------- gather proj + x1 + LayerNorm2 (fused) --------------------
__global__ __launch_bounds__(256) void x1ln2_kernel(
    const float* __restrict__ x, const float* __restrict__ projbuf,
    const int* __restrict__ cnt, const int* __restrict__ inv,
    const float* __restrict__ w, const float* __restrict__ b,
    float* __restrict__ x1, float* __restrict__ out) {
    int warp = threadIdx.x >> 5, lane = threadIdx.x & 31;
    int row = blockIdx.x * 8 + warp;
    int c = cnt[row];
    const float4* xp = (const float4*)(x + (size_t)row * C_DIM);
    float4 v0 = xp[lane * 2], v1 = xp[lane * 2 + 1];
    float4 y0 = make_float4(0.f, 0.f, 0.f, 0.f), y1 = y0;
    if (c >= 1) {
        const float4* p = (const float4*)(projbuf + (size_t)inv[row * 2] * C_DIM);
        y0 = p[lane * 2]; y1 = p[lane * 2 + 1];
    }
    if (c >= 2) {
        const float4* p = (const float4*)(projbuf + (size_t)inv[row * 2 + 1] * C_DIM);
        float4 a = p[lane * 2], bq = p[lane * 2 + 1];
        y0.x += a.x; y0.y += a.y; y0.z += a.z; y0.w += a.w;
        y1.x += bq.x; y1.y += bq.y; y1.z += bq.z; y1.w += bq.w;
    }
    float ic = 1.0f / fmaxf((float)c, 1.0f);
    v0.x += y0.x * ic; v0.y += y0.y * ic; v0.z += y0.z * ic; v0.w += y0.w * ic;
    v1.x += y1.x * ic; v1.y += y1.y * ic; v1.z += y1.z * ic; v1.w += y1.w * ic;
    float4* xq = (float4*)(x1 + (size_t)row * C_DIM);
    xq[lane * 2] = v0; xq[lane * 2 + 1] = v1;
    float s = v0.x + v0.y + v0.z + v0.w + v1.x + v1.y + v1.z + v1.w;
    #pragma unroll
    for (int off = 16; off; off >>= 1) s += __shfl_xor_sync(FULLMASK, s, off);
    float mu = s * (1.0f / 256.0f);
    float d0 = v0.x - mu, d1 = v0.y - mu, d2 = v0.z - mu, d3 = v0.w - mu;
    float d4 = v1.x - mu, d5 = v1.y - mu, d6 = v1.z - mu, d7 = v1.w - mu;
    float s2 = d0*d0 + d1*d1 + d2*d2 + d3*d3 + d4*d4 + d5*d5 + d6*d6 + d7*d7;
    #pragma unroll
    for (int off = 16; off; off >>= 1) s2 += __shfl_xor_sync(FULLMASK, s2, off);
    float rs = rsqrtf(s2 * (1.0f / 256.0f) + 1e-5f);
    float4 w0 = ((const float4*)w)[lane * 2], w1 = ((const float4*)w)[lane * 2 + 1];
    float4 b0 = ((const float4*)b)[lane * 2], b1 = ((const float4*)b)[lane * 2 + 1];
    float4 o0, o1;
    o0.x = to_tf32(d0 * rs * w0.x + b0.x); o0.y = to_tf32(d1 * rs * w0.y + b0.y);
    o0.z = to_tf32(d2 * rs * w0.z + b0.z); o0.w = to_tf32(d3 * rs * w0.w + b0.w);
    o1.x = to_tf32(d4 * rs * w1.x + b1.x); o1.y = to_tf32(d5 * rs * w1.y + b1.y);
    o1.z = to_tf32(d6 * rs * w1.z + b1.z); o1.w = to_tf32(d7 * rs * w1.w + b1.w);
    float4* q = (float4*)(out + (size_t)row * C_DIM);
    q[lane * 2] = o0; q[lane * 2 + 1] = o1;
}

// ---------------- tf32 tensor-core NT GEMM (BM=128, BN=64) -----------------
// 8 warps (2x4), warp tile 64x16, acc=32 regs -> 3 CTAs/SM for latency hiding.
// MODE 0: QKV  (A gathered via gidx, no bias, tf32-rounded store)
// MODE 1: PROJ (bias, *mask, plain store to projbuf)
// MODE 2: FFN1 (bias, store)
// MODE 3: FFN2 (bias + residual, store)
#define GP 36
#define BUFW 6912       // words per stage: A 128*36 + B 64*36
template <int MODE, int NC, int KD>
__global__ __launch_bounds__(256) void mma_gemm(
    const float* __restrict__ A, const float* __restrict__ Bw,
    const float* __restrict__ bias, const int* __restrict__ gidx,
    const float* __restrict__ maskf, const float* __restrict__ resid,
    float* __restrict__ Cout) {
    extern __shared__ float sm[];
    uint32_t smem_u32 = (uint32_t)__cvta_generic_to_shared(sm);
    const int tid = threadIdx.x, lane = tid & 31, warp = tid >> 5;
    const int wm = warp >> 2, wn = warp & 3;
    const int bm = blockIdx.y * 128, bn = blockIdx.x * 64;

    // loaders: threads 0-127 -> A rows (32 floats each); 128-255 -> B half-rows
    const bool isA = tid < 128;
    const float* gbase;
    uint32_t sdst;
    if (isA) {
        int lrow = tid;
        int arow = (MODE == 0) ? gidx[bm + lrow] : (bm + lrow);
        gbase = A + (size_t)arow * KD;
        sdst = smem_u32 + (uint32_t)((lrow * GP) * 4);
    } else {
        int t2 = tid - 128;
        int brow = t2 >> 1, half = t2 & 1;
        gbase = Bw + (size_t)(bn + brow) * KD + half * 16;
        sdst = smem_u32 + (uint32_t)((4608 + brow * GP + half * 16) * 4);
    }

    const int lr8 = lane & 7, sub = lane >> 3, lb = lane & 15;
    const uint32_t a_off = smem_u32 +
        (uint32_t)(((wm * 64 + (sub & 1) * 8 + lr8) * GP + (sub >> 1) * 4) * 4);
    const uint32_t b_off = smem_u32 +
        (uint32_t)((4608 + (wn * 16 + (lb & 7)) * GP + (lb >> 3) * 4) * 4);

    float acc[4][2][4];
    #pragma unroll
    for (int i = 0; i < 4; i++)
        #pragma unroll
        for (int j = 0; j < 2; j++)
            #pragma unroll
            for (int r = 0; r < 4; r++) acc[i][j][r] = 0.f;

    const int T = KD / 32;
    {
        const float* g = gbase;
        if (isA) {
            #pragma unroll
            for (int i = 0; i < 8; i++) cp16(sdst + i * 16, g + i * 4);
        } else {
            #pragma unroll
            for (int i = 0; i < 4; i++) cp16(sdst + i * 16, g + i * 4);
        }
        asm volatile("cp.async.commit_group;");
    }
    for (int t = 0; t < T; t++) {
        if (t + 1 < T) {
            const float* g = gbase + (t + 1) * 32;
            uint32_t d = sdst + (uint32_t)(((t + 1) & 1) * BUFW * 4);
            if (isA) {
                #pragma unroll
                for (int i = 0; i < 8; i++) cp16(d + i * 16, g + i * 4);
            } else {
                #pragma unroll
                for (int i = 0; i < 4; i++) cp16(d + i * 16, g + i * 4);
            }
            asm volatile("cp.async.commit_group;");
            asm volatile("cp.async.wait_group 1;");
        } else {
            asm volatile("cp.async.wait_group 0;");
        }
        __syncthreads();
        const uint32_t boff = (uint32_t)((t & 1) * BUFW * 4);
        #pragma unroll
        for (int ks = 0; ks < 4; ks++) {
            uint32_t a[4][4], b[2][2];
            #pragma unroll
            for (int i = 0; i < 4; i++)
                ldsm4(a[i], a_off + boff + i * 2304 + ks * 32);
            #pragma unroll
            for (int j = 0; j < 2; j++)
                ldsm2(b[j], b_off + boff + j * 1152 + ks * 32);
            #pragma unroll
            for (int i = 0; i < 4; i++)
                #pragma unroll
                for (int j = 0; j < 2; j++)
                    mma_tf32(acc[i][j], a[i], b[j]);
        }
        __syncthreads();
    }

    const int er = bm + wm * 64 + (lane >> 2);
    const int ec = bn + wn * 16 + (lane & 3) * 2;
    #pragma unroll
    for (int i = 0; i < 4; i++) {
        const int r0 = er + i * 16, r1 = r0 + 8;
        float mk0 = 0.f, mk1 = 0.f;
        if (MODE == 1) { mk0 = maskf[r0]; mk1 = maskf[r1]; }
        #pragma unroll
        for (int j = 0; j < 2; j++) {
            const int c = ec + j * 8;
            float v0 = acc[i][j][0], v1 = acc[i][j][1];
            float v2 = acc[i][j][2], v3 = acc[i][j][3];
            if (MODE == 0) {
                *(float2*)&Cout[(size_t)r0 * NC + c] =
                    make_float2(to_tf32(v0), to_tf32(v1));
                *(float2*)&Cout[(size_t)r1 * NC + c] =
                    make_float2(to_tf32(v2), to_tf32(v3));
            } else if (MODE == 1) {
                float b0 = bias[c], b1 = bias[c + 1];
                *(float2*)&Cout[(size_t)r0 * NC + c] =
                    make_float2((v0 + b0) * mk0, (v1 + b1) * mk0);
                *(float2*)&Cout[(size_t)r1 * NC + c] =
                    make_float2((v2 + b0) * mk1, (v3 + b1) * mk1);
            } else if (MODE == 2) {
                float b0 = bias[c], b1 = bias[c + 1];
                *(float2*)&Cout[(size_t)r0 * NC + c] = make_float2(v0 + b0, v1 + b1);
                *(float2*)&Cout[(size_t)r1 * NC + c] = make_float2(v2 + b0, v3 + b1);
            } else {
                float b0 = bias[c], b1 = bias[c + 1];
                float2 x0 = *(const float2*)&resid[(size_t)r0 * 256 + c];
                float2 x1v = *(const float2*)&resid[(size_t)r1 * 256 + c];
                *(float2*)&Cout[(size_t)r0 * NC + c] =
                    make_float2(v0 + b0 + x0.x, v1 + b1 + x0.y);
                *(float2*)&Cout[(size_t)r1 * NC + c] =
                    make_float2(v2 + b0 + x1v.x, v3 + b1 + x1v.y);
            }
        }
    }
}

// ---------------- tensor-core flash attention (no-max softmax) -------------
// Contiguous per-window qkv (R6 layout — gather indirection regressed in R7).
#define ATP 36
#define AT_KOFF (512 + 8 * 2304)
#define AT_SMEMW (AT_KOFF + 4 * 1152)
__global__ __launch_bounds__(256, 1) void attn_mma_kernel(
    const float* __restrict__ qkv, const float* __restrict__ maskf,
    float* __restrict__ attn) {
    extern __shared__ float sm[];
    const uint32_t smb = (uint32_t)__cvta_generic_to_shared(sm);
    const int m = blockIdx.x >> 3, h = blockIdx.x & 7;
    const int tid = threadIdx.x, lane = tid & 31, wp = tid >> 5;
    const int lr8 = lane & 7, sub = lane >> 3, lb = lane & 15;

    float* maskA = sm;
    float* Qw = sm + 512 + wp * 2304;

    const float* qg = qkv + (size_t)m * 512 * 768 + h * 32;
    const float* kg = qg + 256;
    const float* vg = qg + 512;

    for (int w = tid; w < 512; w += 256)
        maskA[w] = (maskf[m * 512 + w] != 0.f) ? 0.f : -1e30f;

    for (int i = lane; i < 512; i += 32) {
        int row = i >> 3, c4 = (i & 7) * 4;
        float4 v = *(const float4*)(qg + (size_t)(wp * 64 + row) * 768 + c4);
        *(float4*)&Qw[row * ATP + c4] = v;
    }
    __syncwarp();
    uint32_t qf[4][4][4];
    {
        uint32_t qb = smb + (uint32_t)((512 + wp * 2304) * 4) +
                      (uint32_t)((((sub & 1) * 8 + lr8) * ATP + (sub >> 1) * 4) * 4);
        #pragma unroll
        for (int i = 0; i < 4; i++)
            #pragma unroll
            for (int ks = 0; ks < 4; ks++)
                ldsm4(qf[i][ks], qb + (uint32_t)(i * 16 * ATP * 4 + ks * 32));
    }
    __syncwarp();

    {
        int row = tid >> 3, c4 = (tid & 7) * 4;
        float4 kv = *(const float4*)(kg + (size_t)row * 768 + c4);
        *(float4*)&sm[AT_KOFF + row * ATP + c4] = kv;
        float4 vv = *(const float4*)(vg + (size_t)row * 768 + c4);
        sm[AT_KOFF + 2304 + (c4 + 0) * ATP + row] = vv.x;
        sm[AT_KOFF + 2304 + (c4 + 1) * ATP + row] = vv.y;
        sm[AT_KOFF + 2304 + (c4 + 2) * ATP + row] = vv.z;
        sm[AT_KOFF + 2304 + (c4 + 3) * ATP + row] = vv.w;
    }
    __syncthreads();

    float o[4][4][4];
    #pragma unroll
    for (int i = 0; i < 4; i++)
        #pragma unroll
        for (int j = 0; j < 4; j++)
            #pragma unroll
            for (int c = 0; c < 4; c++) o[i][j][c] = 0.f;
    float Ls[4][2];
    #pragma unroll
    for (int i = 0; i < 4; i++) { Ls[i][0] = 0.f; Ls[i][1] = 0.f; }
    const float SCL2 = 0.25503485900582243f;   // log2(e)/sqrt(32)
    const int ldrow = tid >> 3, ldc4 = (tid & 7) * 4;

    for (int kt = 0; kt < 16; kt++) {
        const int cb = kt & 1;
        float4 vpre;
        if (kt < 15) {
            uint32_t d = smb + (uint32_t)((AT_KOFF + (1 - cb) * 1152 +
                                           ldrow * ATP + ldc4) * 4);
            cp16(d, kg + (size_t)((kt + 1) * 32 + ldrow) * 768 + ldc4);
            asm volatile("cp.async.commit_group;");
            vpre = *(const float4*)(vg + (size_t)((kt + 1) * 32 + ldrow) * 768 + ldc4);
        }

        float s[4][4][4];
        #pragma unroll
        for (int i = 0; i < 4; i++)
            #pragma unroll
            for (int j = 0; j < 4; j++)
                #pragma unroll
                for (int c = 0; c < 4; c++) s[i][j][c] = 0.f;
        {
            uint32_t kb = smb + (uint32_t)((AT_KOFF + cb * 1152) * 4) +
                          (uint32_t)(((lb & 7) * ATP + (lb >> 3) * 4) * 4);
            #pragma unroll
            for (int ks = 0; ks < 4; ks++) {
                uint32_t bf[4][2];
                #pragma unroll
                for (int j = 0; j < 4; j++)
                    ldsm2(bf[j], kb + (uint32_t)(j * 8 * ATP * 4 + ks * 32));
                #pragma unroll
                for (int i = 0; i < 4; i++)
                    #pragma unroll
                    for (int j = 0; j < 4; j++)
                        mma_tf32(s[i][j], qf[i][ks], bf[j]);
            }
        }

        float mk[4][2];
        #pragma unroll
        for (int j = 0; j < 4; j++) {
            float2 mm = *(const float2*)&maskA[kt * 32 + j * 8 + 2 * (lane & 3)];
            mk[j][0] = mm.x; mk[j][1] = mm.y;
        }
        #pragma unroll
        for (int i = 0; i < 4; i++)
            #pragma unroll
            for (int j = 0; j < 4; j++)
                #pragma unroll
                for (int c = 0; c < 4; c++) {
                    float p = ex2(s[i][j][c] * SCL2 + mk[j][c & 1]);
                    s[i][j][c] = p;
                    Ls[i][c >> 1] += p;
                }

        {
            int r = lane >> 2, q2 = 2 * (lane & 3);
            #pragma unroll
            for (int i = 0; i < 4; i++)
                #pragma unroll
                for (int j = 0; j < 4; j++) {
                    *(float2*)&Qw[(i * 16 + r) * ATP + j * 8 + q2] =
                        make_float2(to_tf32(s[i][j][0]), to_tf32(s[i][j][1]));
                    *(float2*)&Qw[(i * 16 + r + 8) * ATP + j * 8 + q2] =
                        make_float2(to_tf32(s[i][j][2]), to_tf32(s[i][j][3]));
                }
        }
        __syncwarp();

        {
            uint32_t pb = smb + (uint32_t)((512 + wp * 2304) * 4) +
                          (uint32_t)((((sub & 1) * 8 + lr8) * ATP + (sub >> 1) * 4) * 4);
            uint32_t vb = smb + (uint32_t)((AT_KOFF + 2304 + cb * 1152) * 4) +
                          (uint32_t)(((lb & 7) * ATP + (lb >> 3) * 4) * 4);
            #pragma unroll
            for (int ks = 0; ks < 4; ks++) {
                uint32_t pf[4][4], vf[4][2];
                #pragma unroll
                for (int i = 0; i < 4; i++)
                    ldsm4(pf[i], pb + (uint32_t)(i * 16 * ATP * 4 + ks * 32));
                #pragma unroll
                for (int jd = 0; jd < 4; jd++)
                    ldsm2(vf[jd], vb + (uint32_t)(jd * 8 * ATP * 4 + ks * 32));
                #pragma unroll
                for (int i = 0; i < 4; i++)
                    #pragma unroll
                    for (int jd = 0; jd < 4; jd++)
                        mma_tf32(o[i][jd], pf[i], vf[jd]);
            }
        }
        __syncwarp();

        if (kt < 15) {
            float* vt = &sm[AT_KOFF + 2304 + (1 - cb) * 1152];
            vt[(ldc4 + 0) * ATP + ldrow] = vpre.x;
            vt[(ldc4 + 1) * ATP + ldrow] = vpre.y;
            vt[(ldc4 + 2) * ATP + ldrow] = vpre.z;
            vt[(ldc4 + 3) * ATP + ldrow] = vpre.w;
            asm volatile("cp.async.wait_group 0;");
        }
        __syncthreads();
    }

    #pragma unroll
    for (int i = 0; i < 4; i++)
        #pragma unroll
        for (int rh = 0; rh < 2; rh++) {
            float v = Ls[i][rh];
            v += __shfl_xor_sync(FULLMASK, v, 1);
            v += __shfl_xor_sync(FULLMASK, v, 2);
            Ls[i][rh] = v;
        }
    {
        int r = lane >> 2, q2 = 2 * (lane & 3);
        #pragma unroll
        for (int i = 0; i < 4; i++) {
            float inv0 = 1.f / Ls[i][0], inv1 = 1.f / Ls[i][1];
            int row0 = m * 512 + wp * 64 + i * 16 + r;
            #pragma unroll
            for (int jd = 0; jd < 4; jd++) {
                int col = h * 32 + jd * 8 + q2;
                *(float2*)&attn[(size_t)row0 * 256 + col] =
                    make_float2(to_tf32(o[i][jd][0] * inv0), to_tf32(o[i][jd][1] * inv0));
                *(float2*)&attn[(size_t)(row0 + 8) * 256 + col] =
                    make_float2(to_tf32(o[i][jd][2] * inv1), to_tf32(o[i][jd][3] * inv1));
            }
        }
    }
}

// ---------------- BatchNorm stats (two-pass, deterministic) ----------------
__global__ void bn_part_kernel(const float* __restrict__ h, float* __restrict__ part) {
    int col = threadIdx.x;
    int b = blockIdx.x;
    float s = 0.f, s2 = 0.f;
    const float* p = h + (size_t)b * 128 * HIDD + col;
    #pragma unroll 4
    for (int r = 0; r < 128; r++) {
        float v = p[(size_t)r * HIDD];
        s += v; s2 += v * v;
    }
    part[b * HIDD + col] = s;
    part[200 * HIDD + b * HIDD + col] = s2;
}

__global__ void bn_final_kernel(const float* __restrict__ part,
                                const float* __restrict__ bn_w,
                                const float* __restrict__ bn_b,
                                float* __restrict__ scale, float* __restrict__ beta) {
    int col = blockIdx.x * 256 + threadIdx.x;
    float s = 0.f, s2 = 0.f;
    for (int b = 0; b < 200; b++) {
        s += part[b * HIDD + col];
        s2 += part[200 * HIDD + b * HIDD + col];
    }
    float mu = s * (1.0f / 25600.0f);
    float var = s2 * (1.0f / 25600.0f) - mu * mu;
    float sc = bn_w[col] * rsqrtf(var + 1e-5f);
    scale[col] = sc;
    beta[col] = bn_b[col] - mu * sc;
}

// ---------------- apply BN+ReLU in place (float4, tf32-rounded) ------------
__global__ void bn_apply_kernel(float* __restrict__ h,
                                const float* __restrict__ scale,
                                const float* __restrict__ beta) {
    int i = blockIdx.x * 256 + threadIdx.x;    // float4 index
    int c = (i * 4) & (HIDD - 1);
    float4 v = ((float4*)h)[i];
    float4 sc = *(const float4*)&scale[c];
    float4 be = *(const float4*)&beta[c];
    v.x = to_tf32(fmaxf(0.f, v.x * sc.x + be.x));
    v.y = to_tf32(fmaxf(0.f, v.y * sc.y + be.y));
    v.z = to_tf32(fmaxf(0.f, v.z * sc.z + be.z));
    v.w = to_tf32(fmaxf(0.f, v.w * sc.w + be.w));
    ((float4*)h)[i] = v;
}

// ---------------- launch ----------------------------------------------------
extern "C" void kernel_launch(void* const* d_in, const int* in_sizes, int n_in,
                              void* d_out, int out_size) {
    (void)in_sizes; (void)n_in; (void)out_size;
    const float* x      = (const float*)d_in[0];
    const int*   widx   = (const int*)d_in[1];
    const float* ln1_w  = (const float*)d_in[3];
    const float* ln1_b  = (const float*)d_in[4];
    const float* w_qkv  = (const float*)d_in[5];
    const float* w_proj = (const float*)d_in[6];
    const float* b_proj = (const float*)d_in[7];
    const float* ln2_w  = (const float*)d_in[8];
    const float* ln2_b  = (const float*)d_in[9];
    const float* w1     = (const float*)d_in[10];
    const float* b1     = (const float*)d_in[11];
    const float* bn_w   = (const float*)d_in[12];
    const float* bn_b   = (const float*)d_in[13];
    const float* w2     = (const float*)d_in[14];
    const float* b2     = (const float*)d_in[15];
    float* out = (float*)d_out;

    float *xin, *qkv, *attn, *x1, *hbuf, *part, *scale, *beta, *maskf;
    float *wq, *wp, *tw1, *tw2;
    int *cnt, *inv;
    cudaGetSymbolAddress((void**)&xin,    g_xin);
    cudaGetSymbolAddress((void**)&qkv,    g_qkv);
    cudaGetSymbolAddress((void**)&attn,   g_attn);
    cudaGetSymbolAddress((void**)&x1,     g_x1);
    cudaGetSymbolAddress((void**)&hbuf,   g_hbuf);
    cudaGetSymbolAddress((void**)&part,   g_bnpart);
    cudaGetSymbolAddress((void**)&scale,  g_scale);
    cudaGetSymbolAddress((void**)&beta,   g_beta);
    cudaGetSymbolAddress((void**)&maskf,  g_maskf);
    cudaGetSymbolAddress((void**)&cnt,    g_cnt);
    cudaGetSymbolAddress((void**)&inv,    g_inv);
    cudaGetSymbolAddress((void**)&wq,     g_wq);
    cudaGetSymbolAddress((void**)&wp,     g_wp);
    cudaGetSymbolAddress((void**)&tw1,    g_w1);
    cudaGetSymbolAddress((void**)&tw2,    g_w2);
    float* projbuf = qkv;   // alias: qkv dead after attention

    const int gemm_smem = 2 * BUFW * (int)sizeof(float);   // 55296
    cudaFuncSetAttribute(mma_gemm<0, 768, 256>,
                         cudaFuncAttributeMaxDynamicSharedMemorySize, gemm_smem);
    cudaFuncSetAttribute(mma_gemm<1, 256, 256>,
                         cudaFuncAttributeMaxDynamicSharedMemorySize, gemm_smem);
    cudaFuncSetAttribute(mma_gemm<2, 512, 256>,
                         cudaFuncAttributeMaxDynamicSharedMemorySize, gemm_smem);
    cudaFuncSetAttribute(mma_gemm<3, 256, 512>,
                         cudaFuncAttributeMaxDynamicSharedMemorySize, gemm_smem);
    const int attn_smem = AT_SMEMW * (int)sizeof(float);
    cudaFuncSetAttribute(attn_mma_kernel,
                         cudaFuncAttributeMaxDynamicSharedMemorySize, attn_smem);

    cudaMemsetAsync(cnt, 0, N_TOK * sizeof(int));

    cvt_all_kernel<<<2048, 256>>>(w_qkv, wq, w_proj, wp, w1, tw1, w2, tw2);
    mask_count_kernel<<<MW / 256, 256>>>(widx, maskf, cnt, inv);
    ln_kernel<<<N_TOK / 8, 256>>>(x, ln1_w, ln1_b, xin, N_TOK);

    mma_gemm<0, 768, 256><<<dim3(12, 400), 256, gemm_smem>>>(
        xin, wq, nullptr, widx, nullptr, nullptr, qkv);

    attn_mma_kernel<<<100 * HEADS, 256, attn_smem>>>(qkv, maskf, attn);

    mma_gemm<1, 256, 256><<<dim3(4, 400), 256, gemm_smem>>>(
        attn, wp, b_proj, nullptr, maskf, nullptr, projbuf);

    x1ln2_kernel<<<N_TOK / 8, 256>>>(x, projbuf, cnt, inv, ln2_w, ln2_b, x1, xin);

    mma_gemm<2, 512, 256><<<dim3(8, 200), 256, gemm_smem>>>(
        xin, tw1, b1, nullptr, nullptr, nullptr, hbuf);

    bn_part_kernel<<<200, HIDD>>>(hbuf, part);
    bn_final_kernel<<<2, 256>>>(part, bn_w, bn_b, scale, beta);
    bn_apply_kernel<<<N_TOK * HIDD / 1024, 256>>>(hbuf, scale, beta);

    mma_gemm<3, 256, 512><<<dim3(4, 200), 256, gemm_smem>>>(
        hbuf, tw2, b2, nullptr, nullptr, x1, out);
}

// round 9
// speedup vs baseline: 1.5311x; 1.1768x over previous
#include <cuda_runtime.h>
#include <cstdint>
#include <math.h>

#define FULLMASK 0xFFFFFFFFu

#define N_TOK 25600
#define C_DIM 256
#define WLEN  512
#define MW    51200     // 100 windows * 512
#define HEADS 8
#define DHEAD 32
#define HIDD  512

// ---------------- scratch (static device globals; no allocations) ----------
static __device__ float g_xin[N_TOK * C_DIM];
static __device__ float g_qkv[MW * 768];      // QKV; later aliased as projbuf
static __device__ float g_attn[MW * C_DIM];
static __device__ float g_x1[N_TOK * C_DIM];
static __device__ float g_hbuf[N_TOK * HIDD];
static __device__ float g_bnpart[2 * 200 * HIDD];
static __device__ float g_scale[HIDD];
static __device__ float g_beta[HIDD];
static __device__ float g_maskf[MW];
static __device__ int   g_cnt[N_TOK];
static __device__ int   g_inv[2 * N_TOK];
// tf32-rounded weight copies
static __device__ float g_wq[768 * 256];
static __device__ float g_wp[256 * 256];
static __device__ float g_w1[512 * 256];
static __device__ float g_w2[256 * 512];

// ---------------- helpers ---------------------------------------------------
__device__ __forceinline__ float to_tf32(float x) {
    unsigned r;
    asm("cvt.rna.tf32.f32 %0, %1;" : "=r"(r) : "f"(x));
    return __uint_as_float(r);
}
__device__ __forceinline__ float ex2(float x) {
    float r;
    asm("ex2.approx.f32 %0, %1;" : "=f"(r) : "f"(x));
    return r;
}
__device__ __forceinline__ void ldsm4(uint32_t* r, uint32_t addr) {
    asm volatile("ldmatrix.sync.aligned.m8n8.x4.shared.b16 {%0,%1,%2,%3}, [%4];"
                 : "=r"(r[0]), "=r"(r[1]), "=r"(r[2]), "=r"(r[3]) : "r"(addr));
}
__device__ __forceinline__ void ldsm2(uint32_t* r, uint32_t addr) {
    asm volatile("ldmatrix.sync.aligned.m8n8.x2.shared.b16 {%0,%1}, [%2];"
                 : "=r"(r[0]), "=r"(r[1]) : "r"(addr));
}
__device__ __forceinline__ void mma_tf32(float* c, const uint32_t* a, const uint32_t* b) {
    asm volatile(
        "mma.sync.aligned.m16n8k8.row.col.f32.tf32.tf32.f32 "
        "{%0,%1,%2,%3}, {%4,%5,%6,%7}, {%8,%9}, {%0,%1,%2,%3};"
        : "+f"(c[0]), "+f"(c[1]), "+f"(c[2]), "+f"(c[3])
        : "r"(a[0]), "r"(a[1]), "r"(a[2]), "r"(a[3]), "r"(b[0]), "r"(b[1]));
}
__device__ __forceinline__ void cp16(uint32_t smem, const void* g) {
    asm volatile("cp.async.cg.shared.global [%0], [%1], 16;" :: "r"(smem), "l"(g));
}
__device__ __forceinline__ void cp16ca(uint32_t smem, const void* g) {
    asm volatile("cp.async.ca.shared.global [%0], [%1], 16;" :: "r"(smem), "l"(g));
}

// ---------------- mask + inverse index from win_idx ------------------------
__global__ void mask_count_kernel(const int* __restrict__ win_idx,
                                  float* __restrict__ maskf,
                                  int* __restrict__ cnt,
                                  int* __restrict__ inv) {
    int r = blockIdx.x * 256 + threadIdx.x;
    if (r >= MW) return;
    int w = r & (WLEN - 1);
    bool valid = (w == 0 || win_idx[r] != win_idx[r - 1]);
    maskf[r] = valid ? 1.0f : 0.0f;
    if (valid) {
        int tok = win_idx[r];
        int slot = atomicAdd(&cnt[tok], 1);
        if (slot < 2) inv[tok * 2 + slot] = r;
    }
}

// ---------------- merged tf32 rounding of all 4 weights --------------------
__global__ void cvt_all_kernel(const float* __restrict__ s0, float* __restrict__ d0,
                               const float* __restrict__ s1, float* __restrict__ d1,
                               const float* __restrict__ s2, float* __restrict__ d2,
                               const float* __restrict__ s3, float* __restrict__ d3) {
    int i = blockIdx.x * 256 + threadIdx.x;   // 524288 total
    if (i < 196608)      d0[i] = to_tf32(s0[i]);
    else if (i < 262144) d1[i - 196608] = to_tf32(s1[i - 196608]);
    else if (i < 393216) d2[i - 262144] = to_tf32(s2[i - 262144]);
    else                 d3[i - 393216] = to_tf32(s3[i - 393216]);
}

// ---------------- LayerNorm over C=256 (tf32-rounded output) ---------------
__global__ __launch_bounds__(256) void ln_kernel(const float* __restrict__ in,
                                                 const float* __restrict__ w,
                                                 const float* __restrict__ b,
                                                 float* __restrict__ out,
                                                 int rows) {
    int warp = threadIdx.x >> 5, lane = threadIdx.x & 31;
    int row = blockIdx.x * 8 + warp;
    if (row >= rows) return;
    const float4* p = (const float4*)(in + (size_t)row * C_DIM);
    float4 v0 = p[lane * 2], v1 = p[lane * 2 + 1];
    float s = v0.x + v0.y + v0.z + v0.w + v1.x + v1.y + v1.z + v1.w;
    #pragma unroll
    for (int off = 16; off; off >>= 1) s += __shfl_xor_sync(FULLMASK, s, off);
    float mu = s * (1.0f / 256.0f);
    float d0 = v0.x - mu, d1 = v0.y - mu, d2 = v0.z - mu, d3 = v0.w - mu;
    float d4 = v1.x - mu, d5 = v1.y - mu, d6 = v1.z - mu, d7 = v1.w - mu;
    float s2 = d0*d0 + d1*d1 + d2*d2 + d3*d3 + d4*d4 + d5*d5 + d6*d6 + d7*d7;
    #pragma unroll
    for (int off = 16; off; off >>= 1) s2 += __shfl_xor_sync(FULLMASK, s2, off);
    float rs = rsqrtf(s2 * (1.0f / 256.0f) + 1e-5f);
    float4 w0 = ((const float4*)w)[lane * 2], w1 = ((const float4*)w)[lane * 2 + 1];
    float4 b0 = ((const float4*)b)[lane * 2], b1 = ((const float4*)b)[lane * 2 + 1];
    float4 o0, o1;
    o0.x = to_tf32(d0 * rs * w0.x + b0.x); o0.y = to_tf32(d1 * rs * w0.y + b0.y);
    o0.z = to_tf32(d2 * rs * w0.z + b0.z); o0.w = to_tf32(d3 * rs * w0.w + b0.w);
    o1.x = to_tf32(d4 * rs * w1.x + b1.x); o1.y = to_tf32(d5 * rs * w1.y + b1.y);
    o1.z = to_tf32(d6 * rs * w1.z + b1.z); o1.w = to_tf32(d7 * rs * w1.w + b1.w);
    float4* q = (float4*)(out + (size_t)row * C_DIM);
    q[lane * 2] = o0; q[lane * 2 + 1] = o1;
}

// ---------------- gather proj + x1 + LayerNorm2 (fused) --------------------
__global__ __launch_bounds__(256) void x1ln2_kernel(
    const float* __restrict__ x, const float* __restrict__ projbuf,
    const int* __restrict__ cnt, const int* __restrict__ inv,
    const float* __restrict__ w, const float* __restrict__ b,
    float* __restrict__ x1, float* __restrict__ out) {
    int warp = threadIdx.x >> 5, lane = threadIdx.x & 31;
    int row = blockIdx.x * 8 + warp;
    int c = cnt[row];
    const float4* xp = (const float4*)(x + (size_t)row * C_DIM);
    float4 v0 = xp[lane * 2], v1 = xp[lane * 2 + 1];
    float4 y0 = make_float4(0.f, 0.f, 0.f, 0.f), y1 = y0;
    if (c >= 1) {
        const float4* p = (const float4*)(projbuf + (size_t)inv[row * 2] * C_DIM);
        y0 = p[lane * 2]; y1 = p[lane * 2 + 1];
    }
    if (c >= 2) {
        const float4* p = (const float4*)(projbuf + (size_t)inv[row * 2 + 1] * C_DIM);
        float4 a = p[lane * 2], bq = p[lane * 2 + 1];
        y0.x += a.x; y0.y += a.y; y0.z += a.z; y0.w += a.w;
        y1.x += bq.x; y1.y += bq.y; y1.z += bq.z; y1.w += bq.w;
    }
    float ic = 1.0f / fmaxf((float)c, 1.0f);
    v0.x += y0.x * ic; v0.y += y0.y * ic; v0.z += y0.z * ic; v0.w += y0.w * ic;
    v1.x += y1.x * ic; v1.y += y1.y * ic; v1.z += y1.z * ic; v1.w += y1.w * ic;
    float4* xq = (float4*)(x1 + (size_t)row * C_DIM);
    xq[lane * 2] = v0; xq[lane * 2 + 1] = v1;
    float s = v0.x + v0.y + v0.z + v0.w + v1.x + v1.y + v1.z + v1.w;
    #pragma unroll
    for (int off = 16; off; off >>= 1) s += __shfl_xor_sync(FULLMASK, s, off);
    float mu = s * (1.0f / 256.0f);
    float d0 = v0.x - mu, d1 = v0.y - mu, d2 = v0.z - mu, d3 = v0.w - mu;
    float d4 = v1.x - mu, d5 = v1.y - mu, d6 = v1.z - mu, d7 = v1.w - mu;
    float s2 = d0*d0 + d1*d1 + d2*d2 + d3*d3 + d4*d4 + d5*d5 + d6*d6 + d7*d7;
    #pragma unroll
    for (int off = 16; off; off >>= 1) s2 += __shfl_xor_sync(FULLMASK, s2, off);
    float rs = rsqrtf(s2 * (1.0f / 256.0f) + 1e-5f);
    float4 w0 = ((const float4*)w)[lane * 2], w1 = ((const float4*)w)[lane * 2 + 1];
    float4 b0 = ((const float4*)b)[lane * 2], b1 = ((const float4*)b)[lane * 2 + 1];
    float4 o0, o1;
    o0.x = to_tf32(d0 * rs * w0.x + b0.x); o0.y = to_tf32(d1 * rs * w0.y + b0.y);
    o0.z = to_tf32(d2 * rs * w0.z + b0.z); o0.w = to_tf32(d3 * rs * w0.w + b0.w);
    o1.x = to_tf32(d4 * rs * w1.x + b1.x); o1.y = to_tf32(d5 * rs * w1.y + b1.y);
    o1.z = to_tf32(d6 * rs * w1.z + b1.z); o1.w = to_tf32(d7 * rs * w1.w + b1.w);
    float4* q = (float4*)(out + (size_t)row * C_DIM);
    q[lane * 2] = o0; q[lane * 2 + 1] = o1;
}

// ---------------- tf32 tensor-core NT GEMM (BM=128, BN=128) ----------------
// 3-stage cp.async pipeline, ONE __syncthreads per k-tile.
// B (weights) loaded with cp.async.ca (L1-cached, ~400x reuse); A with .cg.
// MODE 0: QKV  (A gathered via gidx, no bias, tf32-rounded store)
// MODE 1: PROJ (bias, *mask, plain store to projbuf)
// MODE 2: FFN1 (bias, store)
// MODE 3: FFN2 (bias + residual, store)
#define GP 36
#define BUFW 9216       // words per stage (A 128*36 + B 128*36)
#define NSTAGE 3
template <int MODE, int NC, int KD>
__global__ __launch_bounds__(256) void mma_gemm(
    const float* __restrict__ A, const float* __restrict__ Bw,
    const float* __restrict__ bias, const int* __restrict__ gidx,
    const float* __restrict__ maskf, const float* __restrict__ resid,
    float* __restrict__ Cout) {
    extern __shared__ float sm[];
    uint32_t smem_u32 = (uint32_t)__cvta_generic_to_shared(sm);
    const int tid = threadIdx.x, lane = tid & 31, warp = tid >> 5;
    const int wm = warp >> 2, wn = warp & 3;
    const int bm = blockIdx.y * 128, bn = blockIdx.x * 128;

    // loaders: threads 0-127 load A rows, 128-255 load B rows (32 floats each)
    const int lrow = tid & 127;
    const bool isA = tid < 128;
    const float* gbase;
    if (isA) {
        int arow = (MODE == 0) ? gidx[bm + lrow] : (bm + lrow);
        gbase = A + (size_t)arow * KD;
    } else {
        gbase = Bw + (size_t)(bn + lrow) * KD;
    }
    const uint32_t sdst = smem_u32 + (uint32_t)(((isA ? 0 : 4608) + lrow * GP) * 4);

    const int lr8 = lane & 7, sub = lane >> 3, lb = lane & 15;
    const uint32_t a_off = smem_u32 +
        (uint32_t)(((wm * 64 + (sub & 1) * 8 + lr8) * GP + (sub >> 1) * 4) * 4);
    const uint32_t b_off = smem_u32 +
        (uint32_t)((4608 + (wn * 32 + (lb & 7)) * GP + (lb >> 3) * 4) * 4);

    float acc[4][4][4];
    #pragma unroll
    for (int i = 0; i < 4; i++)
        #pragma unroll
        for (int j = 0; j < 4; j++)
            #pragma unroll
            for (int r = 0; r < 4; r++) acc[i][j][r] = 0.f;

    const int T = KD / 32;
    // prologue: tiles 0..NSTAGE-2
    #pragma unroll
    for (int ps = 0; ps < NSTAGE - 1; ps++) {
        const float* g = gbase + ps * 32;
        uint32_t d = sdst + (uint32_t)(ps * BUFW * 4);
        if (isA) {
            #pragma unroll
            for (int i = 0; i < 8; i++) cp16(d + i * 16, g + i * 4);
        } else {
            #pragma unroll
            for (int i = 0; i < 8; i++) cp16ca(d + i * 16, g + i * 4);
        }
        asm volatile("cp.async.commit_group;");
    }

    int buf = 0, nbuf = NSTAGE - 1;
    for (int t = 0; t < T; t++) {
        asm volatile("cp.async.wait_group %0;" :: "n"(NSTAGE - 2));
        __syncthreads();

        const uint32_t boff = (uint32_t)(buf * BUFW * 4);
        #pragma unroll
        for (int ks = 0; ks < 4; ks++) {
            uint32_t a[4][4], b[4][2];
            #pragma unroll
            for (int i = 0; i < 4; i++)
                ldsm4(a[i], a_off + boff + i * 2304 + ks * 32);
            #pragma unroll
            for (int j = 0; j < 4; j++)
                ldsm2(b[j], b_off + boff + j * 1152 + ks * 32);
            #pragma unroll
            for (int i = 0; i < 4; i++)
                #pragma unroll
                for (int j = 0; j < 4; j++)
                    mma_tf32(acc[i][j], a[i], b[j]);
        }

        // prefetch tile t+NSTAGE-1 into nbuf (safe: nbuf != current read buf,
        // and all warps passed this iter's barrier -> done reading nbuf)
        if (t + NSTAGE - 1 < T) {
            const float* g = gbase + (t + NSTAGE - 1) * 32;
            uint32_t d = sdst + (uint32_t)(nbuf * BUFW * 4);
            if (isA) {
                #pragma unroll
                for (int i = 0; i < 8; i++) cp16(d + i * 16, g + i * 4);
            } else {
                #pragma unroll
                for (int i = 0; i < 8; i++) cp16ca(d + i * 16, g + i * 4);
            }
        }
        asm volatile("cp.async.commit_group;");
        buf = (buf + 1) % NSTAGE;
        nbuf = (nbuf + 1) % NSTAGE;
    }

    const int er = bm + wm * 64 + (lane >> 2);
    const int ec = bn + wn * 32 + (lane & 3) * 2;
    #pragma unroll
    for (int i = 0; i < 4; i++) {
        const int r0 = er + i * 16, r1 = r0 + 8;
        float mk0 = 0.f, mk1 = 0.f;
        if (MODE == 1) { mk0 = maskf[r0]; mk1 = maskf[r1]; }
        #pragma unroll
        for (int j = 0; j < 4; j++) {
            const int c = ec + j * 8;
            float v0 = acc[i][j][0], v1 = acc[i][j][1];
            float v2 = acc[i][j][2], v3 = acc[i][j][3];
            if (MODE == 0) {
                *(float2*)&Cout[(size_t)r0 * NC + c] =
                    make_float2(to_tf32(v0), to_tf32(v1));
                *(float2*)&Cout[(size_t)r1 * NC + c] =
                    make_float2(to_tf32(v2), to_tf32(v3));
            } else if (MODE == 1) {
                float b0 = bias[c], b1 = bias[c + 1];
                *(float2*)&Cout[(size_t)r0 * NC + c] =
                    make_float2((v0 + b0) * mk0, (v1 + b1) * mk0);
                *(float2*)&Cout[(size_t)r1 * NC + c] =
                    make_float2((v2 + b0) * mk1, (v3 + b1) * mk1);
            } else if (MODE == 2) {
                float b0 = bias[c], b1 = bias[c + 1];
                *(float2*)&Cout[(size_t)r0 * NC + c] = make_float2(v0 + b0, v1 + b1);
                *(float2*)&Cout[(size_t)r1 * NC + c] = make_float2(v2 + b0, v3 + b1);
            } else {
                float b0 = bias[c], b1 = bias[c + 1];
                float2 x0 = *(const float2*)&resid[(size_t)r0 * 256 + c];
                float2 x1v = *(const float2*)&resid[(size_t)r1 * 256 + c];
                *(float2*)&Cout[(size_t)r0 * NC + c] =
                    make_float2(v0 + b0 + x0.x, v1 + b1 + x0.y);
                *(float2*)&Cout[(size_t)r1 * NC + c] =
                    make_float2(v2 + b0 + x1v.x, v3 + b1 + x1v.y);
            }
        }
    }
}

// ---------------- tensor-core flash attention (no-max softmax) -------------
#define ATP 36
#define AT_KOFF (512 + 8 * 2304)
#define AT_SMEMW (AT_KOFF + 4 * 1152)
__global__ __launch_bounds__(256, 1) void attn_mma_kernel(
    const float* __restrict__ qkv, const float* __restrict__ maskf,
    float* __restrict__ attn) {
    extern __shared__ float sm[];
    const uint32_t smb = (uint32_t)__cvta_generic_to_shared(sm);
    const int m = blockIdx.x >> 3, h = blockIdx.x & 7;
    const int tid = threadIdx.x, lane = tid & 31, wp = tid >> 5;
    const int lr8 = lane & 7, sub = lane >> 3, lb = lane & 15;

    float* maskA = sm;
    float* Qw = sm + 512 + wp * 2304;

    const float* qg = qkv + (size_t)m * 512 * 768 + h * 32;
    const float* kg = qg + 256;
    const float* vg = qg + 512;

    for (int w = tid; w < 512; w += 256)
        maskA[w] = (maskf[m * 512 + w] != 0.f) ? 0.f : -1e30f;

    for (int i = lane; i < 512; i += 32) {
        int row = i >> 3, c4 = (i & 7) * 4;
        float4 v = *(const float4*)(qg + (size_t)(wp * 64 + row) * 768 + c4);
        *(float4*)&Qw[row * ATP + c4] = v;
    }
    __syncwarp();
    uint32_t qf[4][4][4];
    {
        uint32_t qb = smb + (uint32_t)((512 + wp * 2304) * 4) +
                      (uint32_t)((((sub & 1) * 8 + lr8) * ATP + (sub >> 1) * 4) * 4);
        #pragma unroll
        for (int i = 0; i < 4; i++)
            #pragma unroll
            for (int ks = 0; ks < 4; ks++)
                ldsm4(qf[i][ks], qb + (uint32_t)(i * 16 * ATP * 4 + ks * 32));
    }
    __syncwarp();

    {
        int row = tid >> 3, c4 = (tid & 7) * 4;
        float4 kv = *(const float4*)(kg + (size_t)row * 768 + c4);
        *(float4*)&sm[AT_KOFF + row * ATP + c4] = kv;
        float4 vv = *(const float4*)(vg + (size_t)row * 768 + c4);
        sm[AT_KOFF + 2304 + (c4 + 0) * ATP + row] = vv.x;
        sm[AT_KOFF + 2304 + (c4 + 1) * ATP + row] = vv.y;
        sm[AT_KOFF + 2304 + (c4 + 2) * ATP + row] = vv.z;
        sm[AT_KOFF + 2304 + (c4 + 3) * ATP + row] = vv.w;
    }
    __syncthreads();

    float o[4][4][4];
    #pragma unroll
    for (int i = 0; i < 4; i++)
        #pragma unroll
        for (int j = 0; j < 4; j++)
            #pragma unroll
            for (int c = 0; c < 4; c++) o[i][j][c] = 0.f;
    float Ls[4][2];
    #pragma unroll
    for (int i = 0; i < 4; i++) { Ls[i][0] = 0.f; Ls[i][1] = 0.f; }
    const float SCL2 = 0.25503485900582243f;   // log2(e)/sqrt(32)
    const int ldrow = tid >> 3, ldc4 = (tid & 7) * 4;

    for (int kt = 0; kt < 16; kt++) {
        const int cb = kt & 1;
        float4 vpre;
        if (kt < 15) {
            uint32_t d = smb + (uint32_t)((AT_KOFF + (1 - cb) * 1152 +
                                           ldrow * ATP + ldc4) * 4);
            cp16(d, kg + (size_t)((kt + 1) * 32 + ldrow) * 768 + ldc4);
            asm volatile("cp.async.commit_group;");
            vpre = *(const float4*)(vg + (size_t)((kt + 1) * 32 + ldrow) * 768 + ldc4);
        }

        float s[4][4][4];
        #pragma unroll
        for (int i = 0; i < 4; i++)
            #pragma unroll
            for (int j = 0; j < 4; j++)
                #pragma unroll
                for (int c = 0; c < 4; c++) s[i][j][c] = 0.f;
        {
            uint32_t kb = smb + (uint32_t)((AT_KOFF + cb * 1152) * 4) +
                          (uint32_t)(((lb & 7) * ATP + (lb >> 3) * 4) * 4);
            #pragma unroll
            for (int ks = 0; ks < 4; ks++) {
                uint32_t bf[4][2];
                #pragma unroll
                for (int j = 0; j < 4; j++)
                    ldsm2(bf[j], kb + (uint32_t)(j * 8 * ATP * 4 + ks * 32));
                #pragma unroll
                for (int i = 0; i < 4; i++)
                    #pragma unroll
                    for (int j = 0; j < 4; j++)
                        mma_tf32(s[i][j], qf[i][ks], bf[j]);
            }
        }

        float mk[4][2];
        #pragma unroll
        for (int j = 0; j < 4; j++) {
            float2 mm = *(const float2*)&maskA[kt * 32 + j * 8 + 2 * (lane & 3)];
            mk[j][0] = mm.x; mk[j][1] = mm.y;
        }
        #pragma unroll
        for (int i = 0; i < 4; i++)
            #pragma unroll
            for (int j = 0; j < 4; j++)
                #pragma unroll
                for (int c = 0; c < 4; c++) {
                    float p = ex2(s[i][j][c] * SCL2 + mk[j][c & 1]);
                    s[i][j][c] = p;
                    Ls[i][c >> 1] += p;
                }

        {
            int r = lane >> 2, q2 = 2 * (lane & 3);
            #pragma unroll
            for (int i = 0; i < 4; i++)
                #pragma unroll
                for (int j = 0; j < 4; j++) {
                    *(float2*)&Qw[(i * 16 + r) * ATP + j * 8 + q2] =
                        make_float2(to_tf32(s[i][j][0]), to_tf32(s[i][j][1]));
                    *(float2*)&Qw[(i * 16 + r + 8) * ATP + j * 8 + q2] =
                        make_float2(to_tf32(s[i][j][2]), to_tf32(s[i][j][3]));
                }
        }
        __syncwarp();

        {
            uint32_t pb = smb + (uint32_t)((512 + wp * 2304) * 4) +
                          (uint32_t)((((sub & 1) * 8 + lr8) * ATP + (sub >> 1) * 4) * 4);
            uint32_t vb = smb + (uint32_t)((AT_KOFF + 2304 + cb * 1152) * 4) +
                          (uint32_t)(((lb & 7) * ATP + (lb >> 3) * 4) * 4);
            #pragma unroll
            for (int ks = 0; ks < 4; ks++) {
                uint32_t pf[4][4], vf[4][2];
                #pragma unroll
                for (int i = 0; i < 4; i++)
                    ldsm4(pf[i], pb + (uint32_t)(i * 16 * ATP * 4 + ks * 32));
                #pragma unroll
                for (int jd = 0; jd < 4; jd++)
                    ldsm2(vf[jd], vb + (uint32_t)(jd * 8 * ATP * 4 + ks * 32));
                #pragma unroll
                for (int i = 0; i < 4; i++)
                    #pragma unroll
                    for (int jd = 0; jd < 4; jd++)
                        mma_tf32(o[i][jd], pf[i], vf[jd]);
            }
        }
        __syncwarp();

        if (kt < 15) {
            float* vt = &sm[AT_KOFF + 2304 + (1 - cb) * 1152];
            vt[(ldc4 + 0) * ATP + ldrow] = vpre.x;
            vt[(ldc4 + 1) * ATP + ldrow] = vpre.y;
            vt[(ldc4 + 2) * ATP + ldrow] = vpre.z;
            vt[(ldc4 + 3) * ATP + ldrow] = vpre.w;
            asm volatile("cp.async.wait_group 0;");
        }
        __syncthreads();
    }

    #pragma unroll
    for (int i = 0; i < 4; i++)
        #pragma unroll
        for (int rh = 0; rh < 2; rh++) {
            float v = Ls[i][rh];
            v += __shfl_xor_sync(FULLMASK, v, 1);
            v += __shfl_xor_sync(FULLMASK, v, 2);
            Ls[i][rh] = v;
        }
    {
        int r = lane >> 2, q2 = 2 * (lane & 3);
        #pragma unroll
        for (int i = 0; i < 4; i++) {
            float inv0 = 1.f / Ls[i][0], inv1 = 1.f / Ls[i][1];
            int row0 = m * 512 + wp * 64 + i * 16 + r;
            #pragma unroll
            for (int jd = 0; jd < 4; jd++) {
                int col = h * 32 + jd * 8 + q2;
                *(float2*)&attn[(size_t)row0 * 256 + col] =
                    make_float2(to_tf32(o[i][jd][0] * inv0), to_tf32(o[i][jd][1] * inv0));
                *(float2*)&attn[(size_t)(row0 + 8) * 256 + col] =
                    make_float2(to_tf32(o[i][jd][2] * inv1), to_tf32(o[i][jd][3] * inv1));
            }
        }
    }
}

// ---------------- BatchNorm stats (two-pass, deterministic) ----------------
__global__ void bn_part_kernel(const float* __restrict__ h, float* __restrict__ part) {
    int col = threadIdx.x;
    int b = blockIdx.x;
    float s = 0.f, s2 = 0.f;
    const float* p = h + (size_t)b * 128 * HIDD + col;
    #pragma unroll 4
    for (int r = 0; r < 128; r++) {
        float v = p[(size_t)r * HIDD];
        s += v; s2 += v * v;
    }
    part[b * HIDD + col] = s;
    part[200 * HIDD + b * HIDD + col] = s2;
}

__global__ void bn_final_kernel(const float* __restrict__ part,
                                const float* __restrict__ bn_w,
                                const float* __restrict__ bn_b,
                                float* __restrict__ scale, float* __restrict__ beta) {
    int col = blockIdx.x * 256 + threadIdx.x;
    float s = 0.f, s2 = 0.f;
    for (int b = 0; b < 200; b++) {
        s += part[b * HIDD + col];
        s2 += part[200 * HIDD + b * HIDD + col];
    }
    float mu = s * (1.0f / 25600.0f);
    float var = s2 * (1.0f / 25600.0f) - mu * mu;
    float sc = bn_w[col] * rsqrtf(var + 1e-5f);
    scale[col] = sc;
    beta[col] = bn_b[col] - mu * sc;
}

// ---------------- apply BN+ReLU in place (float4, tf32-rounded) ------------
__global__ void bn_apply_kernel(float* __restrict__ h,
                                const float* __restrict__ scale,
                                const float* __restrict__ beta) {
    int i = blockIdx.x * 256 + threadIdx.x;    // float4 index
    int c = (i * 4) & (HIDD - 1);
    float4 v = ((float4*)h)[i];
    float4 sc = *(const float4*)&scale[c];
    float4 be = *(const float4*)&beta[c];
    v.x = to_tf32(fmaxf(0.f, v.x * sc.x + be.x));
    v.y = to_tf32(fmaxf(0.f, v.y * sc.y + be.y));
    v.z = to_tf32(fmaxf(0.f, v.z * sc.z + be.z));
    v.w = to_tf32(fmaxf(0.f, v.w * sc.w + be.w));
    ((float4*)h)[i] = v;
}

// ---------------- launch ----------------------------------------------------
extern "C" void kernel_launch(void* const* d_in, const int* in_sizes, int n_in,
                              void* d_out, int out_size) {
    (void)in_sizes; (void)n_in; (void)out_size;
    const float* x      = (const float*)d_in[0];
    const int*   widx   = (const int*)d_in[1];
    const float* ln1_w  = (const float*)d_in[3];
    const float* ln1_b  = (const float*)d_in[4];
    const float* w_qkv  = (const float*)d_in[5];
    const float* w_proj = (const float*)d_in[6];
    const float* b_proj = (const float*)d_in[7];
    const float* ln2_w  = (const float*)d_in[8];
    const float* ln2_b  = (const float*)d_in[9];
    const float* w1     = (const float*)d_in[10];
    const float* b1     = (const float*)d_in[11];
    const float* bn_w   = (const float*)d_in[12];
    const float* bn_b   = (const float*)d_in[13];
    const float* w2     = (const float*)d_in[14];
    const float* b2     = (const float*)d_in[15];
    float* out = (float*)d_out;

    float *xin, *qkv, *attn, *x1, *hbuf, *part, *scale, *beta, *maskf;
    float *wq, *wp, *tw1, *tw2;
    int *cnt, *inv;
    cudaGetSymbolAddress((void**)&xin,    g_xin);
    cudaGetSymbolAddress((void**)&qkv,    g_qkv);
    cudaGetSymbolAddress((void**)&attn,   g_attn);
    cudaGetSymbolAddress((void**)&x1,     g_x1);
    cudaGetSymbolAddress((void**)&hbuf,   g_hbuf);
    cudaGetSymbolAddress((void**)&part,   g_bnpart);
    cudaGetSymbolAddress((void**)&scale,  g_scale);
    cudaGetSymbolAddress((void**)&beta,   g_beta);
    cudaGetSymbolAddress((void**)&maskf,  g_maskf);
    cudaGetSymbolAddress((void**)&cnt,    g_cnt);
    cudaGetSymbolAddress((void**)&inv,    g_inv);
    cudaGetSymbolAddress((void**)&wq,     g_wq);
    cudaGetSymbolAddress((void**)&wp,     g_wp);
    cudaGetSymbolAddress((void**)&tw1,    g_w1);
    cudaGetSymbolAddress((void**)&tw2,    g_w2);
    float* projbuf = qkv;   // alias: qkv dead after attention

    const int gemm_smem = NSTAGE * BUFW * (int)sizeof(float);   // 110592
    cudaFuncSetAttribute(mma_gemm<0, 768, 256>,
                         cudaFuncAttributeMaxDynamicSharedMemorySize, gemm_smem);
    cudaFuncSetAttribute(mma_gemm<1, 256, 256>,
                         cudaFuncAttributeMaxDynamicSharedMemorySize, gemm_smem);
    cudaFuncSetAttribute(mma_gemm<2, 512, 256>,
                         cudaFuncAttributeMaxDynamicSharedMemorySize, gemm_smem);
    cudaFuncSetAttribute(mma_gemm<3, 256, 512>,
                         cudaFuncAttributeMaxDynamicSharedMemorySize, gemm_smem);
    const int attn_smem = AT_SMEMW * (int)sizeof(float);
    cudaFuncSetAttribute(attn_mma_kernel,
                         cudaFuncAttributeMaxDynamicSharedMemorySize, attn_smem);

    cudaMemsetAsync(cnt, 0, N_TOK * sizeof(int));

    cvt_all_kernel<<<2048, 256>>>(w_qkv, wq, w_proj, wp, w1, tw1, w2, tw2);
    mask_count_kernel<<<MW / 256, 256>>>(widx, maskf, cnt, inv);
    ln_kernel<<<N_TOK / 8, 256>>>(x, ln1_w, ln1_b, xin, N_TOK);

    mma_gemm<0, 768, 256><<<dim3(6, 400), 256, gemm_smem>>>(
        xin, wq, nullptr, widx, nullptr, nullptr, qkv);

    attn_mma_kernel<<<100 * HEADS, 256, attn_smem>>>(qkv, maskf, attn);

    mma_gemm<1, 256, 256><<<dim3(2, 400), 256, gemm_smem>>>(
        attn, wp, b_proj, nullptr, maskf, nullptr, projbuf);

    x1ln2_kernel<<<N_TOK / 8, 256>>>(x, projbuf, cnt, inv, ln2_w, ln2_b, x1, xin);

    mma_gemm<2, 512, 256><<<dim3(4, 200), 256, gemm_smem>>>(
        xin, tw1, b1, nullptr, nullptr, nullptr, hbuf);

    bn_part_kernel<<<200, HIDD>>>(hbuf, part);
    bn_final_kernel<<<2, 256>>>(part, bn_w, bn_b, scale, beta);
    bn_apply_kernel<<<N_TOK * HIDD / 1024, 256>>>(hbuf, scale, beta);

    mma_gemm<3, 256, 512><<<dim3(2, 200), 256, gemm_smem>>>(
        hbuf, tw2, b2, nullptr, nullptr, x1, out);
}

// round 10
// speedup vs baseline: 1.7048x; 1.1135x over previous
#include <cuda_runtime.h>
#include <cstdint>
#include <math.h>

#define FULLMASK 0xFFFFFFFFu

#define N_TOK 25600
#define C_DIM 256
#define WLEN  512
#define MW    51200     // 100 windows * 512
#define HEADS 8
#define DHEAD 32
#define HIDD  512

// ---------------- scratch (static device globals; no allocations) ----------
static __device__ float g_xin[N_TOK * C_DIM];
static __device__ float g_qkv[MW * 768];      // QKV; later aliased as projbuf
static __device__ float g_attn[MW * C_DIM];
static __device__ float g_x1[N_TOK * C_DIM];
static __device__ float g_hbuf[N_TOK * HIDD];
static __device__ float g_bnpart[2 * 200 * HIDD];
static __device__ float g_scale[HIDD];
static __device__ float g_beta[HIDD];
static __device__ float g_maskf[MW];
static __device__ int   g_cnt[N_TOK];
static __device__ int   g_inv[2 * N_TOK];
// tf32-rounded weight copies
static __device__ float g_wq[768 * 256];
static __device__ float g_wp[256 * 256];
static __device__ float g_w1[512 * 256];
static __device__ float g_w2[256 * 512];

// ---------------- helpers ---------------------------------------------------
__device__ __forceinline__ float to_tf32(float x) {
    unsigned r;
    asm("cvt.rna.tf32.f32 %0, %1;" : "=r"(r) : "f"(x));
    return __uint_as_float(r);
}
__device__ __forceinline__ float ex2(float x) {
    float r;
    asm("ex2.approx.f32 %0, %1;" : "=f"(r) : "f"(x));
    return r;
}
__device__ __forceinline__ void ldsm4(uint32_t* r, uint32_t addr) {
    asm volatile("ldmatrix.sync.aligned.m8n8.x4.shared.b16 {%0,%1,%2,%3}, [%4];"
                 : "=r"(r[0]), "=r"(r[1]), "=r"(r[2]), "=r"(r[3]) : "r"(addr));
}
__device__ __forceinline__ void ldsm2(uint32_t* r, uint32_t addr) {
    asm volatile("ldmatrix.sync.aligned.m8n8.x2.shared.b16 {%0,%1}, [%2];"
                 : "=r"(r[0]), "=r"(r[1]) : "r"(addr));
}
__device__ __forceinline__ void mma_tf32(float* c, const uint32_t* a, const uint32_t* b) {
    asm volatile(
        "mma.sync.aligned.m16n8k8.row.col.f32.tf32.tf32.f32 "
        "{%0,%1,%2,%3}, {%4,%5,%6,%7}, {%8,%9}, {%0,%1,%2,%3};"
        : "+f"(c[0]), "+f"(c[1]), "+f"(c[2]), "+f"(c[3])
        : "r"(a[0]), "r"(a[1]), "r"(a[2]), "r"(a[3]), "r"(b[0]), "r"(b[1]));
}
__device__ __forceinline__ void cp16(uint32_t smem, const void* g) {
    asm volatile("cp.async.cg.shared.global [%0], [%1], 16;" :: "r"(smem), "l"(g));
}
__device__ __forceinline__ void cp16ca(uint32_t smem, const void* g) {
    asm volatile("cp.async.ca.shared.global [%0], [%1], 16;" :: "r"(smem), "l"(g));
}

// ---------------- mask + inverse index from win_idx ------------------------
__global__ void mask_count_kernel(const int* __restrict__ win_idx,
                                  float* __restrict__ maskf,
                                  int* __restrict__ cnt,
                                  int* __restrict__ inv) {
    int r = blockIdx.x * 256 + threadIdx.x;
    if (r >= MW) return;
    int w = r & (WLEN - 1);
    bool valid = (w == 0 || win_idx[r] != win_idx[r - 1]);
    maskf[r] = valid ? 1.0f : 0.0f;
    if (valid) {
        int tok = win_idx[r];
        int slot = atomicAdd(&cnt[tok], 1);
        if (slot < 2) inv[tok * 2 + slot] = r;
    }
}

// ---------------- merged tf32 rounding of all 4 weights --------------------
__global__ void cvt_all_kernel(const float* __restrict__ s0, float* __restrict__ d0,
                               const float* __restrict__ s1, float* __restrict__ d1,
                               const float* __restrict__ s2, float* __restrict__ d2,
                               const float* __restrict__ s3, float* __restrict__ d3) {
    int i = blockIdx.x * 256 + threadIdx.x;   // 524288 total
    if (i < 196608)      d0[i] = to_tf32(s0[i]);
    else if (i < 262144) d1[i - 196608] = to_tf32(s1[i - 196608]);
    else if (i < 393216) d2[i - 262144] = to_tf32(s2[i - 262144]);
    else                 d3[i - 393216] = to_tf32(s3[i - 393216]);
}

// ---------------- LayerNorm over C=256 (tf32-rounded output) ---------------
__global__ __launch_bounds__(256) void ln_kernel(const float* __restrict__ in,
                                                 const float* __restrict__ w,
                                                 const float* __restrict__ b,
                                                 float* __restrict__ out,
                                                 int rows) {
    int warp = threadIdx.x >> 5, lane = threadIdx.x & 31;
    int row = blockIdx.x * 8 + warp;
    if (row >= rows) return;
    const float4* p = (const float4*)(in + (size_t)row * C_DIM);
    float4 v0 = p[lane * 2], v1 = p[lane * 2 + 1];
    float s = v0.x + v0.y + v0.z + v0.w + v1.x + v1.y + v1.z + v1.w;
    #pragma unroll
    for (int off = 16; off; off >>= 1) s += __shfl_xor_sync(FULLMASK, s, off);
    float mu = s * (1.0f / 256.0f);
    float d0 = v0.x - mu, d1 = v0.y - mu, d2 = v0.z - mu, d3 = v0.w - mu;
    float d4 = v1.x - mu, d5 = v1.y - mu, d6 = v1.z - mu, d7 = v1.w - mu;
    float s2 = d0*d0 + d1*d1 + d2*d2 + d3*d3 + d4*d4 + d5*d5 + d6*d6 + d7*d7;
    #pragma unroll
    for (int off = 16; off; off >>= 1) s2 += __shfl_xor_sync(FULLMASK, s2, off);
    float rs = rsqrtf(s2 * (1.0f / 256.0f) + 1e-5f);
    float4 w0 = ((const float4*)w)[lane * 2], w1 = ((const float4*)w)[lane * 2 + 1];
    float4 b0 = ((const float4*)b)[lane * 2], b1 = ((const float4*)b)[lane * 2 + 1];
    float4 o0, o1;
    o0.x = to_tf32(d0 * rs * w0.x + b0.x); o0.y = to_tf32(d1 * rs * w0.y + b0.y);
    o0.z = to_tf32(d2 * rs * w0.z + b0.z); o0.w = to_tf32(d3 * rs * w0.w + b0.w);
    o1.x = to_tf32(d4 * rs * w1.x + b1.x); o1.y = to_tf32(d5 * rs * w1.y + b1.y);
    o1.z = to_tf32(d6 * rs * w1.z + b1.z); o1.w = to_tf32(d7 * rs * w1.w + b1.w);
    float4* q = (float4*)(out + (size_t)row * C_DIM);
    q[lane * 2] = o0; q[lane * 2 + 1] = o1;
}

// ---------------- gather proj + x1 + LayerNorm2 (fused) --------------------
__global__ __launch_bounds__(256) void x1ln2_kernel(
    const float* __restrict__ x, const float* __restrict__ projbuf,
    const int* __restrict__ cnt, const int* __restrict__ inv,
    const float* __restrict__ w, const float* __restrict__ b,
    float* __restrict__ x1, float* __restrict__ out) {
    int warp = threadIdx.x >> 5, lane = threadIdx.x & 31;
    int row = blockIdx.x * 8 + warp;
    int c = cnt[row];
    const float4* xp = (const float4*)(x + (size_t)row * C_DIM);
    float4 v0 = xp[lane * 2], v1 = xp[lane * 2 + 1];
    float4 y0 = make_float4(0.f, 0.f, 0.f, 0.f), y1 = y0;
    if (c >= 1) {
        const float4* p = (const float4*)(projbuf + (size_t)inv[row * 2] * C_DIM);
        y0 = p[lane * 2]; y1 = p[lane * 2 + 1];
    }
    if (c >= 2) {
        const float4* p = (const float4*)(projbuf + (size_t)inv[row * 2 + 1] * C_DIM);
        float4 a = p[lane * 2], bq = p[lane * 2 + 1];
        y0.x += a.x; y0.y += a.y; y0.z += a.z; y0.w += a.w;
        y1.x += bq.x; y1.y += bq.y; y1.z += bq.z; y1.w += bq.w;
    }
    float ic = 1.0f / fmaxf((float)c, 1.0f);
    v0.x += y0.x * ic; v0.y += y0.y * ic; v0.z += y0.z * ic; v0.w += y0.w * ic;
    v1.x += y1.x * ic; v1.y += y1.y * ic; v1.z += y1.z * ic; v1.w += y1.w * ic;
    float4* xq = (float4*)(x1 + (size_t)row * C_DIM);
    xq[lane * 2] = v0; xq[lane * 2 + 1] = v1;
    float s = v0.x + v0.y + v0.z + v0.w + v1.x + v1.y + v1.z + v1.w;
    #pragma unroll
    for (int off = 16; off; off >>= 1) s += __shfl_xor_sync(FULLMASK, s, off);
    float mu = s * (1.0f / 256.0f);
    float d0 = v0.x - mu, d1 = v0.y - mu, d2 = v0.z - mu, d3 = v0.w - mu;
    float d4 = v1.x - mu, d5 = v1.y - mu, d6 = v1.z - mu, d7 = v1.w - mu;
    float s2 = d0*d0 + d1*d1 + d2*d2 + d3*d3 + d4*d4 + d5*d5 + d6*d6 + d7*d7;
    #pragma unroll
    for (int off = 16; off; off >>= 1) s2 += __shfl_xor_sync(FULLMASK, s2, off);
    float rs = rsqrtf(s2 * (1.0f / 256.0f) + 1e-5f);
    float4 w0 = ((const float4*)w)[lane * 2], w1 = ((const float4*)w)[lane * 2 + 1];
    float4 b0 = ((const float4*)b)[lane * 2], b1 = ((const float4*)b)[lane * 2 + 1];
    float4 o0, o1;
    o0.x = to_tf32(d0 * rs * w0.x + b0.x); o0.y = to_tf32(d1 * rs * w0.y + b0.y);
    o0.z = to_tf32(d2 * rs * w0.z + b0.z); o0.w = to_tf32(d3 * rs * w0.w + b0.w);
    o1.x = to_tf32(d4 * rs * w1.x + b1.x); o1.y = to_tf32(d5 * rs * w1.y + b1.y);
    o1.z = to_tf32(d6 * rs * w1.z + b1.z); o1.w = to_tf32(d7 * rs * w1.w + b1.w);
    float4* q = (float4*)(out + (size_t)row * C_DIM);
    q[lane * 2] = o0; q[lane * 2 + 1] = o1;
}

// ---------------- tf32 tensor-core NT GEMM (BM=128, BN=128) ----------------
// 3-stage cp.async pipeline, ONE __syncthreads per k-tile.
// B (weights) loaded with cp.async.ca (L1-cached, ~400x reuse); A with .cg.
#define GP 36
#define BUFW 9216       // words per stage (A 128*36 + B 128*36)
#define NSTAGE 3
template <int MODE, int NC, int KD>
__global__ __launch_bounds__(256) void mma_gemm(
    const float* __restrict__ A, const float* __restrict__ Bw,
    const float* __restrict__ bias, const int* __restrict__ gidx,
    const float* __restrict__ maskf, const float* __restrict__ resid,
    float* __restrict__ Cout) {
    extern __shared__ float sm[];
    uint32_t smem_u32 = (uint32_t)__cvta_generic_to_shared(sm);
    const int tid = threadIdx.x, lane = tid & 31, warp = tid >> 5;
    const int wm = warp >> 2, wn = warp & 3;
    const int bm = blockIdx.y * 128, bn = blockIdx.x * 128;

    const int lrow = tid & 127;
    const bool isA = tid < 128;
    const float* gbase;
    if (isA) {
        int arow = (MODE == 0) ? gidx[bm + lrow] : (bm + lrow);
        gbase = A + (size_t)arow * KD;
    } else {
        gbase = Bw + (size_t)(bn + lrow) * KD;
    }
    const uint32_t sdst = smem_u32 + (uint32_t)(((isA ? 0 : 4608) + lrow * GP) * 4);

    const int lr8 = lane & 7, sub = lane >> 3, lb = lane & 15;
    const uint32_t a_off = smem_u32 +
        (uint32_t)(((wm * 64 + (sub & 1) * 8 + lr8) * GP + (sub >> 1) * 4) * 4);
    const uint32_t b_off = smem_u32 +
        (uint32_t)((4608 + (wn * 32 + (lb & 7)) * GP + (lb >> 3) * 4) * 4);

    float acc[4][4][4];
    #pragma unroll
    for (int i = 0; i < 4; i++)
        #pragma unroll
        for (int j = 0; j < 4; j++)
            #pragma unroll
            for (int r = 0; r < 4; r++) acc[i][j][r] = 0.f;

    const int T = KD / 32;
    #pragma unroll
    for (int ps = 0; ps < NSTAGE - 1; ps++) {
        const float* g = gbase + ps * 32;
        uint32_t d = sdst + (uint32_t)(ps * BUFW * 4);
        if (isA) {
            #pragma unroll
            for (int i = 0; i < 8; i++) cp16(d + i * 16, g + i * 4);
        } else {
            #pragma unroll
            for (int i = 0; i < 8; i++) cp16ca(d + i * 16, g + i * 4);
        }
        asm volatile("cp.async.commit_group;");
    }

    int buf = 0, nbuf = NSTAGE - 1;
    for (int t = 0; t < T; t++) {
        asm volatile("cp.async.wait_group %0;" :: "n"(NSTAGE - 2));
        __syncthreads();

        const uint32_t boff = (uint32_t)(buf * BUFW * 4);
        #pragma unroll
        for (int ks = 0; ks < 4; ks++) {
            uint32_t a[4][4], b[4][2];
            #pragma unroll
            for (int i = 0; i < 4; i++)
                ldsm4(a[i], a_off + boff + i * 2304 + ks * 32);
            #pragma unroll
            for (int j = 0; j < 4; j++)
                ldsm2(b[j], b_off + boff + j * 1152 + ks * 32);
            #pragma unroll
            for (int i = 0; i < 4; i++)
                #pragma unroll
                for (int j = 0; j < 4; j++)
                    mma_tf32(acc[i][j], a[i], b[j]);
        }

        if (t + NSTAGE - 1 < T) {
            const float* g = gbase + (t + NSTAGE - 1) * 32;
            uint32_t d = sdst + (uint32_t)(nbuf * BUFW * 4);
            if (isA) {
                #pragma unroll
                for (int i = 0; i < 8; i++) cp16(d + i * 16, g + i * 4);
            } else {
                #pragma unroll
                for (int i = 0; i < 8; i++) cp16ca(d + i * 16, g + i * 4);
            }
        }
        asm volatile("cp.async.commit_group;");
        buf = (buf + 1) % NSTAGE;
        nbuf = (nbuf + 1) % NSTAGE;
    }

    const int er = bm + wm * 64 + (lane >> 2);
    const int ec = bn + wn * 32 + (lane & 3) * 2;
    #pragma unroll
    for (int i = 0; i < 4; i++) {
        const int r0 = er + i * 16, r1 = r0 + 8;
        float mk0 = 0.f, mk1 = 0.f;
        if (MODE == 1) { mk0 = maskf[r0]; mk1 = maskf[r1]; }
        #pragma unroll
        for (int j = 0; j < 4; j++) {
            const int c = ec + j * 8;
            float v0 = acc[i][j][0], v1 = acc[i][j][1];
            float v2 = acc[i][j][2], v3 = acc[i][j][3];
            if (MODE == 0) {
                *(float2*)&Cout[(size_t)r0 * NC + c] =
                    make_float2(to_tf32(v0), to_tf32(v1));
                *(float2*)&Cout[(size_t)r1 * NC + c] =
                    make_float2(to_tf32(v2), to_tf32(v3));
            } else if (MODE == 1) {
                float b0 = bias[c], b1 = bias[c + 1];
                *(float2*)&Cout[(size_t)r0 * NC + c] =
                    make_float2((v0 + b0) * mk0, (v1 + b1) * mk0);
                *(float2*)&Cout[(size_t)r1 * NC + c] =
                    make_float2((v2 + b0) * mk1, (v3 + b1) * mk1);
            } else if (MODE == 2) {
                float b0 = bias[c], b1 = bias[c + 1];
                *(float2*)&Cout[(size_t)r0 * NC + c] = make_float2(v0 + b0, v1 + b1);
                *(float2*)&Cout[(size_t)r1 * NC + c] = make_float2(v2 + b0, v3 + b1);
            } else {
                float b0 = bias[c], b1 = bias[c + 1];
                float2 x0 = *(const float2*)&resid[(size_t)r0 * 256 + c];
                float2 x1v = *(const float2*)&resid[(size_t)r1 * 256 + c];
                *(float2*)&Cout[(size_t)r0 * NC + c] =
                    make_float2(v0 + b0 + x0.x, v1 + b1 + x0.y);
                *(float2*)&Cout[(size_t)r1 * NC + c] =
                    make_float2(v2 + b0 + x1v.x, v3 + b1 + x1v.y);
            }
        }
    }
}

// ---------------- tensor-core flash attention (no-max softmax) -------------
// Split-q: one CTA per (window m, head h, q-half). 8 warps x 32 q-rows.
// Halved register state (qf/o/s) + 57KB smem -> 2 CTAs/SM for latency hiding.
// P and output are NOT pre-rounded to tf32 (HW truncation bias is diluted
// through y/counts; saves ~96 CVTs/thread/iter).
#define ATP 36
#define AT_KOFF (512 + 8 * 1152)          // 9728
#define AT_SMEMW (AT_KOFF + 4 * 1152)     // 14336 words = 57344 B
__global__ __launch_bounds__(256, 2) void attn_mma_kernel(
    const float* __restrict__ qkv, const float* __restrict__ maskf,
    float* __restrict__ attn) {
    extern __shared__ float sm[];
    const uint32_t smb = (uint32_t)__cvta_generic_to_shared(sm);
    const int m = blockIdx.x >> 4;
    const int h = (blockIdx.x >> 1) & 7;
    const int qh = blockIdx.x & 1;
    const int tid = threadIdx.x, lane = tid & 31, wp = tid >> 5;
    const int lr8 = lane & 7, sub = lane >> 3, lb = lane & 15;

    float* maskA = sm;
    float* Qw = sm + 512 + wp * 1152;      // warp's 32-row Q staging / P buffer

    const float* qg = qkv + (size_t)m * 512 * 768 + h * 32;
    const float* kg = qg + 256;
    const float* vg = qg + 512;
    const int qrow0 = qh * 256 + wp * 32;

    for (int w = tid; w < 512; w += 256)
        maskA[w] = (maskf[m * 512 + w] != 0.f) ? 0.f : -1e30f;

    // stage warp's 32 Q rows
    for (int i = lane; i < 256; i += 32) {
        int row = i >> 3, c4 = (i & 7) * 4;
        float4 v = *(const float4*)(qg + (size_t)(qrow0 + row) * 768 + c4);
        *(float4*)&Qw[row * ATP + c4] = v;
    }
    __syncwarp();
    uint32_t qf[2][4][4];
    {
        uint32_t qb = smb + (uint32_t)((512 + wp * 1152) * 4) +
                      (uint32_t)((((sub & 1) * 8 + lr8) * ATP + (sub >> 1) * 4) * 4);
        #pragma unroll
        for (int i = 0; i < 2; i++)
            #pragma unroll
            for (int ks = 0; ks < 4; ks++)
                ldsm4(qf[i][ks], qb + (uint32_t)(i * 16 * ATP * 4 + ks * 32));
    }
    __syncwarp();

    // prologue: K(0), Vt(0)
    {
        int row = tid >> 3, c4 = (tid & 7) * 4;
        float4 kv = *(const float4*)(kg + (size_t)row * 768 + c4);
        *(float4*)&sm[AT_KOFF + row * ATP + c4] = kv;
        float4 vv = *(const float4*)(vg + (size_t)row * 768 + c4);
        sm[AT_KOFF + 2304 + (c4 + 0) * ATP + row] = vv.x;
        sm[AT_KOFF + 2304 + (c4 + 1) * ATP + row] = vv.y;
        sm[AT_KOFF + 2304 + (c4 + 2) * ATP + row] = vv.z;
        sm[AT_KOFF + 2304 + (c4 + 3) * ATP + row] = vv.w;
    }
    __syncthreads();

    float o[2][4][4];
    #pragma unroll
    for (int i = 0; i < 2; i++)
        #pragma unroll
        for (int j = 0; j < 4; j++)
            #pragma unroll
            for (int c = 0; c < 4; c++) o[i][j][c] = 0.f;
    float Ls[2][2];
    #pragma unroll
    for (int i = 0; i < 2; i++) { Ls[i][0] = 0.f; Ls[i][1] = 0.f; }
    const float SCL2 = 0.25503485900582243f;   // log2(e)/sqrt(32)
    const int ldrow = tid >> 3, ldc4 = (tid & 7) * 4;

    for (int kt = 0; kt < 16; kt++) {
        const int cb = kt & 1;
        float4 vpre;
        if (kt < 15) {
            uint32_t d = smb + (uint32_t)((AT_KOFF + (1 - cb) * 1152 +
                                           ldrow * ATP + ldc4) * 4);
            cp16(d, kg + (size_t)((kt + 1) * 32 + ldrow) * 768 + ldc4);
            asm volatile("cp.async.commit_group;");
            vpre = *(const float4*)(vg + (size_t)((kt + 1) * 32 + ldrow) * 768 + ldc4);
        }

        // ---- S = Q . K^T ----
        float s[2][4][4];
        #pragma unroll
        for (int i = 0; i < 2; i++)
            #pragma unroll
            for (int j = 0; j < 4; j++)
                #pragma unroll
                for (int c = 0; c < 4; c++) s[i][j][c] = 0.f;
        {
            uint32_t kb = smb + (uint32_t)((AT_KOFF + cb * 1152) * 4) +
                          (uint32_t)(((lb & 7) * ATP + (lb >> 3) * 4) * 4);
            #pragma unroll
            for (int ks = 0; ks < 4; ks++) {
                uint32_t bf[4][2];
                #pragma unroll
                for (int j = 0; j < 4; j++)
                    ldsm2(bf[j], kb + (uint32_t)(j * 8 * ATP * 4 + ks * 32));
                #pragma unroll
                for (int i = 0; i < 2; i++)
                    #pragma unroll
                    for (int j = 0; j < 4; j++)
                        mma_tf32(s[i][j], qf[i][ks], bf[j]);
            }
        }

        // ---- p = 2^(s*SCL2 + mask), accumulate row sums in registers ----
        float mk[4][2];
        #pragma unroll
        for (int j = 0; j < 4; j++) {
            float2 mm = *(const float2*)&maskA[kt * 32 + j * 8 + 2 * (lane & 3)];
            mk[j][0] = mm.x; mk[j][1] = mm.y;
        }
        #pragma unroll
        for (int i = 0; i < 2; i++)
            #pragma unroll
            for (int j = 0; j < 4; j++)
                #pragma unroll
                for (int c = 0; c < 4; c++) {
                    float p = ex2(s[i][j][c] * SCL2 + mk[j][c & 1]);
                    s[i][j][c] = p;
                    Ls[i][c >> 1] += p;
                }

        // ---- store P into warp-private buffer (no rounding) ----
        {
            int r = lane >> 2, q2 = 2 * (lane & 3);
            #pragma unroll
            for (int i = 0; i < 2; i++)
                #pragma unroll
                for (int j = 0; j < 4; j++) {
                    *(float2*)&Qw[(i * 16 + r) * ATP + j * 8 + q2] =
                        make_float2(s[i][j][0], s[i][j][1]);
                    *(float2*)&Qw[(i * 16 + r + 8) * ATP + j * 8 + q2] =
                        make_float2(s[i][j][2], s[i][j][3]);
                }
        }
        __syncwarp();

        // ---- O += P . V ----
        {
            uint32_t pb = smb + (uint32_t)((512 + wp * 1152) * 4) +
                          (uint32_t)((((sub & 1) * 8 + lr8) * ATP + (sub >> 1) * 4) * 4);
            uint32_t vb = smb + (uint32_t)((AT_KOFF + 2304 + cb * 1152) * 4) +
                          (uint32_t)(((lb & 7) * ATP + (lb >> 3) * 4) * 4);
            #pragma unroll
            for (int ks = 0; ks < 4; ks++) {
                uint32_t pf[2][4], vf[4][2];
                #pragma unroll
                for (int i = 0; i < 2; i++)
                    ldsm4(pf[i], pb + (uint32_t)(i * 16 * ATP * 4 + ks * 32));
                #pragma unroll
                for (int jd = 0; jd < 4; jd++)
                    ldsm2(vf[jd], vb + (uint32_t)(jd * 8 * ATP * 4 + ks * 32));
                #pragma unroll
                for (int i = 0; i < 2; i++)
                    #pragma unroll
                    for (int jd = 0; jd < 4; jd++)
                        mma_tf32(o[i][jd], pf[i], vf[jd]);
            }
        }
        __syncwarp();

        if (kt < 15) {
            float* vt = &sm[AT_KOFF + 2304 + (1 - cb) * 1152];
            vt[(ldc4 + 0) * ATP + ldrow] = vpre.x;
            vt[(ldc4 + 1) * ATP + ldrow] = vpre.y;
            vt[(ldc4 + 2) * ATP + ldrow] = vpre.z;
            vt[(ldc4 + 3) * ATP + ldrow] = vpre.w;
            asm volatile("cp.async.wait_group 0;");
        }
        __syncthreads();
    }

    // ---- final row-sum reduction + normalize + writeout ----
    #pragma unroll
    for (int i = 0; i < 2; i++)
        #pragma unroll
        for (int rh = 0; rh < 2; rh++) {
            float v = Ls[i][rh];
            v += __shfl_xor_sync(FULLMASK, v, 1);
            v += __shfl_xor_sync(FULLMASK, v, 2);
            Ls[i][rh] = v;
        }
    {
        int r = lane >> 2, q2 = 2 * (lane & 3);
        #pragma unroll
        for (int i = 0; i < 2; i++) {
            float inv0 = 1.f / Ls[i][0], inv1 = 1.f / Ls[i][1];
            int row0 = m * 512 + qrow0 + i * 16 + r;
            #pragma unroll
            for (int jd = 0; jd < 4; jd++) {
                int col = h * 32 + jd * 8 + q2;
                *(float2*)&attn[(size_t)row0 * 256 + col] =
                    make_float2(o[i][jd][0] * inv0, o[i][jd][1] * inv0);
                *(float2*)&attn[(size_t)(row0 + 8) * 256 + col] =
                    make_float2(o[i][jd][2] * inv1, o[i][jd][3] * inv1);
            }
        }
    }
}

// ---------------- BatchNorm stats (two-pass, deterministic) ----------------
__global__ void bn_part_kernel(const float* __restrict__ h, float* __restrict__ part) {
    int col = threadIdx.x;
    int b = blockIdx.x;
    float s = 0.f, s2 = 0.f;
    const float* p = h + (size_t)b * 128 * HIDD + col;
    #pragma unroll 4
    for (int r = 0; r < 128; r++) {
        float v = p[(size_t)r * HIDD];
        s += v; s2 += v * v;
    }
    part[b * HIDD + col] = s;
    part[200 * HIDD + b * HIDD + col] = s2;
}

__global__ void bn_final_kernel(const float* __restrict__ part,
                                const float* __restrict__ bn_w,
                                const float* __restrict__ bn_b,
                                float* __restrict__ scale, float* __restrict__ beta) {
    int col = blockIdx.x * 256 + threadIdx.x;
    float s = 0.f, s2 = 0.f;
    for (int b = 0; b < 200; b++) {
        s += part[b * HIDD + col];
        s2 += part[200 * HIDD + b * HIDD + col];
    }
    float mu = s * (1.0f / 25600.0f);
    float var = s2 * (1.0f / 25600.0f) - mu * mu;
    float sc = bn_w[col] * rsqrtf(var + 1e-5f);
    scale[col] = sc;
    beta[col] = bn_b[col] - mu * sc;
}

// ---------------- apply BN+ReLU in place (float4, tf32-rounded) ------------
__global__ void bn_apply_kernel(float* __restrict__ h,
                                const float* __restrict__ scale,
                                const float* __restrict__ beta) {
    int i = blockIdx.x * 256 + threadIdx.x;    // float4 index
    int c = (i * 4) & (HIDD - 1);
    float4 v = ((float4*)h)[i];
    float4 sc = *(const float4*)&scale[c];
    float4 be = *(const float4*)&beta[c];
    v.x = to_tf32(fmaxf(0.f, v.x * sc.x + be.x));
    v.y = to_tf32(fmaxf(0.f, v.y * sc.y + be.y));
    v.z = to_tf32(fmaxf(0.f, v.z * sc.z + be.z));
    v.w = to_tf32(fmaxf(0.f, v.w * sc.w + be.w));
    ((float4*)h)[i] = v;
}

// ---------------- launch ----------------------------------------------------
extern "C" void kernel_launch(void* const* d_in, const int* in_sizes, int n_in,
                              void* d_out, int out_size) {
    (void)in_sizes; (void)n_in; (void)out_size;
    const float* x      = (const float*)d_in[0];
    const int*   widx   = (const int*)d_in[1];
    const float* ln1_w  = (const float*)d_in[3];
    const float* ln1_b  = (const float*)d_in[4];
    const float* w_qkv  = (const float*)d_in[5];
    const float* w_proj = (const float*)d_in[6];
    const float* b_proj = (const float*)d_in[7];
    const float* ln2_w  = (const float*)d_in[8];
    const float* ln2_b  = (const float*)d_in[9];
    const float* w1     = (const float*)d_in[10];
    const float* b1     = (const float*)d_in[11];
    const float* bn_w   = (const float*)d_in[12];
    const float* bn_b   = (const float*)d_in[13];
    const float* w2     = (const float*)d_in[14];
    const float* b2     = (const float*)d_in[15];
    float* out = (float*)d_out;

    float *xin, *qkv, *attn, *x1, *hbuf, *part, *scale, *beta, *maskf;
    float *wq, *wp, *tw1, *tw2;
    int *cnt, *inv;
    cudaGetSymbolAddress((void**)&xin,    g_xin);
    cudaGetSymbolAddress((void**)&qkv,    g_qkv);
    cudaGetSymbolAddress((void**)&attn,   g_attn);
    cudaGetSymbolAddress((void**)&x1,     g_x1);
    cudaGetSymbolAddress((void**)&hbuf,   g_hbuf);
    cudaGetSymbolAddress((void**)&part,   g_bnpart);
    cudaGetSymbolAddress((void**)&scale,  g_scale);
    cudaGetSymbolAddress((void**)&beta,   g_beta);
    cudaGetSymbolAddress((void**)&maskf,  g_maskf);
    cudaGetSymbolAddress((void**)&cnt,    g_cnt);
    cudaGetSymbolAddress((void**)&inv,    g_inv);
    cudaGetSymbolAddress((void**)&wq,     g_wq);
    cudaGetSymbolAddress((void**)&wp,     g_wp);
    cudaGetSymbolAddress((void**)&tw1,    g_w1);
    cudaGetSymbolAddress((void**)&tw2,    g_w2);
    float* projbuf = qkv;   // alias: qkv dead after attention

    const int gemm_smem = NSTAGE * BUFW * (int)sizeof(float);   // 110592
    cudaFuncSetAttribute(mma_gemm<0, 768, 256>,
                         cudaFuncAttributeMaxDynamicSharedMemorySize, gemm_smem);
    cudaFuncSetAttribute(mma_gemm<1, 256, 256>,
                         cudaFuncAttributeMaxDynamicSharedMemorySize, gemm_smem);
    cudaFuncSetAttribute(mma_gemm<2, 512, 256>,
                         cudaFuncAttributeMaxDynamicSharedMemorySize, gemm_smem);
    cudaFuncSetAttribute(mma_gemm<3, 256, 512>,
                         cudaFuncAttributeMaxDynamicSharedMemorySize, gemm_smem);
    const int attn_smem = AT_SMEMW * (int)sizeof(float);   // 57344
    cudaFuncSetAttribute(attn_mma_kernel,
                         cudaFuncAttributeMaxDynamicSharedMemorySize, attn_smem);

    cudaMemsetAsync(cnt, 0, N_TOK * sizeof(int));

    cvt_all_kernel<<<2048, 256>>>(w_qkv, wq, w_proj, wp, w1, tw1, w2, tw2);
    mask_count_kernel<<<MW / 256, 256>>>(widx, maskf, cnt, inv);
    ln_kernel<<<N_TOK / 8, 256>>>(x, ln1_w, ln1_b, xin, N_TOK);

    mma_gemm<0, 768, 256><<<dim3(6, 400), 256, gemm_smem>>>(
        xin, wq, nullptr, widx, nullptr, nullptr, qkv);

    attn_mma_kernel<<<100 * HEADS * 2, 256, attn_smem>>>(qkv, maskf, attn);

    mma_gemm<1, 256, 256><<<dim3(2, 400), 256, gemm_smem>>>(
        attn, wp, b_proj, nullptr, maskf, nullptr, projbuf);

    x1ln2_kernel<<<N_TOK / 8, 256>>>(x, projbuf, cnt, inv, ln2_w, ln2_b, x1, xin);

    mma_gemm<2, 512, 256><<<dim3(4, 200), 256, gemm_smem>>>(
        xin, tw1, b1, nullptr, nullptr, nullptr, hbuf);

    bn_part_kernel<<<200, HIDD>>>(hbuf, part);
    bn_final_kernel<<<2, 256>>>(part, bn_w, bn_b, scale, beta);
    bn_apply_kernel<<<N_TOK * HIDD / 1024, 256>>>(hbuf, scale, beta);

    mma_gemm<3, 256, 512><<<dim3(2, 200), 256, gemm_smem>>>(
        hbuf, tw2, b2, nullptr, nullptr, x1, out);
}

// round 11
// speedup vs baseline: 1.8821x; 1.1040x over previous
#include <cuda_runtime.h>
#include <cstdint>
#include <math.h>

#define FULLMASK 0xFFFFFFFFu

#define N_TOK 25600
#define C_DIM 256
#define WLEN  512
#define MW    51200     // 100 windows * 512
#define HEADS 8
#define DHEAD 32
#define HIDD  512

// ---------------- scratch (static device globals; no allocations) ----------
static __device__ float g_xin[N_TOK * C_DIM];
static __device__ float g_qkvtok[N_TOK * 768]; // per-token QKV (deduped)
static __device__ float g_qkv[MW * 768];       // window-layout QKV; later projbuf
static __device__ float g_attn[MW * C_DIM];
static __device__ float g_x1[N_TOK * C_DIM];
static __device__ float g_hbuf[N_TOK * HIDD];
static __device__ float g_bnpart[2 * 200 * HIDD];
static __device__ float g_scale[HIDD];
static __device__ float g_beta[HIDD];
static __device__ float g_maskf[MW];
static __device__ int   g_cnt[N_TOK];
static __device__ int   g_inv[2 * N_TOK];
// tf32-rounded weight copies
static __device__ float g_wq[768 * 256];
static __device__ float g_wp[256 * 256];
static __device__ float g_w1[512 * 256];
static __device__ float g_w2[256 * 512];

// ---------------- helpers ---------------------------------------------------
__device__ __forceinline__ float to_tf32(float x) {
    unsigned r;
    asm("cvt.rna.tf32.f32 %0, %1;" : "=r"(r) : "f"(x));
    return __uint_as_float(r);
}
__device__ __forceinline__ float ex2(float x) {
    float r;
    asm("ex2.approx.f32 %0, %1;" : "=f"(r) : "f"(x));
    return r;
}
__device__ __forceinline__ void ldsm4(uint32_t* r, uint32_t addr) {
    asm volatile("ldmatrix.sync.aligned.m8n8.x4.shared.b16 {%0,%1,%2,%3}, [%4];"
                 : "=r"(r[0]), "=r"(r[1]), "=r"(r[2]), "=r"(r[3]) : "r"(addr));
}
__device__ __forceinline__ void ldsm2(uint32_t* r, uint32_t addr) {
    asm volatile("ldmatrix.sync.aligned.m8n8.x2.shared.b16 {%0,%1}, [%2];"
                 : "=r"(r[0]), "=r"(r[1]) : "r"(addr));
}
__device__ __forceinline__ void mma_tf32(float* c, const uint32_t* a, const uint32_t* b) {
    asm volatile(
        "mma.sync.aligned.m16n8k8.row.col.f32.tf32.tf32.f32 "
        "{%0,%1,%2,%3}, {%4,%5,%6,%7}, {%8,%9}, {%0,%1,%2,%3};"
        : "+f"(c[0]), "+f"(c[1]), "+f"(c[2]), "+f"(c[3])
        : "r"(a[0]), "r"(a[1]), "r"(a[2]), "r"(a[3]), "r"(b[0]), "r"(b[1]));
}
__device__ __forceinline__ void cp16(uint32_t smem, const void* g) {
    asm volatile("cp.async.cg.shared.global [%0], [%1], 16;" :: "r"(smem), "l"(g));
}
__device__ __forceinline__ void cp16ca(uint32_t smem, const void* g) {
    asm volatile("cp.async.ca.shared.global [%0], [%1], 16;" :: "r"(smem), "l"(g));
}

// ---------------- mask + inverse index from win_idx ------------------------
__global__ void mask_count_kernel(const int* __restrict__ win_idx,
                                  float* __restrict__ maskf,
                                  int* __restrict__ cnt,
                                  int* __restrict__ inv) {
    int r = blockIdx.x * 256 + threadIdx.x;
    if (r >= MW) return;
    int w = r & (WLEN - 1);
    bool valid = (w == 0 || win_idx[r] != win_idx[r - 1]);
    maskf[r] = valid ? 1.0f : 0.0f;
    if (valid) {
        int tok = win_idx[r];
        int slot = atomicAdd(&cnt[tok], 1);
        if (slot < 2) inv[tok * 2 + slot] = r;
    }
}

// ---------------- merged tf32 rounding of all 4 weights --------------------
__global__ void cvt_all_kernel(const float* __restrict__ s0, float* __restrict__ d0,
                               const float* __restrict__ s1, float* __restrict__ d1,
                               const float* __restrict__ s2, float* __restrict__ d2,
                               const float* __restrict__ s3, float* __restrict__ d3) {
    int i = blockIdx.x * 256 + threadIdx.x;   // 524288 total
    if (i < 196608)      d0[i] = to_tf32(s0[i]);
    else if (i < 262144) d1[i - 196608] = to_tf32(s1[i - 196608]);
    else if (i < 393216) d2[i - 262144] = to_tf32(s2[i - 262144]);
    else                 d3[i - 393216] = to_tf32(s3[i - 393216]);
}

// ---------------- expand per-token QKV into window layout ------------------
// dst[r][0..768) = src[widx[r]][0..768); coalesced float4 writes, reads are
// near-sequential (windows are contiguous token ranges) and largely L2-hit.
__global__ void expand_kernel(const float* __restrict__ src,
                              const int* __restrict__ widx,
                              float* __restrict__ dst) {
    int idx = blockIdx.x * 256 + threadIdx.x;   // float4 index, MW*192 total
    int r = idx / 192;
    int c = idx - r * 192;
    int tok = __ldg(&widx[r]);
    ((float4*)dst)[idx] = ((const float4*)src)[(size_t)tok * 192 + c];
}

// ---------------- LayerNorm over C=256 (tf32-rounded output) ---------------
__global__ __launch_bounds__(256) void ln_kernel(const float* __restrict__ in,
                                                 const float* __restrict__ w,
                                                 const float* __restrict__ b,
                                                 float* __restrict__ out,
                                                 int rows) {
    int warp = threadIdx.x >> 5, lane = threadIdx.x & 31;
    int row = blockIdx.x * 8 + warp;
    if (row >= rows) return;
    const float4* p = (const float4*)(in + (size_t)row * C_DIM);
    float4 v0 = p[lane * 2], v1 = p[lane * 2 + 1];
    float s = v0.x + v0.y + v0.z + v0.w + v1.x + v1.y + v1.z + v1.w;
    #pragma unroll
    for (int off = 16; off; off >>= 1) s += __shfl_xor_sync(FULLMASK, s, off);
    float mu = s * (1.0f / 256.0f);
    float d0 = v0.x - mu, d1 = v0.y - mu, d2 = v0.z - mu, d3 = v0.w - mu;
    float d4 = v1.x - mu, d5 = v1.y - mu, d6 = v1.z - mu, d7 = v1.w - mu;
    float s2 = d0*d0 + d1*d1 + d2*d2 + d3*d3 + d4*d4 + d5*d5 + d6*d6 + d7*d7;
    #pragma unroll
    for (int off = 16; off; off >>= 1) s2 += __shfl_xor_sync(FULLMASK, s2, off);
    float rs = rsqrtf(s2 * (1.0f / 256.0f) + 1e-5f);
    float4 w0 = ((const float4*)w)[lane * 2], w1 = ((const float4*)w)[lane * 2 + 1];
    float4 b0 = ((const float4*)b)[lane * 2], b1 = ((const float4*)b)[lane * 2 + 1];
    float4 o0, o1;
    o0.x = to_tf32(d0 * rs * w0.x + b0.x); o0.y = to_tf32(d1 * rs * w0.y + b0.y);
    o0.z = to_tf32(d2 * rs * w0.z + b0.z); o0.w = to_tf32(d3 * rs * w0.w + b0.w);
    o1.x = to_tf32(d4 * rs * w1.x + b1.x); o1.y = to_tf32(d5 * rs * w1.y + b1.y);
    o1.z = to_tf32(d6 * rs * w1.z + b1.z); o1.w = to_tf32(d7 * rs * w1.w + b1.w);
    float4* q = (float4*)(out + (size_t)row * C_DIM);
    q[lane * 2] = o0; q[lane * 2 + 1] = o1;
}

// ---------------- gather proj + x1 + LayerNorm2 (fused) --------------------
__global__ __launch_bounds__(256) void x1ln2_kernel(
    const float* __restrict__ x, const float* __restrict__ projbuf,
    const int* __restrict__ cnt, const int* __restrict__ inv,
    const float* __restrict__ w, const float* __restrict__ b,
    float* __restrict__ x1, float* __restrict__ out) {
    int warp = threadIdx.x >> 5, lane = threadIdx.x & 31;
    int row = blockIdx.x * 8 + warp;
    int c = cnt[row];
    const float4* xp = (const float4*)(x + (size_t)row * C_DIM);
    float4 v0 = xp[lane * 2], v1 = xp[lane * 2 + 1];
    float4 y0 = make_float4(0.f, 0.f, 0.f, 0.f), y1 = y0;
    if (c >= 1) {
        const float4* p = (const float4*)(projbuf + (size_t)inv[row * 2] * C_DIM);
        y0 = p[lane * 2]; y1 = p[lane * 2 + 1];
    }
    if (c >= 2) {
        const float4* p = (const float4*)(projbuf + (size_t)inv[row * 2 + 1] * C_DIM);
        float4 a = p[lane * 2], bq = p[lane * 2 + 1];
        y0.x += a.x; y0.y += a.y; y0.z += a.z; y0.w += a.w;
        y1.x += bq.x; y1.y += bq.y; y1.z += bq.z; y1.w += bq.w;
    }
    float ic = 1.0f / fmaxf((float)c, 1.0f);
    v0.x += y0.x * ic; v0.y += y0.y * ic; v0.z += y0.z * ic; v0.w += y0.w * ic;
    v1.x += y1.x * ic; v1.y += y1.y * ic; v1.z += y1.z * ic; v1.w += y1.w * ic;
    float4* xq = (float4*)(x1 + (size_t)row * C_DIM);
    xq[lane * 2] = v0; xq[lane * 2 + 1] = v1;
    float s = v0.x + v0.y + v0.z + v0.w + v1.x + v1.y + v1.z + v1.w;
    #pragma unroll
    for (int off = 16; off; off >>= 1) s += __shfl_xor_sync(FULLMASK, s, off);
    float mu = s * (1.0f / 256.0f);
    float d0 = v0.x - mu, d1 = v0.y - mu, d2 = v0.z - mu, d3 = v0.w - mu;
    float d4 = v1.x - mu, d5 = v1.y - mu, d6 = v1.z - mu, d7 = v1.w - mu;
    float s2 = d0*d0 + d1*d1 + d2*d2 + d3*d3 + d4*d4 + d5*d5 + d6*d6 + d7*d7;
    #pragma unroll
    for (int off = 16; off; off >>= 1) s2 += __shfl_xor_sync(FULLMASK, s2, off);
    float rs = rsqrtf(s2 * (1.0f / 256.0f) + 1e-5f);
    float4 w0 = ((const float4*)w)[lane * 2], w1 = ((const float4*)w)[lane * 2 + 1];
    float4 b0 = ((const float4*)b)[lane * 2], b1 = ((const float4*)b)[lane * 2 + 1];
    float4 o0, o1;
    o0.x = to_tf32(d0 * rs * w0.x + b0.x); o0.y = to_tf32(d1 * rs * w0.y + b0.y);
    o0.z = to_tf32(d2 * rs * w0.z + b0.z); o0.w = to_tf32(d3 * rs * w0.w + b0.w);
    o1.x = to_tf32(d4 * rs * w1.x + b1.x); o1.y = to_tf32(d5 * rs * w1.y + b1.y);
    o1.z = to_tf32(d6 * rs * w1.z + b1.z); o1.w = to_tf32(d7 * rs * w1.w + b1.w);
    float4* q = (float4*)(out + (size_t)row * C_DIM);
    q[lane * 2] = o0; q[lane * 2 + 1] = o1;
}

// ---------------- tf32 tensor-core NT GEMM (BM=128, BN=128) ----------------
// 3-stage cp.async pipeline, ONE __syncthreads per k-tile.
// B (weights) loaded with cp.async.ca (L1-cached, ~400x reuse); A with .cg.
// MODE 0: QKV  (per-token rows, no bias, tf32-rounded store)
// MODE 1: PROJ (bias, *mask, plain store to projbuf)
// MODE 2: FFN1 (bias, store)
// MODE 3: FFN2 (bias + residual, store)
#define GP 36
#define BUFW 9216       // words per stage (A 128*36 + B 128*36)
#define NSTAGE 3
template <int MODE, int NC, int KD>
__global__ __launch_bounds__(256) void mma_gemm(
    const float* __restrict__ A, const float* __restrict__ Bw,
    const float* __restrict__ bias, const int* __restrict__ gidx,
    const float* __restrict__ maskf, const float* __restrict__ resid,
    float* __restrict__ Cout) {
    extern __shared__ float sm[];
    uint32_t smem_u32 = (uint32_t)__cvta_generic_to_shared(sm);
    const int tid = threadIdx.x, lane = tid & 31, warp = tid >> 5;
    const int wm = warp >> 2, wn = warp & 3;
    const int bm = blockIdx.y * 128, bn = blockIdx.x * 128;

    const int lrow = tid & 127;
    const bool isA = tid < 128;
    const float* gbase;
    if (isA) gbase = A + (size_t)(bm + lrow) * KD;
    else     gbase = Bw + (size_t)(bn + lrow) * KD;
    const uint32_t sdst = smem_u32 + (uint32_t)(((isA ? 0 : 4608) + lrow * GP) * 4);

    const int lr8 = lane & 7, sub = lane >> 3, lb = lane & 15;
    const uint32_t a_off = smem_u32 +
        (uint32_t)(((wm * 64 + (sub & 1) * 8 + lr8) * GP + (sub >> 1) * 4) * 4);
    const uint32_t b_off = smem_u32 +
        (uint32_t)((4608 + (wn * 32 + (lb & 7)) * GP + (lb >> 3) * 4) * 4);

    float acc[4][4][4];
    #pragma unroll
    for (int i = 0; i < 4; i++)
        #pragma unroll
        for (int j = 0; j < 4; j++)
            #pragma unroll
            for (int r = 0; r < 4; r++) acc[i][j][r] = 0.f;

    const int T = KD / 32;
    #pragma unroll
    for (int ps = 0; ps < NSTAGE - 1; ps++) {
        const float* g = gbase + ps * 32;
        uint32_t d = sdst + (uint32_t)(ps * BUFW * 4);
        if (isA) {
            #pragma unroll
            for (int i = 0; i < 8; i++) cp16(d + i * 16, g + i * 4);
        } else {
            #pragma unroll
            for (int i = 0; i < 8; i++) cp16ca(d + i * 16, g + i * 4);
        }
        asm volatile("cp.async.commit_group;");
    }

    int buf = 0, nbuf = NSTAGE - 1;
    for (int t = 0; t < T; t++) {
        asm volatile("cp.async.wait_group %0;" :: "n"(NSTAGE - 2));
        __syncthreads();

        const uint32_t boff = (uint32_t)(buf * BUFW * 4);
        #pragma unroll
        for (int ks = 0; ks < 4; ks++) {
            uint32_t a[4][4], b[4][2];
            #pragma unroll
            for (int i = 0; i < 4; i++)
                ldsm4(a[i], a_off + boff + i * 2304 + ks * 32);
            #pragma unroll
            for (int j = 0; j < 4; j++)
                ldsm2(b[j], b_off + boff + j * 1152 + ks * 32);
            #pragma unroll
            for (int i = 0; i < 4; i++)
                #pragma unroll
                for (int j = 0; j < 4; j++)
                    mma_tf32(acc[i][j], a[i], b[j]);
        }

        if (t + NSTAGE - 1 < T) {
            const float* g = gbase + (t + NSTAGE - 1) * 32;
            uint32_t d = sdst + (uint32_t)(nbuf * BUFW * 4);
            if (isA) {
                #pragma unroll
                for (int i = 0; i < 8; i++) cp16(d + i * 16, g + i * 4);
            } else {
                #pragma unroll
                for (int i = 0; i < 8; i++) cp16ca(d + i * 16, g + i * 4);
            }
        }
        asm volatile("cp.async.commit_group;");
        buf = (buf + 1) % NSTAGE;
        nbuf = (nbuf + 1) % NSTAGE;
    }

    const int er = bm + wm * 64 + (lane >> 2);
    const int ec = bn + wn * 32 + (lane & 3) * 2;
    #pragma unroll
    for (int i = 0; i < 4; i++) {
        const int r0 = er + i * 16, r1 = r0 + 8;
        float mk0 = 0.f, mk1 = 0.f;
        if (MODE == 1) { mk0 = maskf[r0]; mk1 = maskf[r1]; }
        #pragma unroll
        for (int j = 0; j < 4; j++) {
            const int c = ec + j * 8;
            float v0 = acc[i][j][0], v1 = acc[i][j][1];
            float v2 = acc[i][j][2], v3 = acc[i][j][3];
            if (MODE == 0) {
                *(float2*)&Cout[(size_t)r0 * NC + c] =
                    make_float2(to_tf32(v0), to_tf32(v1));
                *(float2*)&Cout[(size_t)r1 * NC + c] =
                    make_float2(to_tf32(v2), to_tf32(v3));
            } else if (MODE == 1) {
                float b0 = bias[c], b1 = bias[c + 1];
                *(float2*)&Cout[(size_t)r0 * NC + c] =
                    make_float2((v0 + b0) * mk0, (v1 + b1) * mk0);
                *(float2*)&Cout[(size_t)r1 * NC + c] =
                    make_float2((v2 + b0) * mk1, (v3 + b1) * mk1);
            } else if (MODE == 2) {
                float b0 = bias[c], b1 = bias[c + 1];
                *(float2*)&Cout[(size_t)r0 * NC + c] = make_float2(v0 + b0, v1 + b1);
                *(float2*)&Cout[(size_t)r1 * NC + c] = make_float2(v2 + b0, v3 + b1);
            } else {
                float b0 = bias[c], b1 = bias[c + 1];
                float2 x0 = *(const float2*)&resid[(size_t)r0 * 256 + c];
                float2 x1v = *(const float2*)&resid[(size_t)r1 * 256 + c];
                *(float2*)&Cout[(size_t)r0 * NC + c] =
                    make_float2(v0 + b0 + x0.x, v1 + b1 + x0.y);
                *(float2*)&Cout[(size_t)r1 * NC + c] =
                    make_float2(v2 + b0 + x1v.x, v3 + b1 + x1v.y);
            }
        }
    }
}

// ---------------- tensor-core flash attention (no-max softmax) -------------
// Split-q: one CTA per (window m, head h, q-half). 8 warps x 32 q-rows.
// 2 CTAs/SM. Reads contiguous window-layout qkv (expanded).
#define ATP 36
#define AT_KOFF (512 + 8 * 1152)          // 9728
#define AT_SMEMW (AT_KOFF + 4 * 1152)     // 14336 words = 57344 B
__global__ __launch_bounds__(256, 2) void attn_mma_kernel(
    const float* __restrict__ qkv, const float* __restrict__ maskf,
    float* __restrict__ attn) {
    extern __shared__ float sm[];
    const uint32_t smb = (uint32_t)__cvta_generic_to_shared(sm);
    const int m = blockIdx.x >> 4;
    const int h = (blockIdx.x >> 1) & 7;
    const int qh = blockIdx.x & 1;
    const int tid = threadIdx.x, lane = tid & 31, wp = tid >> 5;
    const int lr8 = lane & 7, sub = lane >> 3, lb = lane & 15;

    float* maskA = sm;
    float* Qw = sm + 512 + wp * 1152;      // warp's 32-row Q staging / P buffer

    const float* qg = qkv + (size_t)m * 512 * 768 + h * 32;
    const float* kg = qg + 256;
    const float* vg = qg + 512;
    const int qrow0 = qh * 256 + wp * 32;

    for (int w = tid; w < 512; w += 256)
        maskA[w] = (maskf[m * 512 + w] != 0.f) ? 0.f : -1e30f;

    // stage warp's 32 Q rows
    for (int i = lane; i < 256; i += 32) {
        int row = i >> 3, c4 = (i & 7) * 4;
        float4 v = *(const float4*)(qg + (size_t)(qrow0 + row) * 768 + c4);
        *(float4*)&Qw[row * ATP + c4] = v;
    }
    __syncwarp();
    uint32_t qf[2][4][4];
    {
        uint32_t qb = smb + (uint32_t)((512 + wp * 1152) * 4) +
                      (uint32_t)((((sub & 1) * 8 + lr8) * ATP + (sub >> 1) * 4) * 4);
        #pragma unroll
        for (int i = 0; i < 2; i++)
            #pragma unroll
            for (int ks = 0; ks < 4; ks++)
                ldsm4(qf[i][ks], qb + (uint32_t)(i * 16 * ATP * 4 + ks * 32));
    }
    __syncwarp();

    // prologue: K(0), Vt(0)
    {
        int row = tid >> 3, c4 = (tid & 7) * 4;
        float4 kv = *(const float4*)(kg + (size_t)row * 768 + c4);
        *(float4*)&sm[AT_KOFF + row * ATP + c4] = kv;
        float4 vv = *(const float4*)(vg + (size_t)row * 768 + c4);
        sm[AT_KOFF + 2304 + (c4 + 0) * ATP + row] = vv.x;
        sm[AT_KOFF + 2304 + (c4 + 1) * ATP + row] = vv.y;
        sm[AT_KOFF + 2304 + (c4 + 2) * ATP + row] = vv.z;
        sm[AT_KOFF + 2304 + (c4 + 3) * ATP + row] = vv.w;
    }
    __syncthreads();

    float o[2][4][4];
    #pragma unroll
    for (int i = 0; i < 2; i++)
        #pragma unroll
        for (int j = 0; j < 4; j++)
            #pragma unroll
            for (int c = 0; c < 4; c++) o[i][j][c] = 0.f;
    float Ls[2][2];
    #pragma unroll
    for (int i = 0; i < 2; i++) { Ls[i][0] = 0.f; Ls[i][1] = 0.f; }
    const float SCL2 = 0.25503485900582243f;   // log2(e)/sqrt(32)
    const int ldrow = tid >> 3, ldc4 = (tid & 7) * 4;

    for (int kt = 0; kt < 16; kt++) {
        const int cb = kt & 1;
        float4 vpre;
        if (kt < 15) {
            uint32_t d = smb + (uint32_t)((AT_KOFF + (1 - cb) * 1152 +
                                           ldrow * ATP + ldc4) * 4);
            cp16(d, kg + (size_t)((kt + 1) * 32 + ldrow) * 768 + ldc4);
            asm volatile("cp.async.commit_group;");
            vpre = *(const float4*)(vg + (size_t)((kt + 1) * 32 + ldrow) * 768 + ldc4);
        }

        // ---- S = Q . K^T ----
        float s[2][4][4];
        #pragma unroll
        for (int i = 0; i < 2; i++)
            #pragma unroll
            for (int j = 0; j < 4; j++)
                #pragma unroll
                for (int c = 0; c < 4; c++) s[i][j][c] = 0.f;
        {
            uint32_t kb = smb + (uint32_t)((AT_KOFF + cb * 1152) * 4) +
                          (uint32_t)(((lb & 7) * ATP + (lb >> 3) * 4) * 4);
            #pragma unroll
            for (int ks = 0; ks < 4; ks++) {
                uint32_t bf[4][2];
                #pragma unroll
                for (int j = 0; j < 4; j++)
                    ldsm2(bf[j], kb + (uint32_t)(j * 8 * ATP * 4 + ks * 32));
                #pragma unroll
                for (int i = 0; i < 2; i++)
                    #pragma unroll
                    for (int j = 0; j < 4; j++)
                        mma_tf32(s[i][j], qf[i][ks], bf[j]);
            }
        }

        // ---- p = 2^(s*SCL2 + mask), accumulate row sums in registers ----
        float mk[4][2];
        #pragma unroll
        for (int j = 0; j < 4; j++) {
            float2 mm = *(const float2*)&maskA[kt * 32 + j * 8 + 2 * (lane & 3)];
            mk[j][0] = mm.x; mk[j][1] = mm.y;
        }
        #pragma unroll
        for (int i = 0; i < 2; i++)
            #pragma unroll
            for (int j = 0; j < 4; j++)
                #pragma unroll
                for (int c = 0; c < 4; c++) {
                    float p = ex2(s[i][j][c] * SCL2 + mk[j][c & 1]);
                    s[i][j][c] = p;
                    Ls[i][c >> 1] += p;
                }

        // ---- store P into warp-private buffer ----
        {
            int r = lane >> 2, q2 = 2 * (lane & 3);
            #pragma unroll
            for (int i = 0; i < 2; i++)
                #pragma unroll
                for (int j = 0; j < 4; j++) {
                    *(float2*)&Qw[(i * 16 + r) * ATP + j * 8 + q2] =
                        make_float2(s[i][j][0], s[i][j][1]);
                    *(float2*)&Qw[(i * 16 + r + 8) * ATP + j * 8 + q2] =
                        make_float2(s[i][j][2], s[i][j][3]);
                }
        }
        __syncwarp();

        // ---- O += P . V ----
        {
            uint32_t pb = smb + (uint32_t)((512 + wp * 1152) * 4) +
                          (uint32_t)((((sub & 1) * 8 + lr8) * ATP + (sub >> 1) * 4) * 4);
            uint32_t vb = smb + (uint32_t)((AT_KOFF + 2304 + cb * 1152) * 4) +
                          (uint32_t)(((lb & 7) * ATP + (lb >> 3) * 4) * 4);
            #pragma unroll
            for (int ks = 0; ks < 4; ks++) {
                uint32_t pf[2][4], vf[4][2];
                #pragma unroll
                for (int i = 0; i < 2; i++)
                    ldsm4(pf[i], pb + (uint32_t)(i * 16 * ATP * 4 + ks * 32));
                #pragma unroll
                for (int jd = 0; jd < 4; jd++)
                    ldsm2(vf[jd], vb + (uint32_t)(jd * 8 * ATP * 4 + ks * 32));
                #pragma unroll
                for (int i = 0; i < 2; i++)
                    #pragma unroll
                    for (int jd = 0; jd < 4; jd++)
                        mma_tf32(o[i][jd], pf[i], vf[jd]);
            }
        }
        __syncwarp();

        if (kt < 15) {
            float* vt = &sm[AT_KOFF + 2304 + (1 - cb) * 1152];
            vt[(ldc4 + 0) * ATP + ldrow] = vpre.x;
            vt[(ldc4 + 1) * ATP + ldrow] = vpre.y;
            vt[(ldc4 + 2) * ATP + ldrow] = vpre.z;
            vt[(ldc4 + 3) * ATP + ldrow] = vpre.w;
            asm volatile("cp.async.wait_group 0;");
        }
        __syncthreads();
    }

    // ---- final row-sum reduction + normalize + writeout ----
    #pragma unroll
    for (int i = 0; i < 2; i++)
        #pragma unroll
        for (int rh = 0; rh < 2; rh++) {
            float v = Ls[i][rh];
            v += __shfl_xor_sync(FULLMASK, v, 1);
            v += __shfl_xor_sync(FULLMASK, v, 2);
            Ls[i][rh] = v;
        }
    {
        int r = lane >> 2, q2 = 2 * (lane & 3);
        #pragma unroll
        for (int i = 0; i < 2; i++) {
            float inv0 = 1.f / Ls[i][0], inv1 = 1.f / Ls[i][1];
            int row0 = m * 512 + qrow0 + i * 16 + r;
            #pragma unroll
            for (int jd = 0; jd < 4; jd++) {
                int col = h * 32 + jd * 8 + q2;
                *(float2*)&attn[(size_t)row0 * 256 + col] =
                    make_float2(o[i][jd][0] * inv0, o[i][jd][1] * inv0);
                *(float2*)&attn[(size_t)(row0 + 8) * 256 + col] =
                    make_float2(o[i][jd][2] * inv1, o[i][jd][3] * inv1);
            }
        }
    }
}

// ---------------- BatchNorm stats (two-pass, deterministic) ----------------
__global__ void bn_part_kernel(const float* __restrict__ h, float* __restrict__ part) {
    int col = threadIdx.x;
    int b = blockIdx.x;
    float s = 0.f, s2 = 0.f;
    const float* p = h + (size_t)b * 128 * HIDD + col;
    #pragma unroll 4
    for (int r = 0; r < 128; r++) {
        float v = p[(size_t)r * HIDD];
        s += v; s2 += v * v;
    }
    part[b * HIDD + col] = s;
    part[200 * HIDD + b * HIDD + col] = s2;
}

__global__ void bn_final_kernel(const float* __restrict__ part,
                                const float* __restrict__ bn_w,
                                const float* __restrict__ bn_b,
                                float* __restrict__ scale, float* __restrict__ beta) {
    int col = blockIdx.x * 256 + threadIdx.x;
    float s = 0.f, s2 = 0.f;
    for (int b = 0; b < 200; b++) {
        s += part[b * HIDD + col];
        s2 += part[200 * HIDD + b * HIDD + col];
    }
    float mu = s * (1.0f / 25600.0f);
    float var = s2 * (1.0f / 25600.0f) - mu * mu;
    float sc = bn_w[col] * rsqrtf(var + 1e-5f);
    scale[col] = sc;
    beta[col] = bn_b[col] - mu * sc;
}

// ---------------- apply BN+ReLU in place (float4, tf32-rounded) ------------
__global__ void bn_apply_kernel(float* __restrict__ h,
                                const float* __restrict__ scale,
                                const float* __restrict__ beta) {
    int i = blockIdx.x * 256 + threadIdx.x;    // float4 index
    int c = (i * 4) & (HIDD - 1);
    float4 v = ((float4*)h)[i];
    float4 sc = *(const float4*)&scale[c];
    float4 be = *(const float4*)&beta[c];
    v.x = to_tf32(fmaxf(0.f, v.x * sc.x + be.x));
    v.y = to_tf32(fmaxf(0.f, v.y * sc.y + be.y));
    v.z = to_tf32(fmaxf(0.f, v.z * sc.z + be.z));
    v.w = to_tf32(fmaxf(0.f, v.w * sc.w + be.w));
    ((float4*)h)[i] = v;
}

// ---------------- launch ----------------------------------------------------
extern "C" void kernel_launch(void* const* d_in, const int* in_sizes, int n_in,
                              void* d_out, int out_size) {
    (void)in_sizes; (void)n_in; (void)out_size;
    const float* x      = (const float*)d_in[0];
    const int*   widx   = (const int*)d_in[1];
    const float* ln1_w  = (const float*)d_in[3];
    const float* ln1_b  = (const float*)d_in[4];
    const float* w_qkv  = (const float*)d_in[5];
    const float* w_proj = (const float*)d_in[6];
    const float* b_proj = (const float*)d_in[7];
    const float* ln2_w  = (const float*)d_in[8];
    const float* ln2_b  = (const float*)d_in[9];
    const float* w1     = (const float*)d_in[10];
    const float* b1     = (const float*)d_in[11];
    const float* bn_w   = (const float*)d_in[12];
    const float* bn_b   = (const float*)d_in[13];
    const float* w2     = (const float*)d_in[14];
    const float* b2     = (const float*)d_in[15];
    float* out = (float*)d_out;

    float *xin, *qkvtok, *qkv, *attn, *x1, *hbuf, *part, *scale, *beta, *maskf;
    float *wq, *wp, *tw1, *tw2;
    int *cnt, *inv;
    cudaGetSymbolAddress((void**)&xin,    g_xin);
    cudaGetSymbolAddress((void**)&qkvtok, g_qkvtok);
    cudaGetSymbolAddress((void**)&qkv,    g_qkv);
    cudaGetSymbolAddress((void**)&attn,   g_attn);
    cudaGetSymbolAddress((void**)&x1,     g_x1);
    cudaGetSymbolAddress((void**)&hbuf,   g_hbuf);
    cudaGetSymbolAddress((void**)&part,   g_bnpart);
    cudaGetSymbolAddress((void**)&scale,  g_scale);
    cudaGetSymbolAddress((void**)&beta,   g_beta);
    cudaGetSymbolAddress((void**)&maskf,  g_maskf);
    cudaGetSymbolAddress((void**)&cnt,    g_cnt);
    cudaGetSymbolAddress((void**)&inv,    g_inv);
    cudaGetSymbolAddress((void**)&wq,     g_wq);
    cudaGetSymbolAddress((void**)&wp,     g_wp);
    cudaGetSymbolAddress((void**)&tw1,    g_w1);
    cudaGetSymbolAddress((void**)&tw2,    g_w2);
    float* projbuf = qkv;   // alias: window-layout qkv dead after attention

    const int gemm_smem = NSTAGE * BUFW * (int)sizeof(float);   // 110592
    cudaFuncSetAttribute(mma_gemm<0, 768, 256>,
                         cudaFuncAttributeMaxDynamicSharedMemorySize, gemm_smem);
    cudaFuncSetAttribute(mma_gemm<1, 256, 256>,
                         cudaFuncAttributeMaxDynamicSharedMemorySize, gemm_smem);
    cudaFuncSetAttribute(mma_gemm<2, 512, 256>,
                         cudaFuncAttributeMaxDynamicSharedMemorySize, gemm_smem);
    cudaFuncSetAttribute(mma_gemm<3, 256, 512>,
                         cudaFuncAttributeMaxDynamicSharedMemorySize, gemm_smem);
    const int attn_smem = AT_SMEMW * (int)sizeof(float);   // 57344
    cudaFuncSetAttribute(attn_mma_kernel,
                         cudaFuncAttributeMaxDynamicSharedMemorySize, attn_smem);

    cudaMemsetAsync(cnt, 0, N_TOK * sizeof(int));

    cvt_all_kernel<<<2048, 256>>>(w_qkv, wq, w_proj, wp, w1, tw1, w2, tw2);
    mask_count_kernel<<<MW / 256, 256>>>(widx, maskf, cnt, inv);
    ln_kernel<<<N_TOK / 8, 256>>>(x, ln1_w, ln1_b, xin, N_TOK);

    // per-token QKV (deduped: windows overlap 50%, each token computed once)
    mma_gemm<0, 768, 256><<<dim3(6, 200), 256, gemm_smem>>>(
        xin, wq, nullptr, nullptr, nullptr, nullptr, qkvtok);

    // expand to window layout (pure bandwidth; values bitwise identical)
    expand_kernel<<<MW * 192 / 256, 256>>>(qkvtok, widx, qkv);

    attn_mma_kernel<<<100 * HEADS * 2, 256, attn_smem>>>(qkv, maskf, attn);

    mma_gemm<1, 256, 256><<<dim3(2, 400), 256, gemm_smem>>>(
        attn, wp, b_proj, nullptr, maskf, nullptr, projbuf);

    x1ln2_kernel<<<N_TOK / 8, 256>>>(x, projbuf, cnt, inv, ln2_w, ln2_b, x1, xin);

    mma_gemm<2, 512, 256><<<dim3(4, 200), 256, gemm_smem>>>(
        xin, tw1, b1, nullptr, nullptr, nullptr, hbuf);

    bn_part_kernel<<<200, HIDD>>>(hbuf, part);
    bn_final_kernel<<<2, 256>>>(part, bn_w, bn_b, scale, beta);
    bn_apply_kernel<<<N_TOK * HIDD / 1024, 256>>>(hbuf, scale, beta);

    mma_gemm<3, 256, 512><<<dim3(2, 200), 256, gemm_smem>>>(
        hbuf, tw2, b2, nullptr, nullptr, x1, out);
}

// round 12
// speedup vs baseline: 1.9818x; 1.0530x over previous
#include <cuda_runtime.h>
#include <cstdint>
#include <math.h>

#define FULLMASK 0xFFFFFFFFu

#define N_TOK 25600
#define C_DIM 256
#define WLEN  512
#define MW    51200     // 100 windows * 512
#define HEADS 8
#define DHEAD 32
#define HIDD  512
#define NWIN  100

// ---------------- scratch (static device globals; no allocations) ----------
static __device__ float g_xin[N_TOK * C_DIM];
static __device__ float g_qkvtok[N_TOK * 768]; // per-token QKV (deduped)
static __device__ float g_projbuf[MW * C_DIM]; // proj output (window rows)
static __device__ float g_attn[MW * C_DIM];
static __device__ float g_x1[N_TOK * C_DIM];
static __device__ float g_hbuf[N_TOK * HIDD];
static __device__ float g_bnpart[2 * 200 * HIDD];
static __device__ float g_scale[HIDD];
static __device__ float g_beta[HIDD];
static __device__ float g_maskf[MW];
static __device__ int   g_cnt[N_TOK];
static __device__ int   g_inv[2 * N_TOK];
static __device__ int   g_wbase[NWIN];
static __device__ int   g_wlenm1[NWIN];
// tf32-rounded weight copies
static __device__ float g_wq[768 * 256];
static __device__ float g_wp[256 * 256];
static __device__ float g_w1[512 * 256];
static __device__ float g_w2[256 * 512];

// ---------------- helpers ---------------------------------------------------
__device__ __forceinline__ float to_tf32(float x) {
    unsigned r;
    asm("cvt.rna.tf32.f32 %0, %1;" : "=r"(r) : "f"(x));
    return __uint_as_float(r);
}
__device__ __forceinline__ float ex2(float x) {
    float r;
    asm("ex2.approx.f32 %0, %1;" : "=f"(r) : "f"(x));
    return r;
}
__device__ __forceinline__ void ldsm4(uint32_t* r, uint32_t addr) {
    asm volatile("ldmatrix.sync.aligned.m8n8.x4.shared.b16 {%0,%1,%2,%3}, [%4];"
                 : "=r"(r[0]), "=r"(r[1]), "=r"(r[2]), "=r"(r[3]) : "r"(addr));
}
__device__ __forceinline__ void ldsm2(uint32_t* r, uint32_t addr) {
    asm volatile("ldmatrix.sync.aligned.m8n8.x2.shared.b16 {%0,%1}, [%2];"
                 : "=r"(r[0]), "=r"(r[1]) : "r"(addr));
}
__device__ __forceinline__ void mma_tf32(float* c, const uint32_t* a, const uint32_t* b) {
    asm volatile(
        "mma.sync.aligned.m16n8k8.row.col.f32.tf32.tf32.f32 "
        "{%0,%1,%2,%3}, {%4,%5,%6,%7}, {%8,%9}, {%0,%1,%2,%3};"
        : "+f"(c[0]), "+f"(c[1]), "+f"(c[2]), "+f"(c[3])
        : "r"(a[0]), "r"(a[1]), "r"(a[2]), "r"(a[3]), "r"(b[0]), "r"(b[1]));
}
__device__ __forceinline__ void cp16(uint32_t smem, const void* g) {
    asm volatile("cp.async.cg.shared.global [%0], [%1], 16;" :: "r"(smem), "l"(g));
}
__device__ __forceinline__ void cp16ca(uint32_t smem, const void* g) {
    asm volatile("cp.async.ca.shared.global [%0], [%1], 16;" :: "r"(smem), "l"(g));
}

// ---------------- mask + inverse index from win_idx ------------------------
__global__ void mask_count_kernel(const int* __restrict__ win_idx,
                                  float* __restrict__ maskf,
                                  int* __restrict__ cnt,
                                  int* __restrict__ inv) {
    int r = blockIdx.x * 256 + threadIdx.x;
    if (r >= MW) return;
    int w = r & (WLEN - 1);
    bool valid = (w == 0 || win_idx[r] != win_idx[r - 1]);
    maskf[r] = valid ? 1.0f : 0.0f;
    if (valid) {
        int tok = win_idx[r];
        int slot = atomicAdd(&cnt[tok], 1);
        if (slot < 2) inv[tok * 2 + slot] = r;
    }
}

// ---------------- per-window base + len-1 (contiguous range structure) -----
__global__ void winmeta_kernel(const int* __restrict__ win_idx,
                               int* __restrict__ wbase, int* __restrict__ wlenm1) {
    int m = threadIdx.x;
    if (m >= NWIN) return;
    int base = win_idx[m * WLEN];
    wbase[m] = base;
    wlenm1[m] = win_idx[m * WLEN + WLEN - 1] - base;
}

// ---------------- merged tf32 rounding of all 4 weights --------------------
__global__ void cvt_all_kernel(const float* __restrict__ s0, float* __restrict__ d0,
                               const float* __restrict__ s1, float* __restrict__ d1,
                               const float* __restrict__ s2, float* __restrict__ d2,
                               const float* __restrict__ s3, float* __restrict__ d3) {
    int i = blockIdx.x * 256 + threadIdx.x;   // 524288 total
    if (i < 196608)      d0[i] = to_tf32(s0[i]);
    else if (i < 262144) d1[i - 196608] = to_tf32(s1[i - 196608]);
    else if (i < 393216) d2[i - 262144] = to_tf32(s2[i - 262144]);
    else                 d3[i - 393216] = to_tf32(s3[i - 393216]);
}

// ---------------- LayerNorm over C=256 (tf32-rounded output) ---------------
__global__ __launch_bounds__(256) void ln_kernel(const float* __restrict__ in,
                                                 const float* __restrict__ w,
                                                 const float* __restrict__ b,
                                                 float* __restrict__ out,
                                                 int rows) {
    int warp = threadIdx.x >> 5, lane = threadIdx.x & 31;
    int row = blockIdx.x * 8 + warp;
    if (row >= rows) return;
    const float4* p = (const float4*)(in + (size_t)row * C_DIM);
    float4 v0 = p[lane * 2], v1 = p[lane * 2 + 1];
    float s = v0.x + v0.y + v0.z + v0.w + v1.x + v1.y + v1.z + v1.w;
    #pragma unroll
    for (int off = 16; off; off >>= 1) s += __shfl_xor_sync(FULLMASK, s, off);
    float mu = s * (1.0f / 256.0f);
    float d0 = v0.x - mu, d1 = v0.y - mu, d2 = v0.z - mu, d3 = v0.w - mu;
    float d4 = v1.x - mu, d5 = v1.y - mu, d6 = v1.z - mu, d7 = v1.w - mu;
    float s2 = d0*d0 + d1*d1 + d2*d2 + d3*d3 + d4*d4 + d5*d5 + d6*d6 + d7*d7;
    #pragma unroll
    for (int off = 16; off; off >>= 1) s2 += __shfl_xor_sync(FULLMASK, s2, off);
    float rs = rsqrtf(s2 * (1.0f / 256.0f) + 1e-5f);
    float4 w0 = ((const float4*)w)[lane * 2], w1 = ((const float4*)w)[lane * 2 + 1];
    float4 b0 = ((const float4*)b)[lane * 2], b1 = ((const float4*)b)[lane * 2 + 1];
    float4 o0, o1;
    o0.x = to_tf32(d0 * rs * w0.x + b0.x); o0.y = to_tf32(d1 * rs * w0.y + b0.y);
    o0.z = to_tf32(d2 * rs * w0.z + b0.z); o0.w = to_tf32(d3 * rs * w0.w + b0.w);
    o1.x = to_tf32(d4 * rs * w1.x + b1.x); o1.y = to_tf32(d5 * rs * w1.y + b1.y);
    o1.z = to_tf32(d6 * rs * w1.z + b1.z); o1.w = to_tf32(d7 * rs * w1.w + b1.w);
    float4* q = (float4*)(out + (size_t)row * C_DIM);
    q[lane * 2] = o0; q[lane * 2 + 1] = o1;
}

// ---------------- gather proj + x1 + LayerNorm2 (fused) --------------------
__global__ __launch_bounds__(256) void x1ln2_kernel(
    const float* __restrict__ x, const float* __restrict__ projbuf,
    const int* __restrict__ cnt, const int* __restrict__ inv,
    const float* __restrict__ w, const float* __restrict__ b,
    float* __restrict__ x1, float* __restrict__ out) {
    int warp = threadIdx.x >> 5, lane = threadIdx.x & 31;
    int row = blockIdx.x * 8 + warp;
    int c = cnt[row];
    const float4* xp = (const float4*)(x + (size_t)row * C_DIM);
    float4 v0 = xp[lane * 2], v1 = xp[lane * 2 + 1];
    float4 y0 = make_float4(0.f, 0.f, 0.f, 0.f), y1 = y0;
    if (c >= 1) {
        const float4* p = (const float4*)(projbuf + (size_t)inv[row * 2] * C_DIM);
        y0 = p[lane * 2]; y1 = p[lane * 2 + 1];
    }
    if (c >= 2) {
        const float4* p = (const float4*)(projbuf + (size_t)inv[row * 2 + 1] * C_DIM);
        float4 a = p[lane * 2], bq = p[lane * 2 + 1];
        y0.x += a.x; y0.y += a.y; y0.z += a.z; y0.w += a.w;
        y1.x += bq.x; y1.y += bq.y; y1.z += bq.z; y1.w += bq.w;
    }
    float ic = 1.0f / fmaxf((float)c, 1.0f);
    v0.x += y0.x * ic; v0.y += y0.y * ic; v0.z += y0.z * ic; v0.w += y0.w * ic;
    v1.x += y1.x * ic; v1.y += y1.y * ic; v1.z += y1.z * ic; v1.w += y1.w * ic;
    float4* xq = (float4*)(x1 + (size_t)row * C_DIM);
    xq[lane * 2] = v0; xq[lane * 2 + 1] = v1;
    float s = v0.x + v0.y + v0.z + v0.w + v1.x + v1.y + v1.z + v1.w;
    #pragma unroll
    for (int off = 16; off; off >>= 1) s += __shfl_xor_sync(FULLMASK, s, off);
    float mu = s * (1.0f / 256.0f);
    float d0 = v0.x - mu, d1 = v0.y - mu, d2 = v0.z - mu, d3 = v0.w - mu;
    float d4 = v1.x - mu, d5 = v1.y - mu, d6 = v1.z - mu, d7 = v1.w - mu;
    float s2 = d0*d0 + d1*d1 + d2*d2 + d3*d3 + d4*d4 + d5*d5 + d6*d6 + d7*d7;
    #pragma unroll
    for (int off = 16; off; off >>= 1) s2 += __shfl_xor_sync(FULLMASK, s2, off);
    float rs = rsqrtf(s2 * (1.0f / 256.0f) + 1e-5f);
    float4 w0 = ((const float4*)w)[lane * 2], w1 = ((const float4*)w)[lane * 2 + 1];
    float4 b0 = ((const float4*)b)[lane * 2], b1 = ((const float4*)b)[lane * 2 + 1];
    float4 o0, o1;
    o0.x = to_tf32(d0 * rs * w0.x + b0.x); o0.y = to_tf32(d1 * rs * w0.y + b0.y);
    o0.z = to_tf32(d2 * rs * w0.z + b0.z); o0.w = to_tf32(d3 * rs * w0.w + b0.w);
    o1.x = to_tf32(d4 * rs * w1.x + b1.x); o1.y = to_tf32(d5 * rs * w1.y + b1.y);
    o1.z = to_tf32(d6 * rs * w1.z + b1.z); o1.w = to_tf32(d7 * rs * w1.w + b1.w);
    float4* q = (float4*)(out + (size_t)row * C_DIM);
    q[lane * 2] = o0; q[lane * 2 + 1] = o1;
}

// ---------------- tf32 tensor-core NT GEMM (BM=128, BN=128) ----------------
// 3-stage cp.async pipeline, ONE __syncthreads per k-tile.
// B (weights) loaded with cp.async.ca (L1-cached, ~400x reuse); A with .cg.
#define GP 36
#define BUFW 9216       // words per stage (A 128*36 + B 128*36)
#define NSTAGE 3
template <int MODE, int NC, int KD>
__global__ __launch_bounds__(256) void mma_gemm(
    const float* __restrict__ A, const float* __restrict__ Bw,
    const float* __restrict__ bias, const int* __restrict__ gidx,
    const float* __restrict__ maskf, const float* __restrict__ resid,
    float* __restrict__ Cout) {
    extern __shared__ float sm[];
    uint32_t smem_u32 = (uint32_t)__cvta_generic_to_shared(sm);
    const int tid = threadIdx.x, lane = tid & 31, warp = tid >> 5;
    const int wm = warp >> 2, wn = warp & 3;
    const int bm = blockIdx.y * 128, bn = blockIdx.x * 128;

    const int lrow = tid & 127;
    const bool isA = tid < 128;
    const float* gbase;
    if (isA) gbase = A + (size_t)(bm + lrow) * KD;
    else     gbase = Bw + (size_t)(bn + lrow) * KD;
    const uint32_t sdst = smem_u32 + (uint32_t)(((isA ? 0 : 4608) + lrow * GP) * 4);

    const int lr8 = lane & 7, sub = lane >> 3, lb = lane & 15;
    const uint32_t a_off = smem_u32 +
        (uint32_t)(((wm * 64 + (sub & 1) * 8 + lr8) * GP + (sub >> 1) * 4) * 4);
    const uint32_t b_off = smem_u32 +
        (uint32_t)((4608 + (wn * 32 + (lb & 7)) * GP + (lb >> 3) * 4) * 4);

    float acc[4][4][4];
    #pragma unroll
    for (int i = 0; i < 4; i++)
        #pragma unroll
        for (int j = 0; j < 4; j++)
            #pragma unroll
            for (int r = 0; r < 4; r++) acc[i][j][r] = 0.f;

    const int T = KD / 32;
    #pragma unroll
    for (int ps = 0; ps < NSTAGE - 1; ps++) {
        const float* g = gbase + ps * 32;
        uint32_t d = sdst + (uint32_t)(ps * BUFW * 4);
        if (isA) {
            #pragma unroll
            for (int i = 0; i < 8; i++) cp16(d + i * 16, g + i * 4);
        } else {
            #pragma unroll
            for (int i = 0; i < 8; i++) cp16ca(d + i * 16, g + i * 4);
        }
        asm volatile("cp.async.commit_group;");
    }

    int buf = 0, nbuf = NSTAGE - 1;
    for (int t = 0; t < T; t++) {
        asm volatile("cp.async.wait_group %0;" :: "n"(NSTAGE - 2));
        __syncthreads();

        const uint32_t boff = (uint32_t)(buf * BUFW * 4);
        #pragma unroll
        for (int ks = 0; ks < 4; ks++) {
            uint32_t a[4][4], b[4][2];
            #pragma unroll
            for (int i = 0; i < 4; i++)
                ldsm4(a[i], a_off + boff + i * 2304 + ks * 32);
            #pragma unroll
            for (int j = 0; j < 4; j++)
                ldsm2(b[j], b_off + boff + j * 1152 + ks * 32);
            #pragma unroll
            for (int i = 0; i < 4; i++)
                #pragma unroll
                for (int j = 0; j < 4; j++)
                    mma_tf32(acc[i][j], a[i], b[j]);
        }

        if (t + NSTAGE - 1 < T) {
            const float* g = gbase + (t + NSTAGE - 1) * 32;
            uint32_t d = sdst + (uint32_t)(nbuf * BUFW * 4);
            if (isA) {
                #pragma unroll
                for (int i = 0; i < 8; i++) cp16(d + i * 16, g + i * 4);
            } else {
                #pragma unroll
                for (int i = 0; i < 8; i++) cp16ca(d + i * 16, g + i * 4);
            }
        }
        asm volatile("cp.async.commit_group;");
        buf = (buf + 1) % NSTAGE;
        nbuf = (nbuf + 1) % NSTAGE;
    }

    const int er = bm + wm * 64 + (lane >> 2);
    const int ec = bn + wn * 32 + (lane & 3) * 2;
    #pragma unroll
    for (int i = 0; i < 4; i++) {
        const int r0 = er + i * 16, r1 = r0 + 8;
        float mk0 = 0.f, mk1 = 0.f;
        if (MODE == 1) { mk0 = maskf[r0]; mk1 = maskf[r1]; }
        #pragma unroll
        for (int j = 0; j < 4; j++) {
            const int c = ec + j * 8;
            float v0 = acc[i][j][0], v1 = acc[i][j][1];
            float v2 = acc[i][j][2], v3 = acc[i][j][3];
            if (MODE == 0) {
                *(float2*)&Cout[(size_t)r0 * NC + c] =
                    make_float2(to_tf32(v0), to_tf32(v1));
                *(float2*)&Cout[(size_t)r1 * NC + c] =
                    make_float2(to_tf32(v2), to_tf32(v3));
            } else if (MODE == 1) {
                float b0 = bias[c], b1 = bias[c + 1];
                *(float2*)&Cout[(size_t)r0 * NC + c] =
                    make_float2((v0 + b0) * mk0, (v1 + b1) * mk0);
                *(float2*)&Cout[(size_t)r1 * NC + c] =
                    make_float2((v2 + b0) * mk1, (v3 + b1) * mk1);
            } else if (MODE == 2) {
                float b0 = bias[c], b1 = bias[c + 1];
                *(float2*)&Cout[(size_t)r0 * NC + c] = make_float2(v0 + b0, v1 + b1);
                *(float2*)&Cout[(size_t)r1 * NC + c] = make_float2(v2 + b0, v3 + b1);
            } else {
                float b0 = bias[c], b1 = bias[c + 1];
                float2 x0 = *(const float2*)&resid[(size_t)r0 * 256 + c];
                float2 x1v = *(const float2*)&resid[(size_t)r1 * 256 + c];
                *(float2*)&Cout[(size_t)r0 * NC + c] =
                    make_float2(v0 + b0 + x0.x, v1 + b1 + x0.y);
                *(float2*)&Cout[(size_t)r1 * NC + c] =
                    make_float2(v2 + b0 + x1v.x, v3 + b1 + x1v.y);
            }
        }
    }
}

// ---------------- tensor-core flash attention (no-max softmax) -------------
// Split-q: one CTA per (window m, head h, q-half). 8 warps x 32 q-rows.
// 2 CTAs/SM. Reads per-token qkv directly: window rows are a contiguous
// token range with tail clamp, tok(w) = base + min(w, len-1) — pure
// arithmetic, no index table, all load addresses affine.
#define ATP 36
#define AT_KOFF (512 + 8 * 1152)          // 9728
#define AT_SMEMW (AT_KOFF + 4 * 1152)     // 14336 words = 57344 B
__global__ __launch_bounds__(256, 2) void attn_mma_kernel(
    const float* __restrict__ qkvtok,
    const int* __restrict__ wbase, const int* __restrict__ wlenm1,
    const float* __restrict__ maskf, float* __restrict__ attn) {
    extern __shared__ float sm[];
    const uint32_t smb = (uint32_t)__cvta_generic_to_shared(sm);
    const int m = blockIdx.x >> 4;
    const int h = (blockIdx.x >> 1) & 7;
    const int qh = blockIdx.x & 1;
    const int tid = threadIdx.x, lane = tid & 31, wp = tid >> 5;
    const int lr8 = lane & 7, sub = lane >> 3, lb = lane & 15;

    const int base = __ldg(&wbase[m]);
    const int lenm1 = __ldg(&wlenm1[m]);

    float* maskA = sm;
    float* Qw = sm + 512 + wp * 1152;      // warp's 32-row Q staging / P buffer

    const float* qk = qkvtok + h * 32;     // +256 for K, +512 for V
    const int qrow0 = qh * 256 + wp * 32;

    for (int w = tid; w < 512; w += 256)
        maskA[w] = (maskf[m * 512 + w] != 0.f) ? 0.f : -1e30f;

    // stage warp's 32 Q rows
    for (int i = lane; i < 256; i += 32) {
        int row = i >> 3, c4 = (i & 7) * 4;
        int tok = base + min(qrow0 + row, lenm1);
        float4 v = *(const float4*)(qk + (size_t)tok * 768 + c4);
        *(float4*)&Qw[row * ATP + c4] = v;
    }
    __syncwarp();
    uint32_t qf[2][4][4];
    {
        uint32_t qb = smb + (uint32_t)((512 + wp * 1152) * 4) +
                      (uint32_t)((((sub & 1) * 8 + lr8) * ATP + (sub >> 1) * 4) * 4);
        #pragma unroll
        for (int i = 0; i < 2; i++)
            #pragma unroll
            for (int ks = 0; ks < 4; ks++)
                ldsm4(qf[i][ks], qb + (uint32_t)(i * 16 * ATP * 4 + ks * 32));
    }
    __syncwarp();

    // prologue: K(0), Vt(0)
    {
        int row = tid >> 3, c4 = (tid & 7) * 4;
        int tok = base + min(row, lenm1);
        float4 kv = *(const float4*)(qk + (size_t)tok * 768 + 256 + c4);
        *(float4*)&sm[AT_KOFF + row * ATP + c4] = kv;
        float4 vv = *(const float4*)(qk + (size_t)tok * 768 + 512 + c4);
        sm[AT_KOFF + 2304 + (c4 + 0) * ATP + row] = vv.x;
        sm[AT_KOFF + 2304 + (c4 + 1) * ATP + row] = vv.y;
        sm[AT_KOFF + 2304 + (c4 + 2) * ATP + row] = vv.z;
        sm[AT_KOFF + 2304 + (c4 + 3) * ATP + row] = vv.w;
    }
    __syncthreads();

    float o[2][4][4];
    #pragma unroll
    for (int i = 0; i < 2; i++)
        #pragma unroll
        for (int j = 0; j < 4; j++)
            #pragma unroll
            for (int c = 0; c < 4; c++) o[i][j][c] = 0.f;
    float Ls[2][2];
    #pragma unroll
    for (int i = 0; i < 2; i++) { Ls[i][0] = 0.f; Ls[i][1] = 0.f; }
    const float SCL2 = 0.25503485900582243f;   // log2(e)/sqrt(32)
    const int ldrow = tid >> 3, ldc4 = (tid & 7) * 4;

    for (int kt = 0; kt < 16; kt++) {
        const int cb = kt & 1;
        float4 vpre;
        if (kt < 15) {
            int tok = base + min((kt + 1) * 32 + ldrow, lenm1);
            uint32_t d = smb + (uint32_t)((AT_KOFF + (1 - cb) * 1152 +
                                           ldrow * ATP + ldc4) * 4);
            cp16(d, qk + (size_t)tok * 768 + 256 + ldc4);
            asm volatile("cp.async.commit_group;");
            vpre = *(const float4*)(qk + (size_t)tok * 768 + 512 + ldc4);
        }

        // ---- S = Q . K^T ----
        float s[2][4][4];
        #pragma unroll
        for (int i = 0; i < 2; i++)
            #pragma unroll
            for (int j = 0; j < 4; j++)
                #pragma unroll
                for (int c = 0; c < 4; c++) s[i][j][c] = 0.f;
        {
            uint32_t kb = smb + (uint32_t)((AT_KOFF + cb * 1152) * 4) +
                          (uint32_t)(((lb & 7) * ATP + (lb >> 3) * 4) * 4);
            #pragma unroll
            for (int ks = 0; ks < 4; ks++) {
                uint32_t bf[4][2];
                #pragma unroll
                for (int j = 0; j < 4; j++)
                    ldsm2(bf[j], kb + (uint32_t)(j * 8 * ATP * 4 + ks * 32));
                #pragma unroll
                for (int i = 0; i < 2; i++)
                    #pragma unroll
                    for (int j = 0; j < 4; j++)
                        mma_tf32(s[i][j], qf[i][ks], bf[j]);
            }
        }

        // ---- p = 2^(s*SCL2 + mask), accumulate row sums in registers ----
        float mk[4][2];
        #pragma unroll
        for (int j = 0; j < 4; j++) {
            float2 mm = *(const float2*)&maskA[kt * 32 + j * 8 + 2 * (lane & 3)];
            mk[j][0] = mm.x; mk[j][1] = mm.y;
        }
        #pragma unroll
        for (int i = 0; i < 2; i++)
            #pragma unroll
            for (int j = 0; j < 4; j++)
                #pragma unroll
                for (int c = 0; c < 4; c++) {
                    float p = ex2(s[i][j][c] * SCL2 + mk[j][c & 1]);
                    s[i][j][c] = p;
                    Ls[i][c >> 1] += p;
                }

        // ---- store P into warp-private buffer ----
        {
            int r = lane >> 2, q2 = 2 * (lane & 3);
            #pragma unroll
            for (int i = 0; i < 2; i++)
                #pragma unroll
                for (int j = 0; j < 4; j++) {
                    *(float2*)&Qw[(i * 16 + r) * ATP + j * 8 + q2] =
                        make_float2(s[i][j][0], s[i][j][1]);
                    *(float2*)&Qw[(i * 16 + r + 8) * ATP + j * 8 + q2] =
                        make_float2(s[i][j][2], s[i][j][3]);
                }
        }
        __syncwarp();

        // ---- O += P . V ----
        {
            uint32_t pb = smb + (uint32_t)((512 + wp * 1152) * 4) +
                          (uint32_t)((((sub & 1) * 8 + lr8) * ATP + (sub >> 1) * 4) * 4);
            uint32_t vb = smb + (uint32_t)((AT_KOFF + 2304 + cb * 1152) * 4) +
                          (uint32_t)(((lb & 7) * ATP + (lb >> 3) * 4) * 4);
            #pragma unroll
            for (int ks = 0; ks < 4; ks++) {
                uint32_t pf[2][4], vf[4][2];
                #pragma unroll
                for (int i = 0; i < 2; i++)
                    ldsm4(pf[i], pb + (uint32_t)(i * 16 * ATP * 4 + ks * 32));
                #pragma unroll
                for (int jd = 0; jd < 4; jd++)
                    ldsm2(vf[jd], vb + (uint32_t)(jd * 8 * ATP * 4 + ks * 32));
                #pragma unroll
                for (int i = 0; i < 2; i++)
                    #pragma unroll
                    for (int jd = 0; jd < 4; jd++)
                        mma_tf32(o[i][jd], pf[i], vf[jd]);
            }
        }
        __syncwarp();

        if (kt < 15) {
            float* vt = &sm[AT_KOFF + 2304 + (1 - cb) * 1152];
            vt[(ldc4 + 0) * ATP + ldrow] = vpre.x;
            vt[(ldc4 + 1) * ATP + ldrow] = vpre.y;
            vt[(ldc4 + 2) * ATP + ldrow] = vpre.z;
            vt[(ldc4 + 3) * ATP + ldrow] = vpre.w;
            asm volatile("cp.async.wait_group 0;");
        }
        __syncthreads();
    }

    // ---- final row-sum reduction + normalize + writeout ----
    #pragma unroll
    for (int i = 0; i < 2; i++)
        #pragma unroll
        for (int rh = 0; rh < 2; rh++) {
            float v = Ls[i][rh];
            v += __shfl_xor_sync(FULLMASK, v, 1);
            v += __shfl_xor_sync(FULLMASK, v, 2);
            Ls[i][rh] = v;
        }
    {
        int r = lane >> 2, q2 = 2 * (lane & 3);
        #pragma unroll
        for (int i = 0; i < 2; i++) {
            float inv0 = 1.f / Ls[i][0], inv1 = 1.f / Ls[i][1];
            int row0 = m * 512 + qrow0 + i * 16 + r;
            #pragma unroll
            for (int jd = 0; jd < 4; jd++) {
                int col = h * 32 + jd * 8 + q2;
                *(float2*)&attn[(size_t)row0 * 256 + col] =
                    make_float2(o[i][jd][0] * inv0, o[i][jd][1] * inv0);
                *(float2*)&attn[(size_t)(row0 + 8) * 256 + col] =
                    make_float2(o[i][jd][2] * inv1, o[i][jd][3] * inv1);
            }
        }
    }
}

// ---------------- BatchNorm stats (two-pass, deterministic) ----------------
__global__ void bn_part_kernel(const float* __restrict__ h, float* __restrict__ part) {
    int col = threadIdx.x;
    int b = blockIdx.x;
    float s = 0.f, s2 = 0.f;
    const float* p = h + (size_t)b * 128 * HIDD + col;
    #pragma unroll 4
    for (int r = 0; r < 128; r++) {
        float v = p[(size_t)r * HIDD];
        s += v; s2 += v * v;
    }
    part[b * HIDD + col] = s;
    part[200 * HIDD + b * HIDD + col] = s2;
}

__global__ void bn_final_kernel(const float* __restrict__ part,
                                const float* __restrict__ bn_w,
                                const float* __restrict__ bn_b,
                                float* __restrict__ scale, float* __restrict__ beta) {
    int col = blockIdx.x * 256 + threadIdx.x;
    float s = 0.f, s2 = 0.f;
    for (int b = 0; b < 200; b++) {
        s += part[b * HIDD + col];
        s2 += part[200 * HIDD + b * HIDD + col];
    }
    float mu = s * (1.0f / 25600.0f);
    float var = s2 * (1.0f / 25600.0f) - mu * mu;
    float sc = bn_w[col] * rsqrtf(var + 1e-5f);
    scale[col] = sc;
    beta[col] = bn_b[col] - mu * sc;
}

// ---------------- apply BN+ReLU in place (float4, tf32-rounded) ------------
__global__ void bn_apply_kernel(float* __restrict__ h,
                                const float* __restrict__ scale,
                                const float* __restrict__ beta) {
    int i = blockIdx.x * 256 + threadIdx.x;    // float4 index
    int c = (i * 4) & (HIDD - 1);
    float4 v = ((float4*)h)[i];
    float4 sc = *(const float4*)&scale[c];
    float4 be = *(const float4*)&beta[c];
    v.x = to_tf32(fmaxf(0.f, v.x * sc.x + be.x));
    v.y = to_tf32(fmaxf(0.f, v.y * sc.y + be.y));
    v.z = to_tf32(fmaxf(0.f, v.z * sc.z + be.z));
    v.w = to_tf32(fmaxf(0.f, v.w * sc.w + be.w));
    ((float4*)h)[i] = v;
}

// ---------------- launch ----------------------------------------------------
extern "C" void kernel_launch(void* const* d_in, const int* in_sizes, int n_in,
                              void* d_out, int out_size) {
    (void)in_sizes; (void)n_in; (void)out_size;
    const float* x      = (const float*)d_in[0];
    const int*   widx   = (const int*)d_in[1];
    const float* ln1_w  = (const float*)d_in[3];
    const float* ln1_b  = (const float*)d_in[4];
    const float* w_qkv  = (const float*)d_in[5];
    const float* w_proj = (const float*)d_in[6];
    const float* b_proj = (const float*)d_in[7];
    const float* ln2_w  = (const float*)d_in[8];
    const float* ln2_b  = (const float*)d_in[9];
    const float* w1     = (const float*)d_in[10];
    const float* b1     = (const float*)d_in[11];
    const float* bn_w   = (const float*)d_in[12];
    const float* bn_b   = (const float*)d_in[13];
    const float* w2     = (const float*)d_in[14];
    const float* b2     = (const float*)d_in[15];
    float* out = (float*)d_out;

    float *xin, *qkvtok, *projbuf, *attn, *x1, *hbuf, *part, *scale, *beta, *maskf;
    float *wq, *wp, *tw1, *tw2;
    int *cnt, *inv, *wbase, *wlenm1;
    cudaGetSymbolAddress((void**)&xin,    g_xin);
    cudaGetSymbolAddress((void**)&qkvtok, g_qkvtok);
    cudaGetSymbolAddress((void**)&projbuf,g_projbuf);
    cudaGetSymbolAddress((void**)&attn,   g_attn);
    cudaGetSymbolAddress((void**)&x1,     g_x1);
    cudaGetSymbolAddress((void**)&hbuf,   g_hbuf);
    cudaGetSymbolAddress((void**)&part,   g_bnpart);
    cudaGetSymbolAddress((void**)&scale,  g_scale);
    cudaGetSymbolAddress((void**)&beta,   g_beta);
    cudaGetSymbolAddress((void**)&maskf,  g_maskf);
    cudaGetSymbolAddress((void**)&cnt,    g_cnt);
    cudaGetSymbolAddress((void**)&inv,    g_inv);
    cudaGetSymbolAddress((void**)&wbase,  g_wbase);
    cudaGetSymbolAddress((void**)&wlenm1, g_wlenm1);
    cudaGetSymbolAddress((void**)&wq,     g_wq);
    cudaGetSymbolAddress((void**)&wp,     g_wp);
    cudaGetSymbolAddress((void**)&tw1,    g_w1);
    cudaGetSymbolAddress((void**)&tw2,    g_w2);

    const int gemm_smem = NSTAGE * BUFW * (int)sizeof(float);   // 110592
    cudaFuncSetAttribute(mma_gemm<0, 768, 256>,
                         cudaFuncAttributeMaxDynamicSharedMemorySize, gemm_smem);
    cudaFuncSetAttribute(mma_gemm<1, 256, 256>,
                         cudaFuncAttributeMaxDynamicSharedMemorySize, gemm_smem);
    cudaFuncSetAttribute(mma_gemm<2, 512, 256>,
                         cudaFuncAttributeMaxDynamicSharedMemorySize, gemm_smem);
    cudaFuncSetAttribute(mma_gemm<3, 256, 512>,
                         cudaFuncAttributeMaxDynamicSharedMemorySize, gemm_smem);
    const int attn_smem = AT_SMEMW * (int)sizeof(float);   // 57344
    cudaFuncSetAttribute(attn_mma_kernel,
                         cudaFuncAttributeMaxDynamicSharedMemorySize, attn_smem);

    cudaMemsetAsync(cnt, 0, N_TOK * sizeof(int));

    cvt_all_kernel<<<2048, 256>>>(w_qkv, wq, w_proj, wp, w1, tw1, w2, tw2);
    mask_count_kernel<<<MW / 256, 256>>>(widx, maskf, cnt, inv);
    winmeta_kernel<<<1, 128>>>(widx, wbase, wlenm1);
    ln_kernel<<<N_TOK / 8, 256>>>(x, ln1_w, ln1_b, xin, N_TOK);

    // per-token QKV (deduped: windows overlap 50%, each token computed once)
    mma_gemm<0, 768, 256><<<dim3(6, 200), 256, gemm_smem>>>(
        xin, wq, nullptr, nullptr, nullptr, nullptr, qkvtok);

    // attention reads per-token qkv directly (window = contiguous range + clamp)
    attn_mma_kernel<<<100 * HEADS * 2, 256, attn_smem>>>(
        qkvtok, wbase, wlenm1, maskf, attn);

    mma_gemm<1, 256, 256><<<dim3(2, 400), 256, gemm_smem>>>(
        attn, wp, b_proj, nullptr, maskf, nullptr, projbuf);

    x1ln2_kernel<<<N_TOK / 8, 256>>>(x, projbuf, cnt, inv, ln2_w, ln2_b, x1, xin);

    mma_gemm<2, 512, 256><<<dim3(4, 200), 256, gemm_smem>>>(
        xin, tw1, b1, nullptr, nullptr, nullptr, hbuf);

    bn_part_kernel<<<200, HIDD>>>(hbuf, part);
    bn_final_kernel<<<2, 256>>>(part, bn_w, bn_b, scale, beta);
    bn_apply_kernel<<<N_TOK * HIDD / 1024, 256>>>(hbuf, scale, beta);

    mma_gemm<3, 256, 512><<<dim3(2, 200), 256, gemm_smem>>>(
        hbuf, tw2, b2, nullptr, nullptr, x1, out);
}

// round 13
// speedup vs baseline: 2.3477x; 1.1846x over previous
#include <cuda_runtime.h>
#include <cuda_bf16.h>
#include <cstdint>
#include <math.h>

#define FULLMASK 0xFFFFFFFFu

#define N_TOK 25600
#define C_DIM 256
#define WLEN  512
#define MW    51200     // 100 windows * 512
#define HEADS 8
#define DHEAD 32
#define HIDD  512
#define NWIN  100

// ---------------- scratch (static device globals; no allocations) ----------
static __device__ float g_xin[N_TOK * C_DIM];
static __device__ __nv_bfloat16 g_qkvtok[N_TOK * 768]; // per-token QKV (bf16)
static __device__ float g_projbuf[MW * C_DIM];
static __device__ float g_attn[MW * C_DIM];
static __device__ float g_x1[N_TOK * C_DIM];
static __device__ float g_hbuf[N_TOK * HIDD];
static __device__ float g_bnpart[2 * 200 * HIDD];
static __device__ float g_scale[HIDD];
static __device__ float g_beta[HIDD];
static __device__ float g_maskf[MW];
static __device__ int   g_cnt[N_TOK];
static __device__ int   g_inv[2 * N_TOK];
static __device__ int   g_wbase[NWIN];
static __device__ int   g_wlenm1[NWIN];
// tf32-rounded weight copies
static __device__ float g_wq[768 * 256];
static __device__ float g_wp[256 * 256];
static __device__ float g_w1[512 * 256];
static __device__ float g_w2[256 * 512];

// ---------------- helpers ---------------------------------------------------
__device__ __forceinline__ float to_tf32(float x) {
    unsigned r;
    asm("cvt.rna.tf32.f32 %0, %1;" : "=r"(r) : "f"(x));
    return __uint_as_float(r);
}
__device__ __forceinline__ float ex2(float x) {
    float r;
    asm("ex2.approx.f32 %0, %1;" : "=f"(r) : "f"(x));
    return r;
}
__device__ __forceinline__ uint32_t bf16x2(float lo, float hi) {
    uint32_t r;   // result = {hi, lo}
    asm("cvt.rn.bf16x2.f32 %0, %1, %2;" : "=r"(r) : "f"(hi), "f"(lo));
    return r;
}
__device__ __forceinline__ void ldsm4(uint32_t* r, uint32_t addr) {
    asm volatile("ldmatrix.sync.aligned.m8n8.x4.shared.b16 {%0,%1,%2,%3}, [%4];"
                 : "=r"(r[0]), "=r"(r[1]), "=r"(r[2]), "=r"(r[3]) : "r"(addr));
}
__device__ __forceinline__ void ldsm2(uint32_t* r, uint32_t addr) {
    asm volatile("ldmatrix.sync.aligned.m8n8.x2.shared.b16 {%0,%1}, [%2];"
                 : "=r"(r[0]), "=r"(r[1]) : "r"(addr));
}
__device__ __forceinline__ void mma_tf32(float* c, const uint32_t* a, const uint32_t* b) {
    asm volatile(
        "mma.sync.aligned.m16n8k8.row.col.f32.tf32.tf32.f32 "
        "{%0,%1,%2,%3}, {%4,%5,%6,%7}, {%8,%9}, {%0,%1,%2,%3};"
        : "+f"(c[0]), "+f"(c[1]), "+f"(c[2]), "+f"(c[3])
        : "r"(a[0]), "r"(a[1]), "r"(a[2]), "r"(a[3]), "r"(b[0]), "r"(b[1]));
}
__device__ __forceinline__ void mma_bf16(float* c, const uint32_t* a, const uint32_t* b) {
    asm volatile(
        "mma.sync.aligned.m16n8k16.row.col.f32.bf16.bf16.f32 "
        "{%0,%1,%2,%3}, {%4,%5,%6,%7}, {%8,%9}, {%0,%1,%2,%3};"
        : "+f"(c[0]), "+f"(c[1]), "+f"(c[2]), "+f"(c[3])
        : "r"(a[0]), "r"(a[1]), "r"(a[2]), "r"(a[3]), "r"(b[0]), "r"(b[1]));
}
__device__ __forceinline__ void cp16(uint32_t smem, const void* g) {
    asm volatile("cp.async.cg.shared.global [%0], [%1], 16;" :: "r"(smem), "l"(g));
}
__device__ __forceinline__ void cp16ca(uint32_t smem, const void* g) {
    asm volatile("cp.async.ca.shared.global [%0], [%1], 16;" :: "r"(smem), "l"(g));
}

// ---------------- mask + inverse index from win_idx ------------------------
__global__ void mask_count_kernel(const int* __restrict__ win_idx,
                                  float* __restrict__ maskf,
                                  int* __restrict__ cnt,
                                  int* __restrict__ inv) {
    int r = blockIdx.x * 256 + threadIdx.x;
    if (r >= MW) return;
    int w = r & (WLEN - 1);
    bool valid = (w == 0 || win_idx[r] != win_idx[r - 1]);
    maskf[r] = valid ? 1.0f : 0.0f;
    if (valid) {
        int tok = win_idx[r];
        int slot = atomicAdd(&cnt[tok], 1);
        if (slot < 2) inv[tok * 2 + slot] = r;
    }
}

// ---------------- per-window base + len-1 ----------------------------------
__global__ void winmeta_kernel(const int* __restrict__ win_idx,
                               int* __restrict__ wbase, int* __restrict__ wlenm1) {
    int m = threadIdx.x;
    if (m >= NWIN) return;
    int base = win_idx[m * WLEN];
    wbase[m] = base;
    wlenm1[m] = win_idx[m * WLEN + WLEN - 1] - base;
}

// ---------------- merged tf32 rounding of all 4 weights --------------------
__global__ void cvt_all_kernel(const float* __restrict__ s0, float* __restrict__ d0,
                               const float* __restrict__ s1, float* __restrict__ d1,
                               const float* __restrict__ s2, float* __restrict__ d2,
                               const float* __restrict__ s3, float* __restrict__ d3) {
    int i = blockIdx.x * 256 + threadIdx.x;   // 524288 total
    if (i < 196608)      d0[i] = to_tf32(s0[i]);
    else if (i < 262144) d1[i - 196608] = to_tf32(s1[i - 196608]);
    else if (i < 393216) d2[i - 262144] = to_tf32(s2[i - 262144]);
    else                 d3[i - 393216] = to_tf32(s3[i - 393216]);
}

// ---------------- LayerNorm over C=256 (tf32-rounded output) ---------------
__global__ __launch_bounds__(256) void ln_kernel(const float* __restrict__ in,
                                                 const float* __restrict__ w,
                                                 const float* __restrict__ b,
                                                 float* __restrict__ out,
                                                 int rows) {
    int warp = threadIdx.x >> 5, lane = threadIdx.x & 31;
    int row = blockIdx.x * 8 + warp;
    if (row >= rows) return;
    const float4* p = (const float4*)(in + (size_t)row * C_DIM);
    float4 v0 = p[lane * 2], v1 = p[lane * 2 + 1];
    float s = v0.x + v0.y + v0.z + v0.w + v1.x + v1.y + v1.z + v1.w;
    #pragma unroll
    for (int off = 16; off; off >>= 1) s += __shfl_xor_sync(FULLMASK, s, off);
    float mu = s * (1.0f / 256.0f);
    float d0 = v0.x - mu, d1 = v0.y - mu, d2 = v0.z - mu, d3 = v0.w - mu;
    float d4 = v1.x - mu, d5 = v1.y - mu, d6 = v1.z - mu, d7 = v1.w - mu;
    float s2 = d0*d0 + d1*d1 + d2*d2 + d3*d3 + d4*d4 + d5*d5 + d6*d6 + d7*d7;
    #pragma unroll
    for (int off = 16; off; off >>= 1) s2 += __shfl_xor_sync(FULLMASK, s2, off);
    float rs = rsqrtf(s2 * (1.0f / 256.0f) + 1e-5f);
    float4 w0 = ((const float4*)w)[lane * 2], w1 = ((const float4*)w)[lane * 2 + 1];
    float4 b0 = ((const float4*)b)[lane * 2], b1 = ((const float4*)b)[lane * 2 + 1];
    float4 o0, o1;
    o0.x = to_tf32(d0 * rs * w0.x + b0.x); o0.y = to_tf32(d1 * rs * w0.y + b0.y);
    o0.z = to_tf32(d2 * rs * w0.z + b0.z); o0.w = to_tf32(d3 * rs * w0.w + b0.w);
    o1.x = to_tf32(d4 * rs * w1.x + b1.x); o1.y = to_tf32(d5 * rs * w1.y + b1.y);
    o1.z = to_tf32(d6 * rs * w1.z + b1.z); o1.w = to_tf32(d7 * rs * w1.w + b1.w);
    float4* q = (float4*)(out + (size_t)row * C_DIM);
    q[lane * 2] = o0; q[lane * 2 + 1] = o1;
}

// ---------------- gather proj + x1 + LayerNorm2 (fused) --------------------
__global__ __launch_bounds__(256) void x1ln2_kernel(
    const float* __restrict__ x, const float* __restrict__ projbuf,
    const int* __restrict__ cnt, const int* __restrict__ inv,
    const float* __restrict__ w, const float* __restrict__ b,
    float* __restrict__ x1, float* __restrict__ out) {
    int warp = threadIdx.x >> 5, lane = threadIdx.x & 31;
    int row = blockIdx.x * 8 + warp;
    int c = cnt[row];
    const float4* xp = (const float4*)(x + (size_t)row * C_DIM);
    float4 v0 = xp[lane * 2], v1 = xp[lane * 2 + 1];
    float4 y0 = make_float4(0.f, 0.f, 0.f, 0.f), y1 = y0;
    if (c >= 1) {
        const float4* p = (const float4*)(projbuf + (size_t)inv[row * 2] * C_DIM);
        y0 = p[lane * 2]; y1 = p[lane * 2 + 1];
    }
    if (c >= 2) {
        const float4* p = (const float4*)(projbuf + (size_t)inv[row * 2 + 1] * C_DIM);
        float4 a = p[lane * 2], bq = p[lane * 2 + 1];
        y0.x += a.x; y0.y += a.y; y0.z += a.z; y0.w += a.w;
        y1.x += bq.x; y1.y += bq.y; y1.z += bq.z; y1.w += bq.w;
    }
    float ic = 1.0f / fmaxf((float)c, 1.0f);
    v0.x += y0.x * ic; v0.y += y0.y * ic; v0.z += y0.z * ic; v0.w += y0.w * ic;
    v1.x += y1.x * ic; v1.y += y1.y * ic; v1.z += y1.z * ic; v1.w += y1.w * ic;
    float4* xq = (float4*)(x1 + (size_t)row * C_DIM);
    xq[lane * 2] = v0; xq[lane * 2 + 1] = v1;
    float s = v0.x + v0.y + v0.z + v0.w + v1.x + v1.y + v1.z + v1.w;
    #pragma unroll
    for (int off = 16; off; off >>= 1) s += __shfl_xor_sync(FULLMASK, s, off);
    float mu = s * (1.0f / 256.0f);
    float d0 = v0.x - mu, d1 = v0.y - mu, d2 = v0.z - mu, d3 = v0.w - mu;
    float d4 = v1.x - mu, d5 = v1.y - mu, d6 = v1.z - mu, d7 = v1.w - mu;
    float s2 = d0*d0 + d1*d1 + d2*d2 + d3*d3 + d4*d4 + d5*d5 + d6*d6 + d7*d7;
    #pragma unroll
    for (int off = 16; off; off >>= 1) s2 += __shfl_xor_sync(FULLMASK, s2, off);
    float rs = rsqrtf(s2 * (1.0f / 256.0f) + 1e-5f);
    float4 w0 = ((const float4*)w)[lane * 2], w1 = ((const float4*)w)[lane * 2 + 1];
    float4 b0 = ((const float4*)b)[lane * 2], b1 = ((const float4*)b)[lane * 2 + 1];
    float4 o0, o1;
    o0.x = to_tf32(d0 * rs * w0.x + b0.x); o0.y = to_tf32(d1 * rs * w0.y + b0.y);
    o0.z = to_tf32(d2 * rs * w0.z + b0.z); o0.w = to_tf32(d3 * rs * w0.w + b0.w);
    o1.x = to_tf32(d4 * rs * w1.x + b1.x); o1.y = to_tf32(d5 * rs * w1.y + b1.y);
    o1.z = to_tf32(d6 * rs * w1.z + b1.z); o1.w = to_tf32(d7 * rs * w1.w + b1.w);
    float4* q = (float4*)(out + (size_t)row * C_DIM);
    q[lane * 2] = o0; q[lane * 2 + 1] = o1;
}

// ---------------- tf32 tensor-core NT GEMM (BM=128, BN=128) ----------------
// MODE 0: QKV  (no bias, bf16-packed store into qkvtok)
// MODE 1: PROJ (bias, *mask, store to projbuf)
// MODE 2: FFN1 (bias, store)
// MODE 3: FFN2 (bias + residual, store)
#define GP 36
#define BUFW 9216
#define NSTAGE 3
template <int MODE, int NC, int KD>
__global__ __launch_bounds__(256) void mma_gemm(
    const float* __restrict__ A, const float* __restrict__ Bw,
    const float* __restrict__ bias, const int* __restrict__ gidx,
    const float* __restrict__ maskf, const float* __restrict__ resid,
    float* __restrict__ Cout) {
    extern __shared__ float sm[];
    uint32_t smem_u32 = (uint32_t)__cvta_generic_to_shared(sm);
    const int tid = threadIdx.x, lane = tid & 31, warp = tid >> 5;
    const int wm = warp >> 2, wn = warp & 3;
    const int bm = blockIdx.y * 128, bn = blockIdx.x * 128;

    const int lrow = tid & 127;
    const bool isA = tid < 128;
    const float* gbase;
    if (isA) gbase = A + (size_t)(bm + lrow) * KD;
    else     gbase = Bw + (size_t)(bn + lrow) * KD;
    const uint32_t sdst = smem_u32 + (uint32_t)(((isA ? 0 : 4608) + lrow * GP) * 4);

    const int lr8 = lane & 7, sub = lane >> 3, lb = lane & 15;
    const uint32_t a_off = smem_u32 +
        (uint32_t)(((wm * 64 + (sub & 1) * 8 + lr8) * GP + (sub >> 1) * 4) * 4);
    const uint32_t b_off = smem_u32 +
        (uint32_t)((4608 + (wn * 32 + (lb & 7)) * GP + (lb >> 3) * 4) * 4);

    float acc[4][4][4];
    #pragma unroll
    for (int i = 0; i < 4; i++)
        #pragma unroll
        for (int j = 0; j < 4; j++)
            #pragma unroll
            for (int r = 0; r < 4; r++) acc[i][j][r] = 0.f;

    const int T = KD / 32;
    #pragma unroll
    for (int ps = 0; ps < NSTAGE - 1; ps++) {
        const float* g = gbase + ps * 32;
        uint32_t d = sdst + (uint32_t)(ps * BUFW * 4);
        if (isA) {
            #pragma unroll
            for (int i = 0; i < 8; i++) cp16(d + i * 16, g + i * 4);
        } else {
            #pragma unroll
            for (int i = 0; i < 8; i++) cp16ca(d + i * 16, g + i * 4);
        }
        asm volatile("cp.async.commit_group;");
    }

    int buf = 0, nbuf = NSTAGE - 1;
    for (int t = 0; t < T; t++) {
        asm volatile("cp.async.wait_group %0;" :: "n"(NSTAGE - 2));
        __syncthreads();

        const uint32_t boff = (uint32_t)(buf * BUFW * 4);
        #pragma unroll
        for (int ks = 0; ks < 4; ks++) {
            uint32_t a[4][4], b[4][2];
            #pragma unroll
            for (int i = 0; i < 4; i++)
                ldsm4(a[i], a_off + boff + i * 2304 + ks * 32);
            #pragma unroll
            for (int j = 0; j < 4; j++)
                ldsm2(b[j], b_off + boff + j * 1152 + ks * 32);
            #pragma unroll
            for (int i = 0; i < 4; i++)
                #pragma unroll
                for (int j = 0; j < 4; j++)
                    mma_tf32(acc[i][j], a[i], b[j]);
        }

        if (t + NSTAGE - 1 < T) {
            const float* g = gbase + (t + NSTAGE - 1) * 32;
            uint32_t d = sdst + (uint32_t)(nbuf * BUFW * 4);
            if (isA) {
                #pragma unroll
                for (int i = 0; i < 8; i++) cp16(d + i * 16, g + i * 4);
            } else {
                #pragma unroll
                for (int i = 0; i < 8; i++) cp16ca(d + i * 16, g + i * 4);
            }
        }
        asm volatile("cp.async.commit_group;");
        buf = (buf + 1) % NSTAGE;
        nbuf = (nbuf + 1) % NSTAGE;
    }

    const int er = bm + wm * 64 + (lane >> 2);
    const int ec = bn + wn * 32 + (lane & 3) * 2;
    #pragma unroll
    for (int i = 0; i < 4; i++) {
        const int r0 = er + i * 16, r1 = r0 + 8;
        float mk0 = 0.f, mk1 = 0.f;
        if (MODE == 1) { mk0 = maskf[r0]; mk1 = maskf[r1]; }
        #pragma unroll
        for (int j = 0; j < 4; j++) {
            const int c = ec + j * 8;
            float v0 = acc[i][j][0], v1 = acc[i][j][1];
            float v2 = acc[i][j][2], v3 = acc[i][j][3];
            if (MODE == 0) {
                __nv_bfloat16* bco = (__nv_bfloat16*)Cout;
                *(uint32_t*)&bco[(size_t)r0 * NC + c] = bf16x2(v0, v1);
                *(uint32_t*)&bco[(size_t)r1 * NC + c] = bf16x2(v2, v3);
            } else if (MODE == 1) {
                float b0 = bias[c], b1 = bias[c + 1];
                *(float2*)&Cout[(size_t)r0 * NC + c] =
                    make_float2((v0 + b0) * mk0, (v1 + b1) * mk0);
                *(float2*)&Cout[(size_t)r1 * NC + c] =
                    make_float2((v2 + b0) * mk1, (v3 + b1) * mk1);
            } else if (MODE == 2) {
                float b0 = bias[c], b1 = bias[c + 1];
                *(float2*)&Cout[(size_t)r0 * NC + c] = make_float2(v0 + b0, v1 + b1);
                *(float2*)&Cout[(size_t)r1 * NC + c] = make_float2(v2 + b0, v3 + b1);
            } else {
                float b0 = bias[c], b1 = bias[c + 1];
                float2 x0 = *(const float2*)&resid[(size_t)r0 * 256 + c];
                float2 x1v = *(const float2*)&resid[(size_t)r1 * 256 + c];
                *(float2*)&Cout[(size_t)r0 * NC + c] =
                    make_float2(v0 + b0 + x0.x, v1 + b1 + x0.y);
                *(float2*)&Cout[(size_t)r1 * NC + c] =
                    make_float2(v2 + b0 + x1v.x, v3 + b1 + x1v.y);
            }
        }
    }
}

// ---------------- bf16 tensor-core flash attention (no-max softmax) --------
// Split-q CTA per (m, h, q-half); 8 warps x 32 q-rows; m16n8k16 bf16 MMA.
// qkvtok is bf16; window rows = contiguous token range + tail clamp.
// smem (bytes): maskA[2048] | per-warp Q/P 8x2560 | K double 2x2560 | Vt 2x2560
#define ATPH 40                       // bf16 pitch (80B rows; ldsm conflict-free)
#define AT_QW_B 2048
#define AT_K_B  (2048 + 8 * 2560)     // 22528
#define AT_V_B  (AT_K_B + 2 * 2560)   // 27648
#define AT_SMEM_B (AT_V_B + 2 * 2560) // 32768
__global__ __launch_bounds__(256, 2) void attn_mma_kernel(
    const __nv_bfloat16* __restrict__ qkvtok,
    const int* __restrict__ wbase, const int* __restrict__ wlenm1,
    const float* __restrict__ maskf, float* __restrict__ attn) {
    extern __shared__ char smc[];
    const uint32_t smb = (uint32_t)__cvta_generic_to_shared(smc);
    const int m = blockIdx.x >> 4;
    const int h = (blockIdx.x >> 1) & 7;
    const int qh = blockIdx.x & 1;
    const int tid = threadIdx.x, lane = tid & 31, wp = tid >> 5;

    const int base = __ldg(&wbase[m]);
    const int lenm1 = __ldg(&wlenm1[m]);

    float* maskA = (float*)smc;
    char* Qw = smc + AT_QW_B + wp * 2560;

    const __nv_bfloat16* qk = qkvtok + h * 32;  // +256 K, +512 V (halves)
    const int qrow0 = qh * 256 + wp * 32;

    for (int w = tid; w < 512; w += 256)
        maskA[w] = (maskf[m * 512 + w] != 0.f) ? 0.f : -1e30f;

    // stage warp's 32 Q rows (bf16, 4 x 16B segs per row)
    for (int i = lane; i < 128; i += 32) {
        int row = i >> 2, seg = i & 3;
        int tok = base + min(qrow0 + row, lenm1);
        uint4 v = *(const uint4*)(qk + (size_t)tok * 768 + seg * 8);
        *(uint4*)(Qw + row * (ATPH * 2) + seg * 16) = v;
    }
    __syncwarp();
    uint32_t qf[2][2][4];
    {
        uint32_t qb = smb + (uint32_t)(AT_QW_B + wp * 2560) +
                      (uint32_t)((((lane & 15)) * ATPH + (lane >> 4) * 8) * 2);
        #pragma unroll
        for (int i = 0; i < 2; i++)
            #pragma unroll
            for (int ks = 0; ks < 2; ks++)
                ldsm4(qf[i][ks], qb + (uint32_t)((i * 16 * ATPH + ks * 16) * 2));
    }
    __syncwarp();

    // prologue: K(0) by threads 0-127, Vt(0) by threads 128-255
    {
        int t2 = tid & 127, row = t2 >> 2, seg = t2 & 3;
        int tok = base + min(row, lenm1);
        if (tid < 128) {
            uint4 kv = *(const uint4*)(qk + (size_t)tok * 768 + 256 + seg * 8);
            *(uint4*)(smc + AT_K_B + row * 80 + seg * 16) = kv;
        } else {
            uint4 vv = *(const uint4*)(qk + (size_t)tok * 768 + 512 + seg * 8);
            const __nv_bfloat16* vp = (const __nv_bfloat16*)&vv;
            #pragma unroll
            for (int u = 0; u < 8; u++)
                *(__nv_bfloat16*)(smc + AT_V_B + (seg * 8 + u) * 80 + row * 2) = vp[u];
        }
    }
    __syncthreads();

    float o[2][4][4];
    #pragma unroll
    for (int i = 0; i < 2; i++)
        #pragma unroll
        for (int j = 0; j < 4; j++)
            #pragma unroll
            for (int c = 0; c < 4; c++) o[i][j][c] = 0.f;
    float Ls[2][2];
    #pragma unroll
    for (int i = 0; i < 2; i++) { Ls[i][0] = 0.f; Ls[i][1] = 0.f; }
    const float SCL2 = 0.25503485900582243f;   // log2(e)/sqrt(32)
    const int ldrow = (tid & 127) >> 2, ldseg = tid & 3;

    for (int kt = 0; kt < 16; kt++) {
        const int cb = kt & 1;
        uint4 vpre;
        if (kt < 15) {
            int tok = base + min((kt + 1) * 32 + ldrow, lenm1);
            if (tid < 128) {
                cp16(smb + (uint32_t)(AT_K_B + (1 - cb) * 2560 + ldrow * 80 + ldseg * 16),
                     qk + (size_t)tok * 768 + 256 + ldseg * 8);
            } else {
                vpre = *(const uint4*)(qk + (size_t)tok * 768 + 512 + ldseg * 8);
            }
            asm volatile("cp.async.commit_group;");
        }

        // ---- S = Q . K^T (bf16 m16n8k16) ----
        float s[2][4][4];
        #pragma unroll
        for (int i = 0; i < 2; i++)
            #pragma unroll
            for (int j = 0; j < 4; j++)
                #pragma unroll
                for (int c = 0; c < 4; c++) s[i][j][c] = 0.f;
        {
            uint32_t kb = smb + (uint32_t)(AT_K_B + cb * 2560) +
                          (uint32_t)((((lane & 7)) * ATPH + ((lane >> 3) & 1) * 8) * 2);
            #pragma unroll
            for (int ks = 0; ks < 2; ks++) {
                uint32_t bf[4][2];
                #pragma unroll
                for (int j = 0; j < 4; j++)
                    ldsm2(bf[j], kb + (uint32_t)((j * 8 * ATPH + ks * 16) * 2));
                #pragma unroll
                for (int i = 0; i < 2; i++)
                    #pragma unroll
                    for (int j = 0; j < 4; j++)
                        mma_bf16(s[i][j], qf[i][ks], bf[j]);
            }
        }

        // ---- p = 2^(s*SCL2 + mask), row sums in registers ----
        float mk[4][2];
        #pragma unroll
        for (int j = 0; j < 4; j++) {
            float2 mm = *(const float2*)&maskA[kt * 32 + j * 8 + 2 * (lane & 3)];
            mk[j][0] = mm.x; mk[j][1] = mm.y;
        }
        #pragma unroll
        for (int i = 0; i < 2; i++)
            #pragma unroll
            for (int j = 0; j < 4; j++)
                #pragma unroll
                for (int c = 0; c < 4; c++) {
                    float p = ex2(s[i][j][c] * SCL2 + mk[j][c & 1]);
                    s[i][j][c] = p;
                    Ls[i][c >> 1] += p;
                }

        // ---- pack P to bf16 into warp-private buffer ----
        {
            int r = lane >> 2, q2 = 2 * (lane & 3);
            #pragma unroll
            for (int i = 0; i < 2; i++)
                #pragma unroll
                for (int j = 0; j < 4; j++) {
                    *(uint32_t*)(Qw + ((i * 16 + r) * ATPH + j * 8 + q2) * 2) =
                        bf16x2(s[i][j][0], s[i][j][1]);
                    *(uint32_t*)(Qw + ((i * 16 + r + 8) * ATPH + j * 8 + q2) * 2) =
                        bf16x2(s[i][j][2], s[i][j][3]);
                }
        }
        __syncwarp();

        // ---- O += P . V (bf16) ----
        {
            uint32_t pb = smb + (uint32_t)(AT_QW_B + wp * 2560) +
                          (uint32_t)((((lane & 15)) * ATPH + (lane >> 4) * 8) * 2);
            uint32_t vb = smb + (uint32_t)(AT_V_B + cb * 2560) +
                          (uint32_t)((((lane & 7)) * ATPH + ((lane >> 3) & 1) * 8) * 2);
            #pragma unroll
            for (int ks = 0; ks < 2; ks++) {
                uint32_t pf[2][4], vf[4][2];
                #pragma unroll
                for (int i = 0; i < 2; i++)
                    ldsm4(pf[i], pb + (uint32_t)((i * 16 * ATPH + ks * 16) * 2));
                #pragma unroll
                for (int jd = 0; jd < 4; jd++)
                    ldsm2(vf[jd], vb + (uint32_t)((jd * 8 * ATPH + ks * 16) * 2));
                #pragma unroll
                for (int i = 0; i < 2; i++)
                    #pragma unroll
                    for (int jd = 0; jd < 4; jd++)
                        mma_bf16(o[i][jd], pf[i], vf[jd]);
            }
        }
        __syncwarp();

        if (kt < 15) {
            if (tid >= 128) {
                const __nv_bfloat16* vp = (const __nv_bfloat16*)&vpre;
                char* vt = smc + AT_V_B + (1 - cb) * 2560;
                #pragma unroll
                for (int u = 0; u < 8; u++)
                    *(__nv_bfloat16*)(vt + (ldseg * 8 + u) * 80 + ldrow * 2) = vp[u];
            }
            asm volatile("cp.async.wait_group 0;");
        }
        __syncthreads();
    }

    // ---- final row-sum reduction + normalize + writeout ----
    #pragma unroll
    for (int i = 0; i < 2; i++)
        #pragma unroll
        for (int rh = 0; rh < 2; rh++) {
            float v = Ls[i][rh];
            v += __shfl_xor_sync(FULLMASK, v, 1);
            v += __shfl_xor_sync(FULLMASK, v, 2);
            Ls[i][rh] = v;
        }
    {
        int r = lane >> 2, q2 = 2 * (lane & 3);
        #pragma unroll
        for (int i = 0; i < 2; i++) {
            float inv0 = 1.f / Ls[i][0], inv1 = 1.f / Ls[i][1];
            int row0 = m * 512 + qrow0 + i * 16 + r;
            #pragma unroll
            for (int jd = 0; jd < 4; jd++) {
                int col = h * 32 + jd * 8 + q2;
                *(float2*)&attn[(size_t)row0 * 256 + col] =
                    make_float2(o[i][jd][0] * inv0, o[i][jd][1] * inv0);
                *(float2*)&attn[(size_t)(row0 + 8) * 256 + col] =
                    make_float2(o[i][jd][2] * inv1, o[i][jd][3] * inv1);
            }
        }
    }
}

// ---------------- BatchNorm stats (two-pass, deterministic) ----------------
__global__ void bn_part_kernel(const float* __restrict__ h, float* __restrict__ part) {
    int col = threadIdx.x;
    int b = blockIdx.x;
    float s = 0.f, s2 = 0.f;
    const float* p = h + (size_t)b * 128 * HIDD + col;
    #pragma unroll 4
    for (int r = 0; r < 128; r++) {
        float v = p[(size_t)r * HIDD];
        s += v; s2 += v * v;
    }
    part[b * HIDD + col] = s;
    part[200 * HIDD + b * HIDD + col] = s2;
}

__global__ void bn_final_kernel(const float* __restrict__ part,
                                const float* __restrict__ bn_w,
                                const float* __restrict__ bn_b,
                                float* __restrict__ scale, float* __restrict__ beta) {
    int col = blockIdx.x * 256 + threadIdx.x;
    float s = 0.f, s2 = 0.f;
    for (int b = 0; b < 200; b++) {
        s += part[b * HIDD + col];
        s2 += part[200 * HIDD + b * HIDD + col];
    }
    float mu = s * (1.0f / 25600.0f);
    float var = s2 * (1.0f / 25600.0f) - mu * mu;
    float sc = bn_w[col] * rsqrtf(var + 1e-5f);
    scale[col] = sc;
    beta[col] = bn_b[col] - mu * sc;
}

// ---------------- apply BN+ReLU in place (float4, tf32-rounded) ------------
__global__ void bn_apply_kernel(float* __restrict__ h,
                                const float* __restrict__ scale,
                                const float* __restrict__ beta) {
    int i = blockIdx.x * 256 + threadIdx.x;    // float4 index
    int c = (i * 4) & (HIDD - 1);
    float4 v = ((float4*)h)[i];
    float4 sc = *(const float4*)&scale[c];
    float4 be = *(const float4*)&beta[c];
    v.x = to_tf32(fmaxf(0.f, v.x * sc.x + be.x));
    v.y = to_tf32(fmaxf(0.f, v.y * sc.y + be.y));
    v.z = to_tf32(fmaxf(0.f, v.z * sc.z + be.z));
    v.w = to_tf32(fmaxf(0.f, v.w * sc.w + be.w));
    ((float4*)h)[i] = v;
}

// ---------------- launch ----------------------------------------------------
extern "C" void kernel_launch(void* const* d_in, const int* in_sizes, int n_in,
                              void* d_out, int out_size) {
    (void)in_sizes; (void)n_in; (void)out_size;
    const float* x      = (const float*)d_in[0];
    const int*   widx   = (const int*)d_in[1];
    const float* ln1_w  = (const float*)d_in[3];
    const float* ln1_b  = (const float*)d_in[4];
    const float* w_qkv  = (const float*)d_in[5];
    const float* w_proj = (const float*)d_in[6];
    const float* b_proj = (const float*)d_in[7];
    const float* ln2_w  = (const float*)d_in[8];
    const float* ln2_b  = (const float*)d_in[9];
    const float* w1     = (const float*)d_in[10];
    const float* b1     = (const float*)d_in[11];
    const float* bn_w   = (const float*)d_in[12];
    const float* bn_b   = (const float*)d_in[13];
    const float* w2     = (const float*)d_in[14];
    const float* b2     = (const float*)d_in[15];
    float* out = (float*)d_out;

    float *xin, *projbuf, *attn, *x1, *hbuf, *part, *scale, *beta, *maskf;
    float *wq, *wp, *tw1, *tw2;
    __nv_bfloat16* qkvtok;
    int *cnt, *inv, *wbase, *wlenm1;
    cudaGetSymbolAddress((void**)&xin,    g_xin);
    cudaGetSymbolAddress((void**)&qkvtok, g_qkvtok);
    cudaGetSymbolAddress((void**)&projbuf,g_projbuf);
    cudaGetSymbolAddress((void**)&attn,   g_attn);
    cudaGetSymbolAddress((void**)&x1,     g_x1);
    cudaGetSymbolAddress((void**)&hbuf,   g_hbuf);
    cudaGetSymbolAddress((void**)&part,   g_bnpart);
    cudaGetSymbolAddress((void**)&scale,  g_scale);
    cudaGetSymbolAddress((void**)&beta,   g_beta);
    cudaGetSymbolAddress((void**)&maskf,  g_maskf);
    cudaGetSymbolAddress((void**)&cnt,    g_cnt);
    cudaGetSymbolAddress((void**)&inv,    g_inv);
    cudaGetSymbolAddress((void**)&wbase,  g_wbase);
    cudaGetSymbolAddress((void**)&wlenm1, g_wlenm1);
    cudaGetSymbolAddress((void**)&wq,     g_wq);
    cudaGetSymbolAddress((void**)&wp,     g_wp);
    cudaGetSymbolAddress((void**)&tw1,    g_w1);
    cudaGetSymbolAddress((void**)&tw2,    g_w2);

    const int gemm_smem = NSTAGE * BUFW * (int)sizeof(float);   // 110592
    cudaFuncSetAttribute(mma_gemm<0, 768, 256>,
                         cudaFuncAttributeMaxDynamicSharedMemorySize, gemm_smem);
    cudaFuncSetAttribute(mma_gemm<1, 256, 256>,
                         cudaFuncAttributeMaxDynamicSharedMemorySize, gemm_smem);
    cudaFuncSetAttribute(mma_gemm<2, 512, 256>,
                         cudaFuncAttributeMaxDynamicSharedMemorySize, gemm_smem);
    cudaFuncSetAttribute(mma_gemm<3, 256, 512>,
                         cudaFuncAttributeMaxDynamicSharedMemorySize, gemm_smem);
    cudaFuncSetAttribute(attn_mma_kernel,
                         cudaFuncAttributeMaxDynamicSharedMemorySize, AT_SMEM_B);

    cudaMemsetAsync(cnt, 0, N_TOK * sizeof(int));

    cvt_all_kernel<<<2048, 256>>>(w_qkv, wq, w_proj, wp, w1, tw1, w2, tw2);
    mask_count_kernel<<<MW / 256, 256>>>(widx, maskf, cnt, inv);
    winmeta_kernel<<<1, 128>>>(widx, wbase, wlenm1);
    ln_kernel<<<N_TOK / 8, 256>>>(x, ln1_w, ln1_b, xin, N_TOK);

    // per-token QKV (deduped), bf16 output
    mma_gemm<0, 768, 256><<<dim3(6, 200), 256, gemm_smem>>>(
        xin, wq, nullptr, nullptr, nullptr, nullptr, (float*)qkvtok);

    attn_mma_kernel<<<100 * HEADS * 2, 256, AT_SMEM_B>>>(
        qkvtok, wbase, wlenm1, maskf, attn);

    mma_gemm<1, 256, 256><<<dim3(2, 400), 256, gemm_smem>>>(
        attn, wp, b_proj, nullptr, maskf, nullptr, projbuf);

    x1ln2_kernel<<<N_TOK / 8, 256>>>(x, projbuf, cnt, inv, ln2_w, ln2_b, x1, xin);

    mma_gemm<2, 512, 256><<<dim3(4, 200), 256, gemm_smem>>>(
        xin, tw1, b1, nullptr, nullptr, nullptr, hbuf);

    bn_part_kernel<<<200, HIDD>>>(hbuf, part);
    bn_final_kernel<<<2, 256>>>(part, bn_w, bn_b, scale, beta);
    bn_apply_kernel<<<N_TOK * HIDD / 1024, 256>>>(hbuf, scale, beta);

    mma_gemm<3, 256, 512><<<dim3(2, 200), 256, gemm_smem>>>(
        hbuf, tw2, b2, nullptr, nullptr, x1, out);
}

// round 14
// speedup vs baseline: 2.7833x; 1.1856x over previous
#include <cuda_runtime.h>
#include <cuda_bf16.h>
#include <cstdint>
#include <math.h>

#define FULLMASK 0xFFFFFFFFu

#define N_TOK 25600
#define C_DIM 256
#define WLEN  512
#define MW    51200     // 100 windows * 512
#define HEADS 8
#define DHEAD 32
#define HIDD  512
#define NWIN  100

// ---------------- scratch (static device globals; no allocations) ----------
static __device__ __nv_bfloat16 g_xin16[N_TOK * C_DIM];   // LN1 out (bf16)
static __device__ float g_xin[N_TOK * C_DIM];             // LN2 out (fp32)
static __device__ __nv_bfloat16 g_qkvtok[N_TOK * 768];    // per-token QKV (bf16)
static __device__ __nv_bfloat16 g_attn16[MW * C_DIM];     // attention out (bf16)
static __device__ float g_projbuf[MW * C_DIM];
static __device__ float g_x1[N_TOK * C_DIM];
static __device__ float g_hbuf[N_TOK * HIDD];
static __device__ float g_bnpart[2 * 200 * HIDD];
static __device__ float g_scale[HIDD];
static __device__ float g_beta[HIDD];
static __device__ float g_maskf[MW];
static __device__ int   g_cnt[N_TOK];
static __device__ int   g_inv[2 * N_TOK];
static __device__ int   g_wbase[NWIN];
static __device__ int   g_wlenm1[NWIN];
// converted weight copies
static __device__ __nv_bfloat16 g_wq16[768 * 256];
static __device__ __nv_bfloat16 g_wp16[256 * 256];
static __device__ float g_w1[512 * 256];
static __device__ float g_w2[256 * 512];

// ---------------- helpers ---------------------------------------------------
__device__ __forceinline__ float to_tf32(float x) {
    unsigned r;
    asm("cvt.rna.tf32.f32 %0, %1;" : "=r"(r) : "f"(x));
    return __uint_as_float(r);
}
__device__ __forceinline__ float ex2(float x) {
    float r;
    asm("ex2.approx.f32 %0, %1;" : "=f"(r) : "f"(x));
    return r;
}
__device__ __forceinline__ uint32_t bf16x2(float lo, float hi) {
    uint32_t r;   // result = {hi, lo}
    asm("cvt.rn.bf16x2.f32 %0, %1, %2;" : "=r"(r) : "f"(hi), "f"(lo));
    return r;
}
__device__ __forceinline__ void ldsm4(uint32_t* r, uint32_t addr) {
    asm volatile("ldmatrix.sync.aligned.m8n8.x4.shared.b16 {%0,%1,%2,%3}, [%4];"
                 : "=r"(r[0]), "=r"(r[1]), "=r"(r[2]), "=r"(r[3]) : "r"(addr));
}
__device__ __forceinline__ void ldsm2(uint32_t* r, uint32_t addr) {
    asm volatile("ldmatrix.sync.aligned.m8n8.x2.shared.b16 {%0,%1}, [%2];"
                 : "=r"(r[0]), "=r"(r[1]) : "r"(addr));
}
__device__ __forceinline__ void mma_tf32(float* c, const uint32_t* a, const uint32_t* b) {
    asm volatile(
        "mma.sync.aligned.m16n8k8.row.col.f32.tf32.tf32.f32 "
        "{%0,%1,%2,%3}, {%4,%5,%6,%7}, {%8,%9}, {%0,%1,%2,%3};"
        : "+f"(c[0]), "+f"(c[1]), "+f"(c[2]), "+f"(c[3])
        : "r"(a[0]), "r"(a[1]), "r"(a[2]), "r"(a[3]), "r"(b[0]), "r"(b[1]));
}
__device__ __forceinline__ void mma_bf16(float* c, const uint32_t* a, const uint32_t* b) {
    asm volatile(
        "mma.sync.aligned.m16n8k16.row.col.f32.bf16.bf16.f32 "
        "{%0,%1,%2,%3}, {%4,%5,%6,%7}, {%8,%9}, {%0,%1,%2,%3};"
        : "+f"(c[0]), "+f"(c[1]), "+f"(c[2]), "+f"(c[3])
        : "r"(a[0]), "r"(a[1]), "r"(a[2]), "r"(a[3]), "r"(b[0]), "r"(b[1]));
}
__device__ __forceinline__ void cp16(uint32_t smem, const void* g) {
    asm volatile("cp.async.cg.shared.global [%0], [%1], 16;" :: "r"(smem), "l"(g));
}
__device__ __forceinline__ void cp16ca(uint32_t smem, const void* g) {
    asm volatile("cp.async.ca.shared.global [%0], [%1], 16;" :: "r"(smem), "l"(g));
}

// ---------------- mask + inverse index from win_idx ------------------------
__global__ void mask_count_kernel(const int* __restrict__ win_idx,
                                  float* __restrict__ maskf,
                                  int* __restrict__ cnt,
                                  int* __restrict__ inv) {
    int r = blockIdx.x * 256 + threadIdx.x;
    if (r >= MW) return;
    int w = r & (WLEN - 1);
    bool valid = (w == 0 || win_idx[r] != win_idx[r - 1]);
    maskf[r] = valid ? 1.0f : 0.0f;
    if (valid) {
        int tok = win_idx[r];
        int slot = atomicAdd(&cnt[tok], 1);
        if (slot < 2) inv[tok * 2 + slot] = r;
    }
}

// ---------------- per-window base + len-1 ----------------------------------
__global__ void winmeta_kernel(const int* __restrict__ win_idx,
                               int* __restrict__ wbase, int* __restrict__ wlenm1) {
    int m = threadIdx.x;
    if (m >= NWIN) return;
    int base = win_idx[m * WLEN];
    wbase[m] = base;
    wlenm1[m] = win_idx[m * WLEN + WLEN - 1] - base;
}

// ---------------- merged weight conversion ---------------------------------
// wq, wp -> bf16 (rn); w1, w2 -> tf32 (rna)
__global__ void cvt_all_kernel(const float* __restrict__ s0, __nv_bfloat16* __restrict__ d0,
                               const float* __restrict__ s1, __nv_bfloat16* __restrict__ d1,
                               const float* __restrict__ s2, float* __restrict__ d2,
                               const float* __restrict__ s3, float* __restrict__ d3) {
    int i = blockIdx.x * 256 + threadIdx.x;   // 524288 total
    if (i < 196608)      d0[i] = __float2bfloat16_rn(s0[i]);
    else if (i < 262144) d1[i - 196608] = __float2bfloat16_rn(s1[i - 196608]);
    else if (i < 393216) d2[i - 262144] = to_tf32(s2[i - 262144]);
    else                 d3[i - 393216] = to_tf32(s3[i - 393216]);
}

// ---------------- LayerNorm over C=256 -------------------------------------
// BF=1: write bf16 (for QKV GEMM). BF=0: write tf32-rounded fp32 (for FFN1).
template <int BF>
__global__ __launch_bounds__(256) void ln_kernel(const float* __restrict__ in,
                                                 const float* __restrict__ w,
                                                 const float* __restrict__ b,
                                                 float* __restrict__ outf,
                                                 __nv_bfloat16* __restrict__ outh,
                                                 int rows) {
    int warp = threadIdx.x >> 5, lane = threadIdx.x & 31;
    int row = blockIdx.x * 8 + warp;
    if (row >= rows) return;
    const float4* p = (const float4*)(in + (size_t)row * C_DIM);
    float4 v0 = p[lane * 2], v1 = p[lane * 2 + 1];
    float s = v0.x + v0.y + v0.z + v0.w + v1.x + v1.y + v1.z + v1.w;
    #pragma unroll
    for (int off = 16; off; off >>= 1) s += __shfl_xor_sync(FULLMASK, s, off);
    float mu = s * (1.0f / 256.0f);
    float d0 = v0.x - mu, d1 = v0.y - mu, d2 = v0.z - mu, d3 = v0.w - mu;
    float d4 = v1.x - mu, d5 = v1.y - mu, d6 = v1.z - mu, d7 = v1.w - mu;
    float s2 = d0*d0 + d1*d1 + d2*d2 + d3*d3 + d4*d4 + d5*d5 + d6*d6 + d7*d7;
    #pragma unroll
    for (int off = 16; off; off >>= 1) s2 += __shfl_xor_sync(FULLMASK, s2, off);
    float rs = rsqrtf(s2 * (1.0f / 256.0f) + 1e-5f);
    float4 w0 = ((const float4*)w)[lane * 2], w1 = ((const float4*)w)[lane * 2 + 1];
    float4 b0 = ((const float4*)b)[lane * 2], b1 = ((const float4*)b)[lane * 2 + 1];
    float r0 = d0 * rs * w0.x + b0.x, r1 = d1 * rs * w0.y + b0.y;
    float r2 = d2 * rs * w0.z + b0.z, r3 = d3 * rs * w0.w + b0.w;
    float r4 = d4 * rs * w1.x + b1.x, r5 = d5 * rs * w1.y + b1.y;
    float r6 = d6 * rs * w1.z + b1.z, r7 = d7 * rs * w1.w + b1.w;
    if (BF) {
        uint4 pk;
        pk.x = bf16x2(r0, r1); pk.y = bf16x2(r2, r3);
        pk.z = bf16x2(r4, r5); pk.w = bf16x2(r6, r7);
        *(uint4*)&outh[(size_t)row * C_DIM + lane * 8] = pk;
    } else {
        float4 o0 = make_float4(to_tf32(r0), to_tf32(r1), to_tf32(r2), to_tf32(r3));
        float4 o1 = make_float4(to_tf32(r4), to_tf32(r5), to_tf32(r6), to_tf32(r7));
        float4* q = (float4*)(outf + (size_t)row * C_DIM);
        q[lane * 2] = o0; q[lane * 2 + 1] = o1;
    }
}

// ---------------- gather proj + x1 + LayerNorm2 (fused) --------------------
__global__ __launch_bounds__(256) void x1ln2_kernel(
    const float* __restrict__ x, const float* __restrict__ projbuf,
    const int* __restrict__ cnt, const int* __restrict__ inv,
    const float* __restrict__ w, const float* __restrict__ b,
    float* __restrict__ x1, float* __restrict__ out) {
    int warp = threadIdx.x >> 5, lane = threadIdx.x & 31;
    int row = blockIdx.x * 8 + warp;
    int c = cnt[row];
    const float4* xp = (const float4*)(x + (size_t)row * C_DIM);
    float4 v0 = xp[lane * 2], v1 = xp[lane * 2 + 1];
    float4 y0 = make_float4(0.f, 0.f, 0.f, 0.f), y1 = y0;
    if (c >= 1) {
        const float4* p = (const float4*)(projbuf + (size_t)inv[row * 2] * C_DIM);
        y0 = p[lane * 2]; y1 = p[lane * 2 + 1];
    }
    if (c >= 2) {
        const float4* p = (const float4*)(projbuf + (size_t)inv[row * 2 + 1] * C_DIM);
        float4 a = p[lane * 2], bq = p[lane * 2 + 1];
        y0.x += a.x; y0.y += a.y; y0.z += a.z; y0.w += a.w;
        y1.x += bq.x; y1.y += bq.y; y1.z += bq.z; y1.w += bq.w;
    }
    float ic = 1.0f / fmaxf((float)c, 1.0f);
    v0.x += y0.x * ic; v0.y += y0.y * ic; v0.z += y0.z * ic; v0.w += y0.w * ic;
    v1.x += y1.x * ic; v1.y += y1.y * ic; v1.z += y1.z * ic; v1.w += y1.w * ic;
    float4* xq = (float4*)(x1 + (size_t)row * C_DIM);
    xq[lane * 2] = v0; xq[lane * 2 + 1] = v1;
    float s = v0.x + v0.y + v0.z + v0.w + v1.x + v1.y + v1.z + v1.w;
    #pragma unroll
    for (int off = 16; off; off >>= 1) s += __shfl_xor_sync(FULLMASK, s, off);
    float mu = s * (1.0f / 256.0f);
    float d0 = v0.x - mu, d1 = v0.y - mu, d2 = v0.z - mu, d3 = v0.w - mu;
    float d4 = v1.x - mu, d5 = v1.y - mu, d6 = v1.z - mu, d7 = v1.w - mu;
    float s2 = d0*d0 + d1*d1 + d2*d2 + d3*d3 + d4*d4 + d5*d5 + d6*d6 + d7*d7;
    #pragma unroll
    for (int off = 16; off; off >>= 1) s2 += __shfl_xor_sync(FULLMASK, s2, off);
    float rs = rsqrtf(s2 * (1.0f / 256.0f) + 1e-5f);
    float4 w0 = ((const float4*)w)[lane * 2], w1 = ((const float4*)w)[lane * 2 + 1];
    float4 b0 = ((const float4*)b)[lane * 2], b1 = ((const float4*)b)[lane * 2 + 1];
    float4 o0, o1;
    o0.x = to_tf32(d0 * rs * w0.x + b0.x); o0.y = to_tf32(d1 * rs * w0.y + b0.y);
    o0.z = to_tf32(d2 * rs * w0.z + b0.z); o0.w = to_tf32(d3 * rs * w0.w + b0.w);
    o1.x = to_tf32(d4 * rs * w1.x + b1.x); o1.y = to_tf32(d5 * rs * w1.y + b1.y);
    o1.z = to_tf32(d6 * rs * w1.z + b1.z); o1.w = to_tf32(d7 * rs * w1.w + b1.w);
    float4* q = (float4*)(out + (size_t)row * C_DIM);
    q[lane * 2] = o0; q[lane * 2 + 1] = o1;
}

// ---------------- tf32 tensor-core NT GEMM (BM=128, BN=128) ----------------
// MODE 2: FFN1 (bias, store)   MODE 3: FFN2 (bias + residual, store)
#define GP 36
#define BUFW 9216
#define NSTAGE 3
template <int MODE, int NC, int KD>
__global__ __launch_bounds__(256) void mma_gemm(
    const float* __restrict__ A, const float* __restrict__ Bw,
    const float* __restrict__ bias, const float* __restrict__ resid,
    float* __restrict__ Cout) {
    extern __shared__ float sm[];
    uint32_t smem_u32 = (uint32_t)__cvta_generic_to_shared(sm);
    const int tid = threadIdx.x, lane = tid & 31, warp = tid >> 5;
    const int wm = warp >> 2, wn = warp & 3;
    const int bm = blockIdx.y * 128, bn = blockIdx.x * 128;

    const int lrow = tid & 127;
    const bool isA = tid < 128;
    const float* gbase;
    if (isA) gbase = A + (size_t)(bm + lrow) * KD;
    else     gbase = Bw + (size_t)(bn + lrow) * KD;
    const uint32_t sdst = smem_u32 + (uint32_t)(((isA ? 0 : 4608) + lrow * GP) * 4);

    const int lr8 = lane & 7, sub = lane >> 3, lb = lane & 15;
    const uint32_t a_off = smem_u32 +
        (uint32_t)(((wm * 64 + (sub & 1) * 8 + lr8) * GP + (sub >> 1) * 4) * 4);
    const uint32_t b_off = smem_u32 +
        (uint32_t)((4608 + (wn * 32 + (lb & 7)) * GP + (lb >> 3) * 4) * 4);

    float acc[4][4][4];
    #pragma unroll
    for (int i = 0; i < 4; i++)
        #pragma unroll
        for (int j = 0; j < 4; j++)
            #pragma unroll
            for (int r = 0; r < 4; r++) acc[i][j][r] = 0.f;

    const int T = KD / 32;
    #pragma unroll
    for (int ps = 0; ps < NSTAGE - 1; ps++) {
        const float* g = gbase + ps * 32;
        uint32_t d = sdst + (uint32_t)(ps * BUFW * 4);
        if (isA) {
            #pragma unroll
            for (int i = 0; i < 8; i++) cp16(d + i * 16, g + i * 4);
        } else {
            #pragma unroll
            for (int i = 0; i < 8; i++) cp16ca(d + i * 16, g + i * 4);
        }
        asm volatile("cp.async.commit_group;");
    }

    int buf = 0, nbuf = NSTAGE - 1;
    for (int t = 0; t < T; t++) {
        asm volatile("cp.async.wait_group %0;" :: "n"(NSTAGE - 2));
        __syncthreads();

        const uint32_t boff = (uint32_t)(buf * BUFW * 4);
        #pragma unroll
        for (int ks = 0; ks < 4; ks++) {
            uint32_t a[4][4], b[4][2];
            #pragma unroll
            for (int i = 0; i < 4; i++)
                ldsm4(a[i], a_off + boff + i * 2304 + ks * 32);
            #pragma unroll
            for (int j = 0; j < 4; j++)
                ldsm2(b[j], b_off + boff + j * 1152 + ks * 32);
            #pragma unroll
            for (int i = 0; i < 4; i++)
                #pragma unroll
                for (int j = 0; j < 4; j++)
                    mma_tf32(acc[i][j], a[i], b[j]);
        }

        if (t + NSTAGE - 1 < T) {
            const float* g = gbase + (t + NSTAGE - 1) * 32;
            uint32_t d = sdst + (uint32_t)(nbuf * BUFW * 4);
            if (isA) {
                #pragma unroll
                for (int i = 0; i < 8; i++) cp16(d + i * 16, g + i * 4);
            } else {
                #pragma unroll
                for (int i = 0; i < 8; i++) cp16ca(d + i * 16, g + i * 4);
            }
        }
        asm volatile("cp.async.commit_group;");
        buf = (buf + 1) % NSTAGE;
        nbuf = (nbuf + 1) % NSTAGE;
    }

    const int er = bm + wm * 64 + (lane >> 2);
    const int ec = bn + wn * 32 + (lane & 3) * 2;
    #pragma unroll
    for (int i = 0; i < 4; i++) {
        const int r0 = er + i * 16, r1 = r0 + 8;
        #pragma unroll
        for (int j = 0; j < 4; j++) {
            const int c = ec + j * 8;
            float v0 = acc[i][j][0], v1 = acc[i][j][1];
            float v2 = acc[i][j][2], v3 = acc[i][j][3];
            float b0 = bias[c], b1 = bias[c + 1];
            if (MODE == 2) {
                *(float2*)&Cout[(size_t)r0 * NC + c] = make_float2(v0 + b0, v1 + b1);
                *(float2*)&Cout[(size_t)r1 * NC + c] = make_float2(v2 + b0, v3 + b1);
            } else {
                float2 x0 = *(const float2*)&resid[(size_t)r0 * 256 + c];
                float2 x1v = *(const float2*)&resid[(size_t)r1 * 256 + c];
                *(float2*)&Cout[(size_t)r0 * NC + c] =
                    make_float2(v0 + b0 + x0.x, v1 + b1 + x0.y);
                *(float2*)&Cout[(size_t)r1 * NC + c] =
                    make_float2(v2 + b0 + x1v.x, v3 + b1 + x1v.y);
            }
        }
    }
}

// ---------------- bf16 tensor-core NT GEMM (BM=128, BN=128, BK=32) ---------
// Pitch-40 bf16 rows (proven layout from attention). m16n8k16.
// MODE 0: QKV  (no bias, bf16 store)   MODE 1: PROJ (bias, *mask, fp32 store)
#define HP 40                        // bf16 elements per smem row (80 B)
#define BUFB 20480                   // bytes per stage: 256 rows * 80
template <int MODE, int NC, int KD>
__global__ __launch_bounds__(256) void mma_gemm16(
    const __nv_bfloat16* __restrict__ A, const __nv_bfloat16* __restrict__ Bw,
    const float* __restrict__ bias, const float* __restrict__ maskf,
    float* __restrict__ Cf, __nv_bfloat16* __restrict__ Cb) {
    extern __shared__ char smc[];
    uint32_t smb = (uint32_t)__cvta_generic_to_shared(smc);
    const int tid = threadIdx.x, lane = tid & 31, warp = tid >> 5;
    const int wm = warp >> 2, wn = warp & 3;
    const int bm = blockIdx.y * 128, bn = blockIdx.x * 128;

    const int lrow = tid & 127;
    const bool isA = tid < 128;
    const __nv_bfloat16* gbase;
    if (isA) gbase = A + (size_t)(bm + lrow) * KD;
    else     gbase = Bw + (size_t)(bn + lrow) * KD;
    const uint32_t sdst = smb + (uint32_t)((isA ? 0 : 128 * 80) + lrow * 80);

    const uint32_t a_off = smb +
        (uint32_t)(((wm * 64 + (lane & 15)) * HP + (lane >> 4) * 8) * 2);
    const uint32_t b_off = smb + (uint32_t)(128 * 80) +
        (uint32_t)(((wn * 32 + (lane & 7)) * HP + ((lane >> 3) & 1) * 8) * 2);

    float acc[4][4][4];
    #pragma unroll
    for (int i = 0; i < 4; i++)
        #pragma unroll
        for (int j = 0; j < 4; j++)
            #pragma unroll
            for (int r = 0; r < 4; r++) acc[i][j][r] = 0.f;

    const int T = KD / 32;
    #pragma unroll
    for (int ps = 0; ps < NSTAGE - 1; ps++) {
        const __nv_bfloat16* g = gbase + ps * 32;
        uint32_t d = sdst + (uint32_t)(ps * BUFB);
        if (isA) {
            #pragma unroll
            for (int i = 0; i < 4; i++) cp16(d + i * 16, g + i * 8);
        } else {
            #pragma unroll
            for (int i = 0; i < 4; i++) cp16ca(d + i * 16, g + i * 8);
        }
        asm volatile("cp.async.commit_group;");
    }

    int buf = 0, nbuf = NSTAGE - 1;
    for (int t = 0; t < T; t++) {
        asm volatile("cp.async.wait_group %0;" :: "n"(NSTAGE - 2));
        __syncthreads();

        const uint32_t boff = (uint32_t)(buf * BUFB);
        #pragma unroll
        for (int ks = 0; ks < 2; ks++) {
            uint32_t a[4][4], b[4][2];
            #pragma unroll
            for (int i = 0; i < 4; i++)
                ldsm4(a[i], a_off + boff + (uint32_t)((i * 16 * HP + ks * 16) * 2));
            #pragma unroll
            for (int j = 0; j < 4; j++)
                ldsm2(b[j], b_off + boff + (uint32_t)((j * 8 * HP + ks * 16) * 2));
            #pragma unroll
            for (int i = 0; i < 4; i++)
                #pragma unroll
                for (int j = 0; j < 4; j++)
                    mma_bf16(acc[i][j], a[i], b[j]);
        }

        if (t + NSTAGE - 1 < T) {
            const __nv_bfloat16* g = gbase + (t + NSTAGE - 1) * 32;
            uint32_t d = sdst + (uint32_t)(nbuf * BUFB);
            if (isA) {
                #pragma unroll
                for (int i = 0; i < 4; i++) cp16(d + i * 16, g + i * 8);
            } else {
                #pragma unroll
                for (int i = 0; i < 4; i++) cp16ca(d + i * 16, g + i * 8);
            }
        }
        asm volatile("cp.async.commit_group;");
        buf = (buf + 1) % NSTAGE;
        nbuf = (nbuf + 1) % NSTAGE;
    }

    const int er = bm + wm * 64 + (lane >> 2);
    const int ec = bn + wn * 32 + (lane & 3) * 2;
    #pragma unroll
    for (int i = 0; i < 4; i++) {
        const int r0 = er + i * 16, r1 = r0 + 8;
        float mk0 = 0.f, mk1 = 0.f;
        if (MODE == 1) { mk0 = maskf[r0]; mk1 = maskf[r1]; }
        #pragma unroll
        for (int j = 0; j < 4; j++) {
            const int c = ec + j * 8;
            float v0 = acc[i][j][0], v1 = acc[i][j][1];
            float v2 = acc[i][j][2], v3 = acc[i][j][3];
            if (MODE == 0) {
                *(uint32_t*)&Cb[(size_t)r0 * NC + c] = bf16x2(v0, v1);
                *(uint32_t*)&Cb[(size_t)r1 * NC + c] = bf16x2(v2, v3);
            } else {
                float b0 = bias[c], b1 = bias[c + 1];
                *(float2*)&Cf[(size_t)r0 * NC + c] =
                    make_float2((v0 + b0) * mk0, (v1 + b1) * mk0);
                *(float2*)&Cf[(size_t)r1 * NC + c] =
                    make_float2((v2 + b0) * mk1, (v3 + b1) * mk1);
            }
        }
    }
}

// ---------------- bf16 tensor-core flash attention (no-max softmax) --------
#define ATPH 40
#define AT_QW_B 2048
#define AT_K_B  (2048 + 8 * 2560)     // 22528
#define AT_V_B  (AT_K_B + 2 * 2560)   // 27648
#define AT_SMEM_B (AT_V_B + 2 * 2560) // 32768
__global__ __launch_bounds__(256, 2) void attn_mma_kernel(
    const __nv_bfloat16* __restrict__ qkvtok,
    const int* __restrict__ wbase, const int* __restrict__ wlenm1,
    const float* __restrict__ maskf, __nv_bfloat16* __restrict__ attn) {
    extern __shared__ char smc[];
    const uint32_t smb = (uint32_t)__cvta_generic_to_shared(smc);
    const int m = blockIdx.x >> 4;
    const int h = (blockIdx.x >> 1) & 7;
    const int qh = blockIdx.x & 1;
    const int tid = threadIdx.x, lane = tid & 31, wp = tid >> 5;

    const int base = __ldg(&wbase[m]);
    const int lenm1 = __ldg(&wlenm1[m]);

    float* maskA = (float*)smc;
    char* Qw = smc + AT_QW_B + wp * 2560;

    const __nv_bfloat16* qk = qkvtok + h * 32;
    const int qrow0 = qh * 256 + wp * 32;

    for (int w = tid; w < 512; w += 256)
        maskA[w] = (maskf[m * 512 + w] != 0.f) ? 0.f : -1e30f;

    for (int i = lane; i < 128; i += 32) {
        int row = i >> 2, seg = i & 3;
        int tok = base + min(qrow0 + row, lenm1);
        uint4 v = *(const uint4*)(qk + (size_t)tok * 768 + seg * 8);
        *(uint4*)(Qw + row * (ATPH * 2) + seg * 16) = v;
    }
    __syncwarp();
    uint32_t qf[2][2][4];
    {
        uint32_t qb = smb + (uint32_t)(AT_QW_B + wp * 2560) +
                      (uint32_t)((((lane & 15)) * ATPH + (lane >> 4) * 8) * 2);
        #pragma unroll
        for (int i = 0; i < 2; i++)
            #pragma unroll
            for (int ks = 0; ks < 2; ks++)
                ldsm4(qf[i][ks], qb + (uint32_t)((i * 16 * ATPH + ks * 16) * 2));
    }
    __syncwarp();

    {
        int t2 = tid & 127, row = t2 >> 2, seg = t2 & 3;
        int tok = base + min(row, lenm1);
        if (tid < 128) {
            uint4 kv = *(const uint4*)(qk + (size_t)tok * 768 + 256 + seg * 8);
            *(uint4*)(smc + AT_K_B + row * 80 + seg * 16) = kv;
        } else {
            uint4 vv = *(const uint4*)(qk + (size_t)tok * 768 + 512 + seg * 8);
            const __nv_bfloat16* vp = (const __nv_bfloat16*)&vv;
            #pragma unroll
            for (int u = 0; u < 8; u++)
                *(__nv_bfloat16*)(smc + AT_V_B + (seg * 8 + u) * 80 + row * 2) = vp[u];
        }
    }
    __syncthreads();

    float o[2][4][4];
    #pragma unroll
    for (int i = 0; i < 2; i++)
        #pragma unroll
        for (int j = 0; j < 4; j++)
            #pragma unroll
            for (int c = 0; c < 4; c++) o[i][j][c] = 0.f;
    float Ls[2][2];
    #pragma unroll
    for (int i = 0; i < 2; i++) { Ls[i][0] = 0.f; Ls[i][1] = 0.f; }
    const float SCL2 = 0.25503485900582243f;
    const int ldrow = (tid & 127) >> 2, ldseg = tid & 3;

    for (int kt = 0; kt < 16; kt++) {
        const int cb = kt & 1;
        uint4 vpre;
        if (kt < 15) {
            int tok = base + min((kt + 1) * 32 + ldrow, lenm1);
            if (tid < 128) {
                cp16(smb + (uint32_t)(AT_K_B + (1 - cb) * 2560 + ldrow * 80 + ldseg * 16),
                     qk + (size_t)tok * 768 + 256 + ldseg * 8);
            } else {
                vpre = *(const uint4*)(qk + (size_t)tok * 768 + 512 + ldseg * 8);
            }
            asm volatile("cp.async.commit_group;");
        }

        float s[2][4][4];
        #pragma unroll
        for (int i = 0; i < 2; i++)
            #pragma unroll
            for (int j = 0; j < 4; j++)
                #pragma unroll
                for (int c = 0; c < 4; c++) s[i][j][c] = 0.f;
        {
            uint32_t kb = smb + (uint32_t)(AT_K_B + cb * 2560) +
                          (uint32_t)((((lane & 7)) * ATPH + ((lane >> 3) & 1) * 8) * 2);
            #pragma unroll
            for (int ks = 0; ks < 2; ks++) {
                uint32_t bf[4][2];
                #pragma unroll
                for (int j = 0; j < 4; j++)
                    ldsm2(bf[j], kb + (uint32_t)((j * 8 * ATPH + ks * 16) * 2));
                #pragma unroll
                for (int i = 0; i < 2; i++)
                    #pragma unroll
                    for (int j = 0; j < 4; j++)
                        mma_bf16(s[i][j], qf[i][ks], bf[j]);
            }
        }

        float mk[4][2];
        #pragma unroll
        for (int j = 0; j < 4; j++) {
            float2 mm = *(const float2*)&maskA[kt * 32 + j * 8 + 2 * (lane & 3)];
            mk[j][0] = mm.x; mk[j][1] = mm.y;
        }
        #pragma unroll
        for (int i = 0; i < 2; i++)
            #pragma unroll
            for (int j = 0; j < 4; j++)
                #pragma unroll
                for (int c = 0; c < 4; c++) {
                    float p = ex2(s[i][j][c] * SCL2 + mk[j][c & 1]);
                    s[i][j][c] = p;
                    Ls[i][c >> 1] += p;
                }

        {
            int r = lane >> 2, q2 = 2 * (lane & 3);
            #pragma unroll
            for (int i = 0; i < 2; i++)
                #pragma unroll
                for (int j = 0; j < 4; j++) {
                    *(uint32_t*)(Qw + ((i * 16 + r) * ATPH + j * 8 + q2) * 2) =
                        bf16x2(s[i][j][0], s[i][j][1]);
                    *(uint32_t*)(Qw + ((i * 16 + r + 8) * ATPH + j * 8 + q2) * 2) =
                        bf16x2(s[i][j][2], s[i][j][3]);
                }
        }
        __syncwarp();

        {
            uint32_t pb = smb + (uint32_t)(AT_QW_B + wp * 2560) +
                          (uint32_t)((((lane & 15)) * ATPH + (lane >> 4) * 8) * 2);
            uint32_t vb = smb + (uint32_t)(AT_V_B + cb * 2560) +
                          (uint32_t)((((lane & 7)) * ATPH + ((lane >> 3) & 1) * 8) * 2);
            #pragma unroll
            for (int ks = 0; ks < 2; ks++) {
                uint32_t pf[2][4], vf[4][2];
                #pragma unroll
                for (int i = 0; i < 2; i++)
                    ldsm4(pf[i], pb + (uint32_t)((i * 16 * ATPH + ks * 16) * 2));
                #pragma unroll
                for (int jd = 0; jd < 4; jd++)
                    ldsm2(vf[jd], vb + (uint32_t)((jd * 8 * ATPH + ks * 16) * 2));
                #pragma unroll
                for (int i = 0; i < 2; i++)
                    #pragma unroll
                    for (int jd = 0; jd < 4; jd++)
                        mma_bf16(o[i][jd], pf[i], vf[jd]);
            }
        }
        __syncwarp();

        if (kt < 15) {
            if (tid >= 128) {
                const __nv_bfloat16* vp = (const __nv_bfloat16*)&vpre;
                char* vt = smc + AT_V_B + (1 - cb) * 2560;
                #pragma unroll
                for (int u = 0; u < 8; u++)
                    *(__nv_bfloat16*)(vt + (ldseg * 8 + u) * 80 + ldrow * 2) = vp[u];
            }
            asm volatile("cp.async.wait_group 0;");
        }
        __syncthreads();
    }

    #pragma unroll
    for (int i = 0; i < 2; i++)
        #pragma unroll
        for (int rh = 0; rh < 2; rh++) {
            float v = Ls[i][rh];
            v += __shfl_xor_sync(FULLMASK, v, 1);
            v += __shfl_xor_sync(FULLMASK, v, 2);
            Ls[i][rh] = v;
        }
    {
        int r = lane >> 2, q2 = 2 * (lane & 3);
        #pragma unroll
        for (int i = 0; i < 2; i++) {
            float inv0 = 1.f / Ls[i][0], inv1 = 1.f / Ls[i][1];
            int row0 = m * 512 + qrow0 + i * 16 + r;
            #pragma unroll
            for (int jd = 0; jd < 4; jd++) {
                int col = h * 32 + jd * 8 + q2;
                *(uint32_t*)&attn[(size_t)row0 * 256 + col] =
                    bf16x2(o[i][jd][0] * inv0, o[i][jd][1] * inv0);
                *(uint32_t*)&attn[(size_t)(row0 + 8) * 256 + col] =
                    bf16x2(o[i][jd][2] * inv1, o[i][jd][3] * inv1);
            }
        }
    }
}

// ---------------- BatchNorm stats (two-pass, deterministic) ----------------
__global__ void bn_part_kernel(const float* __restrict__ h, float* __restrict__ part) {
    int col = threadIdx.x;
    int b = blockIdx.x;
    float s = 0.f, s2 = 0.f;
    const float* p = h + (size_t)b * 128 * HIDD + col;
    #pragma unroll 4
    for (int r = 0; r < 128; r++) {
        float v = p[(size_t)r * HIDD];
        s += v; s2 += v * v;
    }
    part[b * HIDD + col] = s;
    part[200 * HIDD + b * HIDD + col] = s2;
}

__global__ void bn_final_kernel(const float* __restrict__ part,
                                const float* __restrict__ bn_w,
                                const float* __restrict__ bn_b,
                                float* __restrict__ scale, float* __restrict__ beta) {
    int col = blockIdx.x * 256 + threadIdx.x;
    float s = 0.f, s2 = 0.f;
    for (int b = 0; b < 200; b++) {
        s += part[b * HIDD + col];
        s2 += part[200 * HIDD + b * HIDD + col];
    }
    float mu = s * (1.0f / 25600.0f);
    float var = s2 * (1.0f / 25600.0f) - mu * mu;
    float sc = bn_w[col] * rsqrtf(var + 1e-5f);
    scale[col] = sc;
    beta[col] = bn_b[col] - mu * sc;
}

// ---------------- apply BN+ReLU in place (float4, tf32-rounded) ------------
__global__ void bn_apply_kernel(float* __restrict__ h,
                                const float* __restrict__ scale,
                                const float* __restrict__ beta) {
    int i = blockIdx.x * 256 + threadIdx.x;
    int c = (i * 4) & (HIDD - 1);
    float4 v = ((float4*)h)[i];
    float4 sc = *(const float4*)&scale[c];
    float4 be = *(const float4*)&beta[c];
    v.x = to_tf32(fmaxf(0.f, v.x * sc.x + be.x));
    v.y = to_tf32(fmaxf(0.f, v.y * sc.y + be.y));
    v.z = to_tf32(fmaxf(0.f, v.z * sc.z + be.z));
    v.w = to_tf32(fmaxf(0.f, v.w * sc.w + be.w));
    ((float4*)h)[i] = v;
}

// ---------------- launch ----------------------------------------------------
extern "C" void kernel_launch(void* const* d_in, const int* in_sizes, int n_in,
                              void* d_out, int out_size) {
    (void)in_sizes; (void)n_in; (void)out_size;
    const float* x      = (const float*)d_in[0];
    const int*   widx   = (const int*)d_in[1];
    const float* ln1_w  = (const float*)d_in[3];
    const float* ln1_b  = (const float*)d_in[4];
    const float* w_qkv  = (const float*)d_in[5];
    const float* w_proj = (const float*)d_in[6];
    const float* b_proj = (const float*)d_in[7];
    const float* ln2_w  = (const float*)d_in[8];
    const float* ln2_b  = (const float*)d_in[9];
    const float* w1     = (const float*)d_in[10];
    const float* b1     = (const float*)d_in[11];
    const float* bn_w   = (const float*)d_in[12];
    const float* bn_b   = (const float*)d_in[13];
    const float* w2     = (const float*)d_in[14];
    const float* b2     = (const float*)d_in[15];
    float* out = (float*)d_out;

    float *xin, *projbuf, *x1, *hbuf, *part, *scale, *beta, *maskf;
    float *tw1, *tw2;
    __nv_bfloat16 *xin16, *qkvtok, *attn16, *wq16, *wp16;
    int *cnt, *inv, *wbase, *wlenm1;
    cudaGetSymbolAddress((void**)&xin16,  g_xin16);
    cudaGetSymbolAddress((void**)&xin,    g_xin);
    cudaGetSymbolAddress((void**)&qkvtok, g_qkvtok);
    cudaGetSymbolAddress((void**)&attn16, g_attn16);
    cudaGetSymbolAddress((void**)&projbuf,g_projbuf);
    cudaGetSymbolAddress((void**)&x1,     g_x1);
    cudaGetSymbolAddress((void**)&hbuf,   g_hbuf);
    cudaGetSymbolAddress((void**)&part,   g_bnpart);
    cudaGetSymbolAddress((void**)&scale,  g_scale);
    cudaGetSymbolAddress((void**)&beta,   g_beta);
    cudaGetSymbolAddress((void**)&maskf,  g_maskf);
    cudaGetSymbolAddress((void**)&cnt,    g_cnt);
    cudaGetSymbolAddress((void**)&inv,    g_inv);
    cudaGetSymbolAddress((void**)&wbase,  g_wbase);
    cudaGetSymbolAddress((void**)&wlenm1, g_wlenm1);
    cudaGetSymbolAddress((void**)&wq16,   g_wq16);
    cudaGetSymbolAddress((void**)&wp16,   g_wp16);
    cudaGetSymbolAddress((void**)&tw1,    g_w1);
    cudaGetSymbolAddress((void**)&tw2,    g_w2);

    const int gemm_smem = NSTAGE * BUFW * (int)sizeof(float);   // 110592
    cudaFuncSetAttribute(mma_gemm<2, 512, 256>,
                         cudaFuncAttributeMaxDynamicSharedMemorySize, gemm_smem);
    cudaFuncSetAttribute(mma_gemm<3, 256, 512>,
                         cudaFuncAttributeMaxDynamicSharedMemorySize, gemm_smem);
    const int gemm16_smem = NSTAGE * BUFB;   // 61440
    cudaFuncSetAttribute(mma_gemm16<0, 768, 256>,
                         cudaFuncAttributeMaxDynamicSharedMemorySize, gemm16_smem);
    cudaFuncSetAttribute(mma_gemm16<1, 256, 256>,
                         cudaFuncAttributeMaxDynamicSharedMemorySize, gemm16_smem);
    cudaFuncSetAttribute(attn_mma_kernel,
                         cudaFuncAttributeMaxDynamicSharedMemorySize, AT_SMEM_B);

    cudaMemsetAsync(cnt, 0, N_TOK * sizeof(int));

    cvt_all_kernel<<<2048, 256>>>(w_qkv, wq16, w_proj, wp16, w1, tw1, w2, tw2);
    mask_count_kernel<<<MW / 256, 256>>>(widx, maskf, cnt, inv);
    winmeta_kernel<<<1, 128>>>(widx, wbase, wlenm1);
    ln_kernel<1><<<N_TOK / 8, 256>>>(x, ln1_w, ln1_b, nullptr, xin16, N_TOK);

    // per-token QKV (deduped), bf16 in/out
    mma_gemm16<0, 768, 256><<<dim3(6, 200), 256, gemm16_smem>>>(
        xin16, wq16, nullptr, nullptr, nullptr, qkvtok);

    attn_mma_kernel<<<100 * HEADS * 2, 256, AT_SMEM_B>>>(
        qkvtok, wbase, wlenm1, maskf, attn16);

    mma_gemm16<1, 256, 256><<<dim3(2, 400), 256, gemm16_smem>>>(
        attn16, wp16, b_proj, maskf, projbuf, nullptr);

    x1ln2_kernel<<<N_TOK / 8, 256>>>(x, projbuf, cnt, inv, ln2_w, ln2_b, x1, xin);

    mma_gemm<2, 512, 256><<<dim3(4, 200), 256, gemm_smem>>>(
        xin, tw1, b1, nullptr, hbuf);

    bn_part_kernel<<<200, HIDD>>>(hbuf, part);
    bn_final_kernel<<<2, 256>>>(part, bn_w, bn_b, scale, beta);
    bn_apply_kernel<<<N_TOK * HIDD / 1024, 256>>>(hbuf, scale, beta);

    mma_gemm<3, 256, 512><<<dim3(2, 200), 256, gemm_smem>>>(
        hbuf, tw2, b2, x1, out);
}

// round 15
// speedup vs baseline: 2.8394x; 1.0201x over previous
#include <cuda_runtime.h>
#include <cuda_bf16.h>
#include <cstdint>
#include <math.h>

#define FULLMASK 0xFFFFFFFFu

#define N_TOK 25600
#define C_DIM 256
#define WLEN  512
#define MW    51200     // 100 windows * 512
#define HEADS 8
#define DHEAD 32
#define HIDD  512
#define NWIN  100

// ---------------- scratch (static device globals; no allocations) ----------
static __device__ __nv_bfloat16 g_xin16[N_TOK * C_DIM];   // LN1 out (bf16)
static __device__ float g_xin[N_TOK * C_DIM];             // LN2 out (fp32)
static __device__ __nv_bfloat16 g_qkvtok[N_TOK * 768];    // per-token QKV (bf16)
static __device__ __nv_bfloat16 g_attn16[MW * C_DIM];     // attention out (bf16)
static __device__ float g_projbuf[MW * C_DIM];
static __device__ float g_x1[N_TOK * C_DIM];
static __device__ float g_hbuf[N_TOK * HIDD];
static __device__ float g_bnpart[2 * 200 * HIDD];
static __device__ float g_scale[HIDD];
static __device__ float g_beta[HIDD];
static __device__ float g_maskf[MW];
static __device__ int   g_cnt[N_TOK];
static __device__ int   g_inv[2 * N_TOK];
static __device__ int   g_wbase[NWIN];
static __device__ int   g_wlenm1[NWIN];
// converted weight copies
static __device__ __nv_bfloat16 g_wq16[768 * 256];
static __device__ __nv_bfloat16 g_wp16[256 * 256];
static __device__ float g_w1[512 * 256];
static __device__ float g_w2[256 * 512];

// ---------------- helpers ---------------------------------------------------
__device__ __forceinline__ float to_tf32(float x) {
    unsigned r;
    asm("cvt.rna.tf32.f32 %0, %1;" : "=r"(r) : "f"(x));
    return __uint_as_float(r);
}
__device__ __forceinline__ float ex2(float x) {
    float r;
    asm("ex2.approx.f32 %0, %1;" : "=f"(r) : "f"(x));
    return r;
}
__device__ __forceinline__ uint32_t bf16x2(float lo, float hi) {
    uint32_t r;   // result = {hi, lo}
    asm("cvt.rn.bf16x2.f32 %0, %1, %2;" : "=r"(r) : "f"(hi), "f"(lo));
    return r;
}
__device__ __forceinline__ void ldsm4(uint32_t* r, uint32_t addr) {
    asm volatile("ldmatrix.sync.aligned.m8n8.x4.shared.b16 {%0,%1,%2,%3}, [%4];"
                 : "=r"(r[0]), "=r"(r[1]), "=r"(r[2]), "=r"(r[3]) : "r"(addr));
}
__device__ __forceinline__ void ldsm2(uint32_t* r, uint32_t addr) {
    asm volatile("ldmatrix.sync.aligned.m8n8.x2.shared.b16 {%0,%1}, [%2];"
                 : "=r"(r[0]), "=r"(r[1]) : "r"(addr));
}
__device__ __forceinline__ void mma_tf32(float* c, const uint32_t* a, const uint32_t* b) {
    asm volatile(
        "mma.sync.aligned.m16n8k8.row.col.f32.tf32.tf32.f32 "
        "{%0,%1,%2,%3}, {%4,%5,%6,%7}, {%8,%9}, {%0,%1,%2,%3};"
        : "+f"(c[0]), "+f"(c[1]), "+f"(c[2]), "+f"(c[3])
        : "r"(a[0]), "r"(a[1]), "r"(a[2]), "r"(a[3]), "r"(b[0]), "r"(b[1]));
}
__device__ __forceinline__ void mma_bf16(float* c, const uint32_t* a, const uint32_t* b) {
    asm volatile(
        "mma.sync.aligned.m16n8k16.row.col.f32.bf16.bf16.f32 "
        "{%0,%1,%2,%3}, {%4,%5,%6,%7}, {%8,%9}, {%0,%1,%2,%3};"
        : "+f"(c[0]), "+f"(c[1]), "+f"(c[2]), "+f"(c[3])
        : "r"(a[0]), "r"(a[1]), "r"(a[2]), "r"(a[3]), "r"(b[0]), "r"(b[1]));
}
__device__ __forceinline__ void cp16(uint32_t smem, const void* g) {
    asm volatile("cp.async.cg.shared.global [%0], [%1], 16;" :: "r"(smem), "l"(g));
}
__device__ __forceinline__ void cp16ca(uint32_t smem, const void* g) {
    asm volatile("cp.async.ca.shared.global [%0], [%1], 16;" :: "r"(smem), "l"(g));
}

// ---------------- mask + inverse index + window meta (merged) --------------
__global__ void mask_count_kernel(const int* __restrict__ win_idx,
                                  float* __restrict__ maskf,
                                  int* __restrict__ cnt,
                                  int* __restrict__ inv,
                                  int* __restrict__ wbase,
                                  int* __restrict__ wlenm1) {
    int r = blockIdx.x * 256 + threadIdx.x;
    if (r >= MW) return;
    int w = r & (WLEN - 1);
    int idx = win_idx[r];
    bool valid = (w == 0 || idx != win_idx[r - 1]);
    maskf[r] = valid ? 1.0f : 0.0f;
    if (valid) {
        int slot = atomicAdd(&cnt[idx], 1);
        if (slot < 2) inv[idx * 2 + slot] = r;
    }
    if (w == 0) {
        int m = r >> 9;
        wbase[m] = idx;
        wlenm1[m] = win_idx[r + WLEN - 1] - idx;
    }
}

// ---------------- merged weight conversion ---------------------------------
__global__ void cvt_all_kernel(const float* __restrict__ s0, __nv_bfloat16* __restrict__ d0,
                               const float* __restrict__ s1, __nv_bfloat16* __restrict__ d1,
                               const float* __restrict__ s2, float* __restrict__ d2,
                               const float* __restrict__ s3, float* __restrict__ d3) {
    int i = blockIdx.x * 256 + threadIdx.x;   // 524288 total
    if (i < 196608)      d0[i] = __float2bfloat16_rn(s0[i]);
    else if (i < 262144) d1[i - 196608] = __float2bfloat16_rn(s1[i - 196608]);
    else if (i < 393216) d2[i - 262144] = to_tf32(s2[i - 262144]);
    else                 d3[i - 393216] = to_tf32(s3[i - 393216]);
}

// ---------------- LayerNorm over C=256 -------------------------------------
template <int BF>
__global__ __launch_bounds__(256) void ln_kernel(const float* __restrict__ in,
                                                 const float* __restrict__ w,
                                                 const float* __restrict__ b,
                                                 float* __restrict__ outf,
                                                 __nv_bfloat16* __restrict__ outh,
                                                 int rows) {
    int warp = threadIdx.x >> 5, lane = threadIdx.x & 31;
    int row = blockIdx.x * 8 + warp;
    if (row >= rows) return;
    const float4* p = (const float4*)(in + (size_t)row * C_DIM);
    float4 v0 = p[lane * 2], v1 = p[lane * 2 + 1];
    float s = v0.x + v0.y + v0.z + v0.w + v1.x + v1.y + v1.z + v1.w;
    #pragma unroll
    for (int off = 16; off; off >>= 1) s += __shfl_xor_sync(FULLMASK, s, off);
    float mu = s * (1.0f / 256.0f);
    float d0 = v0.x - mu, d1 = v0.y - mu, d2 = v0.z - mu, d3 = v0.w - mu;
    float d4 = v1.x - mu, d5 = v1.y - mu, d6 = v1.z - mu, d7 = v1.w - mu;
    float s2 = d0*d0 + d1*d1 + d2*d2 + d3*d3 + d4*d4 + d5*d5 + d6*d6 + d7*d7;
    #pragma unroll
    for (int off = 16; off; off >>= 1) s2 += __shfl_xor_sync(FULLMASK, s2, off);
    float rs = rsqrtf(s2 * (1.0f / 256.0f) + 1e-5f);
    float4 w0 = ((const float4*)w)[lane * 2], w1 = ((const float4*)w)[lane * 2 + 1];
    float4 b0 = ((const float4*)b)[lane * 2], b1 = ((const float4*)b)[lane * 2 + 1];
    float r0 = d0 * rs * w0.x + b0.x, r1 = d1 * rs * w0.y + b0.y;
    float r2 = d2 * rs * w0.z + b0.z, r3 = d3 * rs * w0.w + b0.w;
    float r4 = d4 * rs * w1.x + b1.x, r5 = d5 * rs * w1.y + b1.y;
    float r6 = d6 * rs * w1.z + b1.z, r7 = d7 * rs * w1.w + b1.w;
    if (BF) {
        uint4 pk;
        pk.x = bf16x2(r0, r1); pk.y = bf16x2(r2, r3);
        pk.z = bf16x2(r4, r5); pk.w = bf16x2(r6, r7);
        *(uint4*)&outh[(size_t)row * C_DIM + lane * 8] = pk;
    } else {
        float4 o0 = make_float4(to_tf32(r0), to_tf32(r1), to_tf32(r2), to_tf32(r3));
        float4 o1 = make_float4(to_tf32(r4), to_tf32(r5), to_tf32(r6), to_tf32(r7));
        float4* q = (float4*)(outf + (size_t)row * C_DIM);
        q[lane * 2] = o0; q[lane * 2 + 1] = o1;
    }
}

// ---------------- gather proj + x1 + LayerNorm2 (fused) --------------------
__global__ __launch_bounds__(256) void x1ln2_kernel(
    const float* __restrict__ x, const float* __restrict__ projbuf,
    const int* __restrict__ cnt, const int* __restrict__ inv,
    const float* __restrict__ w, const float* __restrict__ b,
    float* __restrict__ x1, float* __restrict__ out) {
    int warp = threadIdx.x >> 5, lane = threadIdx.x & 31;
    int row = blockIdx.x * 8 + warp;
    int c = cnt[row];
    const float4* xp = (const float4*)(x + (size_t)row * C_DIM);
    float4 v0 = xp[lane * 2], v1 = xp[lane * 2 + 1];
    float4 y0 = make_float4(0.f, 0.f, 0.f, 0.f), y1 = y0;
    if (c >= 1) {
        const float4* p = (const float4*)(projbuf + (size_t)inv[row * 2] * C_DIM);
        y0 = p[lane * 2]; y1 = p[lane * 2 + 1];
    }
    if (c >= 2) {
        const float4* p = (const float4*)(projbuf + (size_t)inv[row * 2 + 1] * C_DIM);
        float4 a = p[lane * 2], bq = p[lane * 2 + 1];
        y0.x += a.x; y0.y += a.y; y0.z += a.z; y0.w += a.w;
        y1.x += bq.x; y1.y += bq.y; y1.z += bq.z; y1.w += bq.w;
    }
    float ic = 1.0f / fmaxf((float)c, 1.0f);
    v0.x += y0.x * ic; v0.y += y0.y * ic; v0.z += y0.z * ic; v0.w += y0.w * ic;
    v1.x += y1.x * ic; v1.y += y1.y * ic; v1.z += y1.z * ic; v1.w += y1.w * ic;
    float4* xq = (float4*)(x1 + (size_t)row * C_DIM);
    xq[lane * 2] = v0; xq[lane * 2 + 1] = v1;
    float s = v0.x + v0.y + v0.z + v0.w + v1.x + v1.y + v1.z + v1.w;
    #pragma unroll
    for (int off = 16; off; off >>= 1) s += __shfl_xor_sync(FULLMASK, s, off);
    float mu = s * (1.0f / 256.0f);
    float d0 = v0.x - mu, d1 = v0.y - mu, d2 = v0.z - mu, d3 = v0.w - mu;
    float d4 = v1.x - mu, d5 = v1.y - mu, d6 = v1.z - mu, d7 = v1.w - mu;
    float s2 = d0*d0 + d1*d1 + d2*d2 + d3*d3 + d4*d4 + d5*d5 + d6*d6 + d7*d7;
    #pragma unroll
    for (int off = 16; off; off >>= 1) s2 += __shfl_xor_sync(FULLMASK, s2, off);
    float rs = rsqrtf(s2 * (1.0f / 256.0f) + 1e-5f);
    float4 w0 = ((const float4*)w)[lane * 2], w1 = ((const float4*)w)[lane * 2 + 1];
    float4 b0 = ((const float4*)b)[lane * 2], b1 = ((const float4*)b)[lane * 2 + 1];
    float4 o0, o1;
    o0.x = to_tf32(d0 * rs * w0.x + b0.x); o0.y = to_tf32(d1 * rs * w0.y + b0.y);
    o0.z = to_tf32(d2 * rs * w0.z + b0.z); o0.w = to_tf32(d3 * rs * w0.w + b0.w);
    o1.x = to_tf32(d4 * rs * w1.x + b1.x); o1.y = to_tf32(d5 * rs * w1.y + b1.y);
    o1.z = to_tf32(d6 * rs * w1.z + b1.z); o1.w = to_tf32(d7 * rs * w1.w + b1.w);
    float4* q = (float4*)(out + (size_t)row * C_DIM);
    q[lane * 2] = o0; q[lane * 2 + 1] = o1;
}

// ---------------- tf32 tensor-core NT GEMM (FFN1) --------------------------
#define GP 36
#define BUFW 9216
#define NSTAGE 3
template <int NC, int KD>
__global__ __launch_bounds__(256) void mma_gemm(
    const float* __restrict__ A, const float* __restrict__ Bw,
    const float* __restrict__ bias, float* __restrict__ Cout) {
    extern __shared__ float sm[];
    uint32_t smem_u32 = (uint32_t)__cvta_generic_to_shared(sm);
    const int tid = threadIdx.x, lane = tid & 31, warp = tid >> 5;
    const int wm = warp >> 2, wn = warp & 3;
    const int bm = blockIdx.y * 128, bn = blockIdx.x * 128;

    const int lrow = tid & 127;
    const bool isA = tid < 128;
    const float* gbase;
    if (isA) gbase = A + (size_t)(bm + lrow) * KD;
    else     gbase = Bw + (size_t)(bn + lrow) * KD;
    const uint32_t sdst = smem_u32 + (uint32_t)(((isA ? 0 : 4608) + lrow * GP) * 4);

    const int lr8 = lane & 7, sub = lane >> 3, lb = lane & 15;
    const uint32_t a_off = smem_u32 +
        (uint32_t)(((wm * 64 + (sub & 1) * 8 + lr8) * GP + (sub >> 1) * 4) * 4);
    const uint32_t b_off = smem_u32 +
        (uint32_t)((4608 + (wn * 32 + (lb & 7)) * GP + (lb >> 3) * 4) * 4);

    float acc[4][4][4];
    #pragma unroll
    for (int i = 0; i < 4; i++)
        #pragma unroll
        for (int j = 0; j < 4; j++)
            #pragma unroll
            for (int r = 0; r < 4; r++) acc[i][j][r] = 0.f;

    const int T = KD / 32;
    #pragma unroll
    for (int ps = 0; ps < NSTAGE - 1; ps++) {
        const float* g = gbase + ps * 32;
        uint32_t d = sdst + (uint32_t)(ps * BUFW * 4);
        if (isA) {
            #pragma unroll
            for (int i = 0; i < 8; i++) cp16(d + i * 16, g + i * 4);
        } else {
            #pragma unroll
            for (int i = 0; i < 8; i++) cp16ca(d + i * 16, g + i * 4);
        }
        asm volatile("cp.async.commit_group;");
    }

    int buf = 0, nbuf = NSTAGE - 1;
    for (int t = 0; t < T; t++) {
        asm volatile("cp.async.wait_group %0;" :: "n"(NSTAGE - 2));
        __syncthreads();

        const uint32_t boff = (uint32_t)(buf * BUFW * 4);
        #pragma unroll
        for (int ks = 0; ks < 4; ks++) {
            uint32_t a[4][4], b[4][2];
            #pragma unroll
            for (int i = 0; i < 4; i++)
                ldsm4(a[i], a_off + boff + i * 2304 + ks * 32);
            #pragma unroll
            for (int j = 0; j < 4; j++)
                ldsm2(b[j], b_off + boff + j * 1152 + ks * 32);
            #pragma unroll
            for (int i = 0; i < 4; i++)
                #pragma unroll
                for (int j = 0; j < 4; j++)
                    mma_tf32(acc[i][j], a[i], b[j]);
        }

        if (t + NSTAGE - 1 < T) {
            const float* g = gbase + (t + NSTAGE - 1) * 32;
            uint32_t d = sdst + (uint32_t)(nbuf * BUFW * 4);
            if (isA) {
                #pragma unroll
                for (int i = 0; i < 8; i++) cp16(d + i * 16, g + i * 4);
            } else {
                #pragma unroll
                for (int i = 0; i < 8; i++) cp16ca(d + i * 16, g + i * 4);
            }
        }
        asm volatile("cp.async.commit_group;");
        buf = (buf + 1) % NSTAGE;
        nbuf = (nbuf + 1) % NSTAGE;
    }

    const int er = bm + wm * 64 + (lane >> 2);
    const int ec = bn + wn * 32 + (lane & 3) * 2;
    #pragma unroll
    for (int i = 0; i < 4; i++) {
        const int r0 = er + i * 16, r1 = r0 + 8;
        #pragma unroll
        for (int j = 0; j < 4; j++) {
            const int c = ec + j * 8;
            float b0 = bias[c], b1 = bias[c + 1];
            *(float2*)&Cout[(size_t)r0 * NC + c] =
                make_float2(acc[i][j][0] + b0, acc[i][j][1] + b1);
            *(float2*)&Cout[(size_t)r1 * NC + c] =
                make_float2(acc[i][j][2] + b0, acc[i][j][3] + b1);
        }
    }
}

// ---------------- FFN2: tf32 GEMM with fused BN+ReLU on A ------------------
// A = raw hbuf; transform to_tf32(relu(v*scale+beta)) applied in registers
// during distance-1 prefetch (all 256 threads stage A: 4 float4 each).
// B via 3-stage cp.async (threads 128-255). Epilogue: bias + residual.
__global__ __launch_bounds__(256, 2) void mma_ffn2(
    const float* __restrict__ A, const float* __restrict__ Bw,
    const float* __restrict__ bias, const float* __restrict__ resid,
    const float* __restrict__ scale, const float* __restrict__ beta,
    float* __restrict__ Cout) {
    const int KD = 512, NC = 256;
    extern __shared__ float sm[];
    uint32_t smem_u32 = (uint32_t)__cvta_generic_to_shared(sm);
    const int tid = threadIdx.x, lane = tid & 31, warp = tid >> 5;
    const int wm = warp >> 2, wn = warp & 3;
    const int bm = blockIdx.y * 128, bn = blockIdx.x * 128;

    // A staging: thread handles segs g = i*256 + tid (i<4); row=g>>3, seg=g&7
    const int ar0 = tid >> 3, as0 = tid & 7;   // i=0 row/seg; i adds 32 rows
    // B loader: threads 128-255
    const bool isB = tid >= 128;
    const int brow = tid & 127;
    const float* gB = Bw + (size_t)(bn + brow) * KD;
    const uint32_t sdstB = smem_u32 + (uint32_t)((4608 + brow * GP) * 4);

    const int lr8 = lane & 7, sub = lane >> 3, lb = lane & 15;
    const uint32_t a_off = smem_u32 +
        (uint32_t)(((wm * 64 + (sub & 1) * 8 + lr8) * GP + (sub >> 1) * 4) * 4);
    const uint32_t b_off = smem_u32 +
        (uint32_t)((4608 + (wn * 32 + (lb & 7)) * GP + (lb >> 3) * 4) * 4);

    float acc[4][4][4];
    #pragma unroll
    for (int i = 0; i < 4; i++)
        #pragma unroll
        for (int j = 0; j < 4; j++)
            #pragma unroll
            for (int r = 0; r < 4; r++) acc[i][j][r] = 0.f;

    const int T = KD / 32;   // 16
    // prologue: A(0) transform+store to stage 0
    #pragma unroll
    for (int i = 0; i < 4; i++) {
        int row = ar0 + i * 32;
        int col = as0 * 4;
        float4 v = *(const float4*)(A + (size_t)(bm + row) * KD + col);
        float4 sc = __ldg((const float4*)&scale[col]);
        float4 be = __ldg((const float4*)&beta[col]);
        v.x = to_tf32(fmaxf(0.f, v.x * sc.x + be.x));
        v.y = to_tf32(fmaxf(0.f, v.y * sc.y + be.y));
        v.z = to_tf32(fmaxf(0.f, v.z * sc.z + be.z));
        v.w = to_tf32(fmaxf(0.f, v.w * sc.w + be.w));
        *(float4*)&sm[row * GP + col] = v;
    }
    // prologue: B stages 0,1 via cp.async
    #pragma unroll
    for (int ps = 0; ps < NSTAGE - 1; ps++) {
        if (isB) {
            const float* g = gB + ps * 32;
            uint32_t d = sdstB + (uint32_t)(ps * BUFW * 4);
            #pragma unroll
            for (int i = 0; i < 8; i++) cp16ca(d + i * 16, g + i * 4);
        }
        asm volatile("cp.async.commit_group;");
    }

    int buf = 0, nbuf = NSTAGE - 1;
    for (int t = 0; t < T; t++) {
        asm volatile("cp.async.wait_group %0;" :: "n"(NSTAGE - 2));
        __syncthreads();

        // prefetch A(t+1) into registers (issued before MMA to hide latency)
        float4 ap[4];
        if (t + 1 < T) {
            #pragma unroll
            for (int i = 0; i < 4; i++) {
                int row = ar0 + i * 32;
                ap[i] = *(const float4*)(A + (size_t)(bm + row) * KD +
                                         (t + 1) * 32 + as0 * 4);
            }
        }

        const uint32_t boff = (uint32_t)(buf * BUFW * 4);
        #pragma unroll
        for (int ks = 0; ks < 4; ks++) {
            uint32_t a[4][4], b[4][2];
            #pragma unroll
            for (int i = 0; i < 4; i++)
                ldsm4(a[i], a_off + boff + i * 2304 + ks * 32);
            #pragma unroll
            for (int j = 0; j < 4; j++)
                ldsm2(b[j], b_off + boff + j * 1152 + ks * 32);
            #pragma unroll
            for (int i = 0; i < 4; i++)
                #pragma unroll
                for (int j = 0; j < 4; j++)
                    mma_tf32(acc[i][j], a[i], b[j]);
        }

        if (t + NSTAGE - 1 < T && isB) {
            const float* g = gB + (t + NSTAGE - 1) * 32;
            uint32_t d = sdstB + (uint32_t)(nbuf * BUFW * 4);
            #pragma unroll
            for (int i = 0; i < 8; i++) cp16ca(d + i * 16, g + i * 4);
        }
        asm volatile("cp.async.commit_group;");

        // transform + STS A(t+1) into stage (t+1)%3 (safe: last read t-2,
        // all warps passed this iter's barrier)
        if (t + 1 < T) {
            const uint32_t aoffS = (uint32_t)(((t + 1) % NSTAGE) * BUFW);
            int colb = (t + 1) * 32 + as0 * 4;
            float4 sc = __ldg((const float4*)&scale[colb]);
            float4 be = __ldg((const float4*)&beta[colb]);
            #pragma unroll
            for (int i = 0; i < 4; i++) {
                float4 v = ap[i];
                v.x = to_tf32(fmaxf(0.f, v.x * sc.x + be.x));
                v.y = to_tf32(fmaxf(0.f, v.y * sc.y + be.y));
                v.z = to_tf32(fmaxf(0.f, v.z * sc.z + be.z));
                v.w = to_tf32(fmaxf(0.f, v.w * sc.w + be.w));
                int row = ar0 + i * 32;
                *(float4*)&sm[aoffS + row * GP + as0 * 4] = v;
            }
        }
        buf = (buf + 1) % NSTAGE;
        nbuf = (nbuf + 1) % NSTAGE;
    }

    const int er = bm + wm * 64 + (lane >> 2);
    const int ec = bn + wn * 32 + (lane & 3) * 2;
    #pragma unroll
    for (int i = 0; i < 4; i++) {
        const int r0 = er + i * 16, r1 = r0 + 8;
        #pragma unroll
        for (int j = 0; j < 4; j++) {
            const int c = ec + j * 8;
            float b0 = bias[c], b1 = bias[c + 1];
            float2 x0 = *(const float2*)&resid[(size_t)r0 * 256 + c];
            float2 x1v = *(const float2*)&resid[(size_t)r1 * 256 + c];
            *(float2*)&Cout[(size_t)r0 * NC + c] =
                make_float2(acc[i][j][0] + b0 + x0.x, acc[i][j][1] + b1 + x0.y);
            *(float2*)&Cout[(size_t)r1 * NC + c] =
                make_float2(acc[i][j][2] + b0 + x1v.x, acc[i][j][3] + b1 + x1v.y);
        }
    }
}

// ---------------- bf16 tensor-core NT GEMM (BM=128, BN=128, BK=32) ---------
#define HP 40
#define BUFB 20480
template <int MODE, int NC, int KD>
__global__ __launch_bounds__(256) void mma_gemm16(
    const __nv_bfloat16* __restrict__ A, const __nv_bfloat16* __restrict__ Bw,
    const float* __restrict__ bias, const float* __restrict__ maskf,
    float* __restrict__ Cf, __nv_bfloat16* __restrict__ Cb) {
    extern __shared__ char smc[];
    uint32_t smb = (uint32_t)__cvta_generic_to_shared(smc);
    const int tid = threadIdx.x, lane = tid & 31, warp = tid >> 5;
    const int wm = warp >> 2, wn = warp & 3;
    const int bm = blockIdx.y * 128, bn = blockIdx.x * 128;

    const int lrow = tid & 127;
    const bool isA = tid < 128;
    const __nv_bfloat16* gbase;
    if (isA) gbase = A + (size_t)(bm + lrow) * KD;
    else     gbase = Bw + (size_t)(bn + lrow) * KD;
    const uint32_t sdst = smb + (uint32_t)((isA ? 0 : 128 * 80) + lrow * 80);

    const uint32_t a_off = smb +
        (uint32_t)(((wm * 64 + (lane & 15)) * HP + (lane >> 4) * 8) * 2);
    const uint32_t b_off = smb + (uint32_t)(128 * 80) +
        (uint32_t)(((wn * 32 + (lane & 7)) * HP + ((lane >> 3) & 1) * 8) * 2);

    float acc[4][4][4];
    #pragma unroll
    for (int i = 0; i < 4; i++)
        #pragma unroll
        for (int j = 0; j < 4; j++)
            #pragma unroll
            for (int r = 0; r < 4; r++) acc[i][j][r] = 0.f;

    const int T = KD / 32;
    #pragma unroll
    for (int ps = 0; ps < NSTAGE - 1; ps++) {
        const __nv_bfloat16* g = gbase + ps * 32;
        uint32_t d = sdst + (uint32_t)(ps * BUFB);
        if (isA) {
            #pragma unroll
            for (int i = 0; i < 4; i++) cp16(d + i * 16, g + i * 8);
        } else {
            #pragma unroll
            for (int i = 0; i < 4; i++) cp16ca(d + i * 16, g + i * 8);
        }
        asm volatile("cp.async.commit_group;");
    }

    int buf = 0, nbuf = NSTAGE - 1;
    for (int t = 0; t < T; t++) {
        asm volatile("cp.async.wait_group %0;" :: "n"(NSTAGE - 2));
        __syncthreads();

        const uint32_t boff = (uint32_t)(buf * BUFB);
        #pragma unroll
        for (int ks = 0; ks < 2; ks++) {
            uint32_t a[4][4], b[4][2];
            #pragma unroll
            for (int i = 0; i < 4; i++)
                ldsm4(a[i], a_off + boff + (uint32_t)((i * 16 * HP + ks * 16) * 2));
            #pragma unroll
            for (int j = 0; j < 4; j++)
                ldsm2(b[j], b_off + boff + (uint32_t)((j * 8 * HP + ks * 16) * 2));
            #pragma unroll
            for (int i = 0; i < 4; i++)
                #pragma unroll
                for (int j = 0; j < 4; j++)
                    mma_bf16(acc[i][j], a[i], b[j]);
        }

        if (t + NSTAGE - 1 < T) {
            const __nv_bfloat16* g = gbase + (t + NSTAGE - 1) * 32;
            uint32_t d = sdst + (uint32_t)(nbuf * BUFB);
            if (isA) {
                #pragma unroll
                for (int i = 0; i < 4; i++) cp16(d + i * 16, g + i * 8);
            } else {
                #pragma unroll
                for (int i = 0; i < 4; i++) cp16ca(d + i * 16, g + i * 8);
            }
        }
        asm volatile("cp.async.commit_group;");
        buf = (buf + 1) % NSTAGE;
        nbuf = (nbuf + 1) % NSTAGE;
    }

    const int er = bm + wm * 64 + (lane >> 2);
    const int ec = bn + wn * 32 + (lane & 3) * 2;
    #pragma unroll
    for (int i = 0; i < 4; i++) {
        const int r0 = er + i * 16, r1 = r0 + 8;
        float mk0 = 0.f, mk1 = 0.f;
        if (MODE == 1) { mk0 = maskf[r0]; mk1 = maskf[r1]; }
        #pragma unroll
        for (int j = 0; j < 4; j++) {
            const int c = ec + j * 8;
            float v0 = acc[i][j][0], v1 = acc[i][j][1];
            float v2 = acc[i][j][2], v3 = acc[i][j][3];
            if (MODE == 0) {
                *(uint32_t*)&Cb[(size_t)r0 * NC + c] = bf16x2(v0, v1);
                *(uint32_t*)&Cb[(size_t)r1 * NC + c] = bf16x2(v2, v3);
            } else {
                float b0 = bias[c], b1 = bias[c + 1];
                *(float2*)&Cf[(size_t)r0 * NC + c] =
                    make_float2((v0 + b0) * mk0, (v1 + b1) * mk0);
                *(float2*)&Cf[(size_t)r1 * NC + c] =
                    make_float2((v2 + b0) * mk1, (v3 + b1) * mk1);
            }
        }
    }
}

// ---------------- bf16 tensor-core flash attention (no-max softmax) --------
#define ATPH 40
#define AT_QW_B 2048
#define AT_K_B  (2048 + 8 * 2560)     // 22528
#define AT_V_B  (AT_K_B + 2 * 2560)   // 27648
#define AT_SMEM_B (AT_V_B + 2 * 2560) // 32768
__global__ __launch_bounds__(256, 2) void attn_mma_kernel(
    const __nv_bfloat16* __restrict__ qkvtok,
    const int* __restrict__ wbase, const int* __restrict__ wlenm1,
    const float* __restrict__ maskf, __nv_bfloat16* __restrict__ attn) {
    extern __shared__ char smc[];
    const uint32_t smb = (uint32_t)__cvta_generic_to_shared(smc);
    const int m = blockIdx.x >> 4;
    const int h = (blockIdx.x >> 1) & 7;
    const int qh = blockIdx.x & 1;
    const int tid = threadIdx.x, lane = tid & 31, wp = tid >> 5;

    const int base = __ldg(&wbase[m]);
    const int lenm1 = __ldg(&wlenm1[m]);

    float* maskA = (float*)smc;
    char* Qw = smc + AT_QW_B + wp * 2560;

    const __nv_bfloat16* qk = qkvtok + h * 32;
    const int qrow0 = qh * 256 + wp * 32;

    for (int w = tid; w < 512; w += 256)
        maskA[w] = (maskf[m * 512 + w] != 0.f) ? 0.f : -1e30f;

    for (int i = lane; i < 128; i += 32) {
        int row = i >> 2, seg = i & 3;
        int tok = base + min(qrow0 + row, lenm1);
        uint4 v = *(const uint4*)(qk + (size_t)tok * 768 + seg * 8);
        *(uint4*)(Qw + row * (ATPH * 2) + seg * 16) = v;
    }
    __syncwarp();
    uint32_t qf[2][2][4];
    {
        uint32_t qb = smb + (uint32_t)(AT_QW_B + wp * 2560) +
                      (uint32_t)((((lane & 15)) * ATPH + (lane >> 4) * 8) * 2);
        #pragma unroll
        for (int i = 0; i < 2; i++)
            #pragma unroll
            for (int ks = 0; ks < 2; ks++)
                ldsm4(qf[i][ks], qb + (uint32_t)((i * 16 * ATPH + ks * 16) * 2));
    }
    __syncwarp();

    {
        int t2 = tid & 127, row = t2 >> 2, seg = t2 & 3;
        int tok = base + min(row, lenm1);
        if (tid < 128) {
            uint4 kv = *(const uint4*)(qk + (size_t)tok * 768 + 256 + seg * 8);
            *(uint4*)(smc + AT_K_B + row * 80 + seg * 16) = kv;
        } else {
            uint4 vv = *(const uint4*)(qk + (size_t)tok * 768 + 512 + seg * 8);
            const __nv_bfloat16* vp = (const __nv_bfloat16*)&vv;
            #pragma unroll
            for (int u = 0; u < 8; u++)
                *(__nv_bfloat16*)(smc + AT_V_B + (seg * 8 + u) * 80 + row * 2) = vp[u];
        }
    }
    __syncthreads();

    float o[2][4][4];
    #pragma unroll
    for (int i = 0; i < 2; i++)
        #pragma unroll
        for (int j = 0; j < 4; j++)
            #pragma unroll
            for (int c = 0; c < 4; c++) o[i][j][c] = 0.f;
    float Ls[2][2];
    #pragma unroll
    for (int i = 0; i < 2; i++) { Ls[i][0] = 0.f; Ls[i][1] = 0.f; }
    const float SCL2 = 0.25503485900582243f;
    const int ldrow = (tid & 127) >> 2, ldseg = tid & 3;

    for (int kt = 0; kt < 16; kt++) {
        const int cb = kt & 1;
        uint4 vpre;
        if (kt < 15) {
            int tok = base + min((kt + 1) * 32 + ldrow, lenm1);
            if (tid < 128) {
                cp16(smb + (uint32_t)(AT_K_B + (1 - cb) * 2560 + ldrow * 80 + ldseg * 16),
                     qk + (size_t)tok * 768 + 256 + ldseg * 8);
            } else {
                vpre = *(const uint4*)(qk + (size_t)tok * 768 + 512 + ldseg * 8);
            }
            asm volatile("cp.async.commit_group;");
        }

        float s[2][4][4];
        #pragma unroll
        for (int i = 0; i < 2; i++)
            #pragma unroll
            for (int j = 0; j < 4; j++)
                #pragma unroll
                for (int c = 0; c < 4; c++) s[i][j][c] = 0.f;
        {
            uint32_t kb = smb + (uint32_t)(AT_K_B + cb * 2560) +
                          (uint32_t)((((lane & 7)) * ATPH + ((lane >> 3) & 1) * 8) * 2);
            #pragma unroll
            for (int ks = 0; ks < 2; ks++) {
                uint32_t bf[4][2];
                #pragma unroll
                for (int j = 0; j < 4; j++)
                    ldsm2(bf[j], kb + (uint32_t)((j * 8 * ATPH + ks * 16) * 2));
                #pragma unroll
                for (int i = 0; i < 2; i++)
                    #pragma unroll
                    for (int j = 0; j < 4; j++)
                        mma_bf16(s[i][j], qf[i][ks], bf[j]);
            }
        }

        float mk[4][2];
        #pragma unroll
        for (int j = 0; j < 4; j++) {
            float2 mm = *(const float2*)&maskA[kt * 32 + j * 8 + 2 * (lane & 3)];
            mk[j][0] = mm.x; mk[j][1] = mm.y;
        }
        #pragma unroll
        for (int i = 0; i < 2; i++)
            #pragma unroll
            for (int j = 0; j < 4; j++)
                #pragma unroll
                for (int c = 0; c < 4; c++) {
                    float p = ex2(s[i][j][c] * SCL2 + mk[j][c & 1]);
                    s[i][j][c] = p;
                    Ls[i][c >> 1] += p;
                }

        {
            int r = lane >> 2, q2 = 2 * (lane & 3);
            #pragma unroll
            for (int i = 0; i < 2; i++)
                #pragma unroll
                for (int j = 0; j < 4; j++) {
                    *(uint32_t*)(Qw + ((i * 16 + r) * ATPH + j * 8 + q2) * 2) =
                        bf16x2(s[i][j][0], s[i][j][1]);
                    *(uint32_t*)(Qw + ((i * 16 + r + 8) * ATPH + j * 8 + q2) * 2) =
                        bf16x2(s[i][j][2], s[i][j][3]);
                }
        }
        __syncwarp();

        {
            uint32_t pb = smb + (uint32_t)(AT_QW_B + wp * 2560) +
                          (uint32_t)((((lane & 15)) * ATPH + (lane >> 4) * 8) * 2);
            uint32_t vb = smb + (uint32_t)(AT_V_B + cb * 2560) +
                          (uint32_t)((((lane & 7)) * ATPH + ((lane >> 3) & 1) * 8) * 2);
            #pragma unroll
            for (int ks = 0; ks < 2; ks++) {
                uint32_t pf[2][4], vf[4][2];
                #pragma unroll
                for (int i = 0; i < 2; i++)
                    ldsm4(pf[i], pb + (uint32_t)((i * 16 * ATPH + ks * 16) * 2));
                #pragma unroll
                for (int jd = 0; jd < 4; jd++)
                    ldsm2(vf[jd], vb + (uint32_t)((jd * 8 * ATPH + ks * 16) * 2));
                #pragma unroll
                for (int i = 0; i < 2; i++)
                    #pragma unroll
                    for (int jd = 0; jd < 4; jd++)
                        mma_bf16(o[i][jd], pf[i], vf[jd]);
            }
        }
        __syncwarp();

        if (kt < 15) {
            if (tid >= 128) {
                const __nv_bfloat16* vp = (const __nv_bfloat16*)&vpre;
                char* vt = smc + AT_V_B + (1 - cb) * 2560;
                #pragma unroll
                for (int u = 0; u < 8; u++)
                    *(__nv_bfloat16*)(vt + (ldseg * 8 + u) * 80 + ldrow * 2) = vp[u];
            }
            asm volatile("cp.async.wait_group 0;");
        }
        __syncthreads();
    }

    #pragma unroll
    for (int i = 0; i < 2; i++)
        #pragma unroll
        for (int rh = 0; rh < 2; rh++) {
            float v = Ls[i][rh];
            v += __shfl_xor_sync(FULLMASK, v, 1);
            v += __shfl_xor_sync(FULLMASK, v, 2);
            Ls[i][rh] = v;
        }
    {
        int r = lane >> 2, q2 = 2 * (lane & 3);
        #pragma unroll
        for (int i = 0; i < 2; i++) {
            float inv0 = 1.f / Ls[i][0], inv1 = 1.f / Ls[i][1];
            int row0 = m * 512 + qrow0 + i * 16 + r;
            #pragma unroll
            for (int jd = 0; jd < 4; jd++) {
                int col = h * 32 + jd * 8 + q2;
                *(uint32_t*)&attn[(size_t)row0 * 256 + col] =
                    bf16x2(o[i][jd][0] * inv0, o[i][jd][1] * inv0);
                *(uint32_t*)&attn[(size_t)(row0 + 8) * 256 + col] =
                    bf16x2(o[i][jd][2] * inv1, o[i][jd][3] * inv1);
            }
        }
    }
}

// ---------------- BatchNorm stats (two-pass, deterministic) ----------------
__global__ void bn_part_kernel(const float* __restrict__ h, float* __restrict__ part) {
    int col = threadIdx.x;
    int b = blockIdx.x;
    float s = 0.f, s2 = 0.f;
    const float* p = h + (size_t)b * 128 * HIDD + col;
    #pragma unroll 4
    for (int r = 0; r < 128; r++) {
        float v = p[(size_t)r * HIDD];
        s += v; s2 += v * v;
    }
    part[b * HIDD + col] = s;
    part[200 * HIDD + b * HIDD + col] = s2;
}

__global__ void bn_final_kernel(const float* __restrict__ part,
                                const float* __restrict__ bn_w,
                                const float* __restrict__ bn_b,
                                float* __restrict__ scale, float* __restrict__ beta) {
    int col = blockIdx.x * 256 + threadIdx.x;
    float s = 0.f, s2 = 0.f;
    for (int b = 0; b < 200; b++) {
        s += part[b * HIDD + col];
        s2 += part[200 * HIDD + b * HIDD + col];
    }
    float mu = s * (1.0f / 25600.0f);
    float var = s2 * (1.0f / 25600.0f) - mu * mu;
    float sc = bn_w[col] * rsqrtf(var + 1e-5f);
    scale[col] = sc;
    beta[col] = bn_b[col] - mu * sc;
}

// ---------------- launch ----------------------------------------------------
extern "C" void kernel_launch(void* const* d_in, const int* in_sizes, int n_in,
                              void* d_out, int out_size) {
    (void)in_sizes; (void)n_in; (void)out_size;
    const float* x      = (const float*)d_in[0];
    const int*   widx   = (const int*)d_in[1];
    const float* ln1_w  = (const float*)d_in[3];
    const float* ln1_b  = (const float*)d_in[4];
    const float* w_qkv  = (const float*)d_in[5];
    const float* w_proj = (const float*)d_in[6];
    const float* b_proj = (const float*)d_in[7];
    const float* ln2_w  = (const float*)d_in[8];
    const float* ln2_b  = (const float*)d_in[9];
    const float* w1     = (const float*)d_in[10];
    const float* b1     = (const float*)d_in[11];
    const float* bn_w   = (const float*)d_in[12];
    const float* bn_b   = (const float*)d_in[13];
    const float* w2     = (const float*)d_in[14];
    const float* b2     = (const float*)d_in[15];
    float* out = (float*)d_out;

    float *xin, *projbuf, *x1, *hbuf, *part, *scale, *beta, *maskf;
    float *tw1, *tw2;
    __nv_bfloat16 *xin16, *qkvtok, *attn16, *wq16, *wp16;
    int *cnt, *inv, *wbase, *wlenm1;
    cudaGetSymbolAddress((void**)&xin16,  g_xin16);
    cudaGetSymbolAddress((void**)&xin,    g_xin);
    cudaGetSymbolAddress((void**)&qkvtok, g_qkvtok);
    cudaGetSymbolAddress((void**)&attn16, g_attn16);
    cudaGetSymbolAddress((void**)&projbuf,g_projbuf);
    cudaGetSymbolAddress((void**)&x1,     g_x1);
    cudaGetSymbolAddress((void**)&hbuf,   g_hbuf);
    cudaGetSymbolAddress((void**)&part,   g_bnpart);
    cudaGetSymbolAddress((void**)&scale,  g_scale);
    cudaGetSymbolAddress((void**)&beta,   g_beta);
    cudaGetSymbolAddress((void**)&maskf,  g_maskf);
    cudaGetSymbolAddress((void**)&cnt,    g_cnt);
    cudaGetSymbolAddress((void**)&inv,    g_inv);
    cudaGetSymbolAddress((void**)&wbase,  g_wbase);
    cudaGetSymbolAddress((void**)&wlenm1, g_wlenm1);
    cudaGetSymbolAddress((void**)&wq16,   g_wq16);
    cudaGetSymbolAddress((void**)&wp16,   g_wp16);
    cudaGetSymbolAddress((void**)&tw1,    g_w1);
    cudaGetSymbolAddress((void**)&tw2,    g_w2);

    const int gemm_smem = NSTAGE * BUFW * (int)sizeof(float);   // 110592
    cudaFuncSetAttribute(mma_gemm<512, 256>,
                         cudaFuncAttributeMaxDynamicSharedMemorySize, gemm_smem);
    cudaFuncSetAttribute(mma_ffn2,
                         cudaFuncAttributeMaxDynamicSharedMemorySize, gemm_smem);
    const int gemm16_smem = NSTAGE * BUFB;   // 61440
    cudaFuncSetAttribute(mma_gemm16<0, 768, 256>,
                         cudaFuncAttributeMaxDynamicSharedMemorySize, gemm16_smem);
    cudaFuncSetAttribute(mma_gemm16<1, 256, 256>,
                         cudaFuncAttributeMaxDynamicSharedMemorySize, gemm16_smem);
    cudaFuncSetAttribute(attn_mma_kernel,
                         cudaFuncAttributeMaxDynamicSharedMemorySize, AT_SMEM_B);

    cudaMemsetAsync(cnt, 0, N_TOK * sizeof(int));

    cvt_all_kernel<<<2048, 256>>>(w_qkv, wq16, w_proj, wp16, w1, tw1, w2, tw2);
    mask_count_kernel<<<MW / 256, 256>>>(widx, maskf, cnt, inv, wbase, wlenm1);
    ln_kernel<1><<<N_TOK / 8, 256>>>(x, ln1_w, ln1_b, nullptr, xin16, N_TOK);

    mma_gemm16<0, 768, 256><<<dim3(6, 200), 256, gemm16_smem>>>(
        xin16, wq16, nullptr, nullptr, nullptr, qkvtok);

    attn_mma_kernel<<<100 * HEADS * 2, 256, AT_SMEM_B>>>(
        qkvtok, wbase, wlenm1, maskf, attn16);

    mma_gemm16<1, 256, 256><<<dim3(2, 400), 256, gemm16_smem>>>(
        attn16, wp16, b_proj, maskf, projbuf, nullptr);

    x1ln2_kernel<<<N_TOK / 8, 256>>>(x, projbuf, cnt, inv, ln2_w, ln2_b, x1, xin);

    mma_gemm<512, 256><<<dim3(4, 200), 256, gemm_smem>>>(
        xin, tw1, b1, hbuf);

    bn_part_kernel<<<200, HIDD>>>(hbuf, part);
    bn_final_kernel<<<2, 256>>>(part, bn_w, bn_b, scale, beta);

    mma_ffn2<<<dim3(2, 200), 256, gemm_smem>>>(
        hbuf, tw2, b2, x1, scale, beta, out);
}

// round 17
// speedup vs baseline: 2.9508x; 1.0393x over previous
#include <cuda_runtime.h>
#include <cuda_bf16.h>
#include <cstdint>
#include <math.h>

#define FULLMASK 0xFFFFFFFFu

#define N_TOK 25600
#define C_DIM 256
#define WLEN  512
#define MW    51200     // 100 windows * 512
#define HEADS 8
#define DHEAD 32
#define HIDD  512
#define NWIN  100

// ---------------- scratch (static device globals; no allocations) ----------
static __device__ __nv_bfloat16 g_xin16[N_TOK * C_DIM];   // LN1 out (bf16)
static __device__ float g_xin[N_TOK * C_DIM];             // LN2 out (fp32)
static __device__ __nv_bfloat16 g_qkvtok[N_TOK * 768];    // per-token QKV (bf16)
static __device__ __nv_bfloat16 g_attn16[MW * C_DIM];     // attention out (bf16)
static __device__ float g_projbuf[MW * C_DIM];
static __device__ float g_x1[N_TOK * C_DIM];
static __device__ float g_hbuf[N_TOK * HIDD];
static __device__ float g_bnpart[2 * 200 * HIDD];
static __device__ float g_scale[HIDD];
static __device__ float g_beta[HIDD];
static __device__ float g_maskf[MW];
static __device__ int   g_cnt[N_TOK];
static __device__ int   g_inv[2 * N_TOK];
static __device__ int   g_wbase[NWIN];
static __device__ int   g_wlenm1[NWIN];
// converted weight copies
static __device__ __nv_bfloat16 g_wq16[768 * 256];
static __device__ __nv_bfloat16 g_wp16[256 * 256];
static __device__ float g_w1[512 * 256];
static __device__ float g_w2[256 * 512];

// ---------------- helpers ---------------------------------------------------
__device__ __forceinline__ float to_tf32(float x) {
    unsigned r;
    asm("cvt.rna.tf32.f32 %0, %1;" : "=r"(r) : "f"(x));
    return __uint_as_float(r);
}
__device__ __forceinline__ float ex2(float x) {
    float r;
    asm("ex2.approx.f32 %0, %1;" : "=f"(r) : "f"(x));
    return r;
}
__device__ __forceinline__ uint32_t bf16x2(float lo, float hi) {
    uint32_t r;   // result = {hi, lo}
    asm("cvt.rn.bf16x2.f32 %0, %1, %2;" : "=r"(r) : "f"(hi), "f"(lo));
    return r;
}
__device__ __forceinline__ void ldsm4(uint32_t* r, uint32_t addr) {
    asm volatile("ldmatrix.sync.aligned.m8n8.x4.shared.b16 {%0,%1,%2,%3}, [%4];"
                 : "=r"(r[0]), "=r"(r[1]), "=r"(r[2]), "=r"(r[3]) : "r"(addr));
}
__device__ __forceinline__ void ldsm2(uint32_t* r, uint32_t addr) {
    asm volatile("ldmatrix.sync.aligned.m8n8.x2.shared.b16 {%0,%1}, [%2];"
                 : "=r"(r[0]), "=r"(r[1]) : "r"(addr));
}
__device__ __forceinline__ void mma_tf32(float* c, const uint32_t* a, const uint32_t* b) {
    asm volatile(
        "mma.sync.aligned.m16n8k8.row.col.f32.tf32.tf32.f32 "
        "{%0,%1,%2,%3}, {%4,%5,%6,%7}, {%8,%9}, {%0,%1,%2,%3};"
        : "+f"(c[0]), "+f"(c[1]), "+f"(c[2]), "+f"(c[3])
        : "r"(a[0]), "r"(a[1]), "r"(a[2]), "r"(a[3]), "r"(b[0]), "r"(b[1]));
}
__device__ __forceinline__ void mma_bf16(float* c, const uint32_t* a, const uint32_t* b) {
    asm volatile(
        "mma.sync.aligned.m16n8k16.row.col.f32.bf16.bf16.f32 "
        "{%0,%1,%2,%3}, {%4,%5,%6,%7}, {%8,%9}, {%0,%1,%2,%3};"
        : "+f"(c[0]), "+f"(c[1]), "+f"(c[2]), "+f"(c[3])
        : "r"(a[0]), "r"(a[1]), "r"(a[2]), "r"(a[3]), "r"(b[0]), "r"(b[1]));
}
__device__ __forceinline__ void cp16(uint32_t smem, const void* g) {
    asm volatile("cp.async.cg.shared.global [%0], [%1], 16;" :: "r"(smem), "l"(g));
}
__device__ __forceinline__ void cp16ca(uint32_t smem, const void* g) {
    asm volatile("cp.async.ca.shared.global [%0], [%1], 16;" :: "r"(smem), "l"(g));
}

// ---------------- mask + inverse index + window meta (merged) --------------
__global__ void mask_count_kernel(const int* __restrict__ win_idx,
                                  float* __restrict__ maskf,
                                  int* __restrict__ cnt,
                                  int* __restrict__ inv,
                                  int* __restrict__ wbase,
                                  int* __restrict__ wlenm1) {
    int r = blockIdx.x * 256 + threadIdx.x;
    if (r >= MW) return;
    int w = r & (WLEN - 1);
    int idx = win_idx[r];
    bool valid = (w == 0 || idx != win_idx[r - 1]);
    maskf[r] = valid ? 1.0f : 0.0f;
    if (valid) {
        int slot = atomicAdd(&cnt[idx], 1);
        if (slot < 2) inv[idx * 2 + slot] = r;
    }
    if (w == 0) {
        int m = r >> 9;
        wbase[m] = idx;
        wlenm1[m] = win_idx[r + WLEN - 1] - idx;
    }
}

// ---------------- merged weight conversion ---------------------------------
__global__ void cvt_all_kernel(const float* __restrict__ s0, __nv_bfloat16* __restrict__ d0,
                               const float* __restrict__ s1, __nv_bfloat16* __restrict__ d1,
                               const float* __restrict__ s2, float* __restrict__ d2,
                               const float* __restrict__ s3, float* __restrict__ d3) {
    int i = blockIdx.x * 256 + threadIdx.x;   // 524288 total
    if (i < 196608)      d0[i] = __float2bfloat16_rn(s0[i]);
    else if (i < 262144) d1[i - 196608] = __float2bfloat16_rn(s1[i - 196608]);
    else if (i < 393216) d2[i - 262144] = to_tf32(s2[i - 262144]);
    else                 d3[i - 393216] = to_tf32(s3[i - 393216]);
}

// ---------------- LayerNorm over C=256 -------------------------------------
template <int BF>
__global__ __launch_bounds__(256) void ln_kernel(const float* __restrict__ in,
                                                 const float* __restrict__ w,
                                                 const float* __restrict__ b,
                                                 float* __restrict__ outf,
                                                 __nv_bfloat16* __restrict__ outh,
                                                 int rows) {
    int warp = threadIdx.x >> 5, lane = threadIdx.x & 31;
    int row = blockIdx.x * 8 + warp;
    if (row >= rows) return;
    const float4* p = (const float4*)(in + (size_t)row * C_DIM);
    float4 v0 = p[lane * 2], v1 = p[lane * 2 + 1];
    float s = v0.x + v0.y + v0.z + v0.w + v1.x + v1.y + v1.z + v1.w;
    #pragma unroll
    for (int off = 16; off; off >>= 1) s += __shfl_xor_sync(FULLMASK, s, off);
    float mu = s * (1.0f / 256.0f);
    float d0 = v0.x - mu, d1 = v0.y - mu, d2 = v0.z - mu, d3 = v0.w - mu;
    float d4 = v1.x - mu, d5 = v1.y - mu, d6 = v1.z - mu, d7 = v1.w - mu;
    float s2 = d0*d0 + d1*d1 + d2*d2 + d3*d3 + d4*d4 + d5*d5 + d6*d6 + d7*d7;
    #pragma unroll
    for (int off = 16; off; off >>= 1) s2 += __shfl_xor_sync(FULLMASK, s2, off);
    float rs = rsqrtf(s2 * (1.0f / 256.0f) + 1e-5f);
    float4 w0 = ((const float4*)w)[lane * 2], w1 = ((const float4*)w)[lane * 2 + 1];
    float4 b0 = ((const float4*)b)[lane * 2], b1 = ((const float4*)b)[lane * 2 + 1];
    float r0 = d0 * rs * w0.x + b0.x, r1 = d1 * rs * w0.y + b0.y;
    float r2 = d2 * rs * w0.z + b0.z, r3 = d3 * rs * w0.w + b0.w;
    float r4 = d4 * rs * w1.x + b1.x, r5 = d5 * rs * w1.y + b1.y;
    float r6 = d6 * rs * w1.z + b1.z, r7 = d7 * rs * w1.w + b1.w;
    if (BF) {
        uint4 pk;
        pk.x = bf16x2(r0, r1); pk.y = bf16x2(r2, r3);
        pk.z = bf16x2(r4, r5); pk.w = bf16x2(r6, r7);
        *(uint4*)&outh[(size_t)row * C_DIM + lane * 8] = pk;
    } else {
        float4 o0 = make_float4(to_tf32(r0), to_tf32(r1), to_tf32(r2), to_tf32(r3));
        float4 o1 = make_float4(to_tf32(r4), to_tf32(r5), to_tf32(r6), to_tf32(r7));
        float4* q = (float4*)(outf + (size_t)row * C_DIM);
        q[lane * 2] = o0; q[lane * 2 + 1] = o1;
    }
}

// ---------------- gather proj + x1 + LayerNorm2 (fused) --------------------
__global__ __launch_bounds__(256) void x1ln2_kernel(
    const float* __restrict__ x, const float* __restrict__ projbuf,
    const int* __restrict__ cnt, const int* __restrict__ inv,
    const float* __restrict__ w, const float* __restrict__ b,
    float* __restrict__ x1, float* __restrict__ out) {
    int warp = threadIdx.x >> 5, lane = threadIdx.x & 31;
    int row = blockIdx.x * 8 + warp;
    int c = cnt[row];
    const float4* xp = (const float4*)(x + (size_t)row * C_DIM);
    float4 v0 = xp[lane * 2], v1 = xp[lane * 2 + 1];
    float4 y0 = make_float4(0.f, 0.f, 0.f, 0.f), y1 = y0;
    if (c >= 1) {
        const float4* p = (const float4*)(projbuf + (size_t)inv[row * 2] * C_DIM);
        y0 = p[lane * 2]; y1 = p[lane * 2 + 1];
    }
    if (c >= 2) {
        const float4* p = (const float4*)(projbuf + (size_t)inv[row * 2 + 1] * C_DIM);
        float4 a = p[lane * 2], bq = p[lane * 2 + 1];
        y0.x += a.x; y0.y += a.y; y0.z += a.z; y0.w += a.w;
        y1.x += bq.x; y1.y += bq.y; y1.z += bq.z; y1.w += bq.w;
    }
    float ic = 1.0f / fmaxf((float)c, 1.0f);
    v0.x += y0.x * ic; v0.y += y0.y * ic; v0.z += y0.z * ic; v0.w += y0.w * ic;
    v1.x += y1.x * ic; v1.y += y1.y * ic; v1.z += y1.z * ic; v1.w += y1.w * ic;
    float4* xq = (float4*)(x1 + (size_t)row * C_DIM);
    xq[lane * 2] = v0; xq[lane * 2 + 1] = v1;
    float s = v0.x + v0.y + v0.z + v0.w + v1.x + v1.y + v1.z + v1.w;
    #pragma unroll
    for (int off = 16; off; off >>= 1) s += __shfl_xor_sync(FULLMASK, s, off);
    float mu = s * (1.0f / 256.0f);
    float d0 = v0.x - mu, d1 = v0.y - mu, d2 = v0.z - mu, d3 = v0.w - mu;
    float d4 = v1.x - mu, d5 = v1.y - mu, d6 = v1.z - mu, d7 = v1.w - mu;
    float s2 = d0*d0 + d1*d1 + d2*d2 + d3*d3 + d4*d4 + d5*d5 + d6*d6 + d7*d7;
    #pragma unroll
    for (int off = 16; off; off >>= 1) s2 += __shfl_xor_sync(FULLMASK, s2, off);
    float rs = rsqrtf(s2 * (1.0f / 256.0f) + 1e-5f);
    float4 w0 = ((const float4*)w)[lane * 2], w1 = ((const float4*)w)[lane * 2 + 1];
    float4 b0 = ((const float4*)b)[lane * 2], b1 = ((const float4*)b)[lane * 2 + 1];
    float4 o0, o1;
    o0.x = to_tf32(d0 * rs * w0.x + b0.x); o0.y = to_tf32(d1 * rs * w0.y + b0.y);
    o0.z = to_tf32(d2 * rs * w0.z + b0.z); o0.w = to_tf32(d3 * rs * w0.w + b0.w);
    o1.x = to_tf32(d4 * rs * w1.x + b1.x); o1.y = to_tf32(d5 * rs * w1.y + b1.y);
    o1.z = to_tf32(d6 * rs * w1.z + b1.z); o1.w = to_tf32(d7 * rs * w1.w + b1.w);
    float4* q = (float4*)(out + (size_t)row * C_DIM);
    q[lane * 2] = o0; q[lane * 2 + 1] = o1;
}

// ---------------- FFN1: tf32 GEMM, 2-stage (2 CTAs/SM), fused BN partials --
// C = A.W1^T + b1 -> hbuf; also per-CTA column sums/sumsq of h -> part
// (unique writer per (m-block, col): deterministic).
#define GP 36
#define BUFW 9216
__global__ __launch_bounds__(256) void mma_ffn1(
    const float* __restrict__ A, const float* __restrict__ Bw,
    const float* __restrict__ bias, float* __restrict__ Cout,
    float* __restrict__ part) {
    const int KD = 256, NC = 512;
    extern __shared__ float sm[];
    uint32_t smem_u32 = (uint32_t)__cvta_generic_to_shared(sm);
    const int tid = threadIdx.x, lane = tid & 31, warp = tid >> 5;
    const int wm = warp >> 2, wn = warp & 3;
    const int bm = blockIdx.y * 128, bn = blockIdx.x * 128;

    const int lrow = tid & 127;
    const bool isA = tid < 128;
    const float* gbase;
    if (isA) gbase = A + (size_t)(bm + lrow) * KD;
    else     gbase = Bw + (size_t)(bn + lrow) * KD;
    const uint32_t sdst = smem_u32 + (uint32_t)(((isA ? 0 : 4608) + lrow * GP) * 4);

    const int lr8 = lane & 7, sub = lane >> 3, lb = lane & 15;
    const uint32_t a_off = smem_u32 +
        (uint32_t)(((wm * 64 + (sub & 1) * 8 + lr8) * GP + (sub >> 1) * 4) * 4);
    const uint32_t b_off = smem_u32 +
        (uint32_t)((4608 + (wn * 32 + (lb & 7)) * GP + (lb >> 3) * 4) * 4);

    float acc[4][4][4];
    #pragma unroll
    for (int i = 0; i < 4; i++)
        #pragma unroll
        for (int j = 0; j < 4; j++)
            #pragma unroll
            for (int r = 0; r < 4; r++) acc[i][j][r] = 0.f;

    const int T = KD / 32;   // 8
    {   // prologue: tile 0 -> stage 0
        #pragma unroll
        for (int i = 0; i < 8; i++) cp16(sdst + i * 16, gbase + i * 4);
        asm volatile("cp.async.commit_group;");
    }
    for (int t = 0; t < T; t++) {
        asm volatile("cp.async.wait_group 0;");
        __syncthreads();
        // prefetch t+1 into the other stage BEFORE mma (full-MMA overlap)
        if (t + 1 < T) {
            const float* g = gbase + (t + 1) * 32;
            uint32_t d = sdst + (uint32_t)(((t + 1) & 1) * BUFW * 4);
            #pragma unroll
            for (int i = 0; i < 8; i++) cp16(d + i * 16, g + i * 4);
        }
        asm volatile("cp.async.commit_group;");

        const uint32_t boff = (uint32_t)((t & 1) * BUFW * 4);
        #pragma unroll
        for (int ks = 0; ks < 4; ks++) {
            uint32_t a[4][4], b[4][2];
            #pragma unroll
            for (int i = 0; i < 4; i++)
                ldsm4(a[i], a_off + boff + i * 2304 + ks * 32);
            #pragma unroll
            for (int j = 0; j < 4; j++)
                ldsm2(b[j], b_off + boff + j * 1152 + ks * 32);
            #pragma unroll
            for (int i = 0; i < 4; i++)
                #pragma unroll
                for (int j = 0; j < 4; j++)
                    mma_tf32(acc[i][j], a[i], b[j]);
        }
    }

    // epilogue: store h = acc + bias; accumulate per-column sum/sumsq
    const int er = bm + wm * 64 + (lane >> 2);
    const int ec = bn + wn * 32 + (lane & 3) * 2;
    float cs[4][2], cq[4][2];
    #pragma unroll
    for (int j = 0; j < 4; j++) { cs[j][0] = cs[j][1] = 0.f; cq[j][0] = cq[j][1] = 0.f; }
    #pragma unroll
    for (int i = 0; i < 4; i++) {
        const int r0 = er + i * 16, r1 = r0 + 8;
        #pragma unroll
        for (int j = 0; j < 4; j++) {
            const int c = ec + j * 8;
            float b0 = bias[c], b1 = bias[c + 1];
            float h0 = acc[i][j][0] + b0, h1 = acc[i][j][1] + b1;
            float h2 = acc[i][j][2] + b0, h3 = acc[i][j][3] + b1;
            *(float2*)&Cout[(size_t)r0 * NC + c] = make_float2(h0, h1);
            *(float2*)&Cout[(size_t)r1 * NC + c] = make_float2(h2, h3);
            cs[j][0] += h0 + h2; cs[j][1] += h1 + h3;
            cq[j][0] += h0 * h0 + h2 * h2; cq[j][1] += h1 * h1 + h3 * h3;
        }
    }
    // reduce over the 8 row-lanes (same lane&3)
    #pragma unroll
    for (int j = 0; j < 4; j++)
        #pragma unroll
        for (int k = 0; k < 2; k++) {
            #pragma unroll
            for (int off = 4; off < 32; off <<= 1) {
                cs[j][k] += __shfl_xor_sync(FULLMASK, cs[j][k], off);
                cq[j][k] += __shfl_xor_sync(FULLMASK, cq[j][k], off);
            }
        }
    // stage smem is dead now (red area = stage0 A region, 512 floats)
    if ((lane >> 2) == 0) {
        #pragma unroll
        for (int j = 0; j < 4; j++)
            #pragma unroll
            for (int k = 0; k < 2; k++) {
                int cl = wn * 32 + lane * 2 + j * 8 + k;
                sm[wm * 128 + cl] = cs[j][k];
                sm[256 + wm * 128 + cl] = cq[j][k];
            }
    }
    __syncthreads();
    if (tid < 128) {
        float ssum = sm[tid] + sm[128 + tid];
        float qsum = sm[256 + tid] + sm[384 + tid];
        part[(size_t)blockIdx.y * HIDD + bn + tid] = ssum;
        part[(size_t)200 * HIDD + blockIdx.y * HIDD + bn + tid] = qsum;
    }
}

// ---------------- FFN2: tf32 GEMM, 2-stage, fused BN+ReLU on A -------------
__global__ __launch_bounds__(256) void mma_ffn2(
    const float* __restrict__ A, const float* __restrict__ Bw,
    const float* __restrict__ bias, const float* __restrict__ resid,
    const float* __restrict__ scale, const float* __restrict__ beta,
    float* __restrict__ Cout) {
    const int KD = 512, NC = 256;
    extern __shared__ float sm[];
    uint32_t smem_u32 = (uint32_t)__cvta_generic_to_shared(sm);
    const int tid = threadIdx.x, lane = tid & 31, warp = tid >> 5;
    const int wm = warp >> 2, wn = warp & 3;
    const int bm = blockIdx.y * 128, bn = blockIdx.x * 128;

    const int ar0 = tid >> 3, as0 = tid & 7;
    const bool isB = tid >= 128;
    const int brow = tid & 127;
    const float* gB = Bw + (size_t)(bn + brow) * KD;
    const uint32_t sdstB = smem_u32 + (uint32_t)((4608 + brow * GP) * 4);

    const int lr8 = lane & 7, sub = lane >> 3, lb = lane & 15;
    const uint32_t a_off = smem_u32 +
        (uint32_t)(((wm * 64 + (sub & 1) * 8 + lr8) * GP + (sub >> 1) * 4) * 4);
    const uint32_t b_off = smem_u32 +
        (uint32_t)((4608 + (wn * 32 + (lb & 7)) * GP + (lb >> 3) * 4) * 4);

    float acc[4][4][4];
    #pragma unroll
    for (int i = 0; i < 4; i++)
        #pragma unroll
        for (int j = 0; j < 4; j++)
            #pragma unroll
            for (int r = 0; r < 4; r++) acc[i][j][r] = 0.f;

    const int T = KD / 32;   // 16
    // prologue: A(0) transform+store to stage 0
    #pragma unroll
    for (int i = 0; i < 4; i++) {
        int row = ar0 + i * 32;
        int col = as0 * 4;
        float4 v = *(const float4*)(A + (size_t)(bm + row) * KD + col);
        float4 sc = __ldg((const float4*)&scale[col]);
        float4 be = __ldg((const float4*)&beta[col]);
        v.x = to_tf32(fmaxf(0.f, v.x * sc.x + be.x));
        v.y = to_tf32(fmaxf(0.f, v.y * sc.y + be.y));
        v.z = to_tf32(fmaxf(0.f, v.z * sc.z + be.z));
        v.w = to_tf32(fmaxf(0.f, v.w * sc.w + be.w));
        *(float4*)&sm[row * GP + col] = v;
    }
    // prologue: B(0)
    if (isB) {
        #pragma unroll
        for (int i = 0; i < 8; i++) cp16ca(sdstB + i * 16, gB + i * 4);
    }
    asm volatile("cp.async.commit_group;");

    for (int t = 0; t < T; t++) {
        asm volatile("cp.async.wait_group 0;");
        __syncthreads();

        float4 ap[4];
        if (t + 1 < T) {
            // LDG A(t+1) into regs; B(t+1) cp.async into other stage
            #pragma unroll
            for (int i = 0; i < 4; i++) {
                int row = ar0 + i * 32;
                ap[i] = *(const float4*)(A + (size_t)(bm + row) * KD +
                                         (t + 1) * 32 + as0 * 4);
            }
            if (isB) {
                const float* g = gB + (t + 1) * 32;
                uint32_t d = sdstB + (uint32_t)(((t + 1) & 1) * BUFW * 4);
                #pragma unroll
                for (int i = 0; i < 8; i++) cp16ca(d + i * 16, g + i * 4);
            }
        }
        asm volatile("cp.async.commit_group;");

        const uint32_t boff = (uint32_t)((t & 1) * BUFW * 4);
        #pragma unroll
        for (int ks = 0; ks < 4; ks++) {
            uint32_t a[4][4], b[4][2];
            #pragma unroll
            for (int i = 0; i < 4; i++)
                ldsm4(a[i], a_off + boff + i * 2304 + ks * 32);
            #pragma unroll
            for (int j = 0; j < 4; j++)
                ldsm2(b[j], b_off + boff + j * 1152 + ks * 32);
            #pragma unroll
            for (int i = 0; i < 4; i++)
                #pragma unroll
                for (int j = 0; j < 4; j++)
                    mma_tf32(acc[i][j], a[i], b[j]);
        }

        // transform + STS A(t+1) into the other stage (barrier-protected)
        if (t + 1 < T) {
            const uint32_t aoffS = (uint32_t)(((t + 1) & 1) * BUFW);
            int colb = (t + 1) * 32 + as0 * 4;
            float4 sc = __ldg((const float4*)&scale[colb]);
            float4 be = __ldg((const float4*)&beta[colb]);
            #pragma unroll
            for (int i = 0; i < 4; i++) {
                float4 v = ap[i];
                v.x = to_tf32(fmaxf(0.f, v.x * sc.x + be.x));
                v.y = to_tf32(fmaxf(0.f, v.y * sc.y + be.y));
                v.z = to_tf32(fmaxf(0.f, v.z * sc.z + be.z));
                v.w = to_tf32(fmaxf(0.f, v.w * sc.w + be.w));
                int row = ar0 + i * 32;
                *(float4*)&sm[aoffS + row * GP + as0 * 4] = v;
            }
        }
    }

    const int er = bm + wm * 64 + (lane >> 2);
    const int ec = bn + wn * 32 + (lane & 3) * 2;
    #pragma unroll
    for (int i = 0; i < 4; i++) {
        const int r0 = er + i * 16, r1 = r0 + 8;
        #pragma unroll
        for (int j = 0; j < 4; j++) {
            const int c = ec + j * 8;
            float b0 = bias[c], b1 = bias[c + 1];
            float2 x0 = *(const float2*)&resid[(size_t)r0 * 256 + c];
            float2 x1v = *(const float2*)&resid[(size_t)r1 * 256 + c];
            *(float2*)&Cout[(size_t)r0 * NC + c] =
                make_float2(acc[i][j][0] + b0 + x0.x, acc[i][j][1] + b1 + x0.y);
            *(float2*)&Cout[(size_t)r1 * NC + c] =
                make_float2(acc[i][j][2] + b0 + x1v.x, acc[i][j][3] + b1 + x1v.y);
        }
    }
}

// ---------------- bf16 tensor-core NT GEMM (BM=128, BN=128, BK=32) ---------
#define HP 40
#define BUFB 20480
#define NSTAGE 3
template <int MODE, int NC, int KD>
__global__ __launch_bounds__(256) void mma_gemm16(
    const __nv_bfloat16* __restrict__ A, const __nv_bfloat16* __restrict__ Bw,
    const float* __restrict__ bias, const float* __restrict__ maskf,
    float* __restrict__ Cf, __nv_bfloat16* __restrict__ Cb) {
    extern __shared__ char smc[];
    uint32_t smb = (uint32_t)__cvta_generic_to_shared(smc);
    const int tid = threadIdx.x, lane = tid & 31, warp = tid >> 5;
    const int wm = warp >> 2, wn = warp & 3;
    const int bm = blockIdx.y * 128, bn = blockIdx.x * 128;

    const int lrow = tid & 127;
    const bool isA = tid < 128;
    const __nv_bfloat16* gbase;
    if (isA) gbase = A + (size_t)(bm + lrow) * KD;
    else     gbase = Bw + (size_t)(bn + lrow) * KD;
    const uint32_t sdst = smb + (uint32_t)((isA ? 0 : 128 * 80) + lrow * 80);

    const uint32_t a_off = smb +
        (uint32_t)(((wm * 64 + (lane & 15)) * HP + (lane >> 4) * 8) * 2);
    const uint32_t b_off = smb + (uint32_t)(128 * 80) +
        (uint32_t)(((wn * 32 + (lane & 7)) * HP + ((lane >> 3) & 1) * 8) * 2);

    float acc[4][4][4];
    #pragma unroll
    for (int i = 0; i < 4; i++)
        #pragma unroll
        for (int j = 0; j < 4; j++)
            #pragma unroll
            for (int r = 0; r < 4; r++) acc[i][j][r] = 0.f;

    const int T = KD / 32;
    #pragma unroll
    for (int ps = 0; ps < NSTAGE - 1; ps++) {
        const __nv_bfloat16* g = gbase + ps * 32;
        uint32_t d = sdst + (uint32_t)(ps * BUFB);
        if (isA) {
            #pragma unroll
            for (int i = 0; i < 4; i++) cp16(d + i * 16, g + i * 8);
        } else {
            #pragma unroll
            for (int i = 0; i < 4; i++) cp16ca(d + i * 16, g + i * 8);
        }
        asm volatile("cp.async.commit_group;");
    }

    int buf = 0, nbuf = NSTAGE - 1;
    for (int t = 0; t < T; t++) {
        asm volatile("cp.async.wait_group %0;" :: "n"(NSTAGE - 2));
        __syncthreads();

        const uint32_t boff = (uint32_t)(buf * BUFB);
        #pragma unroll
        for (int ks = 0; ks < 2; ks++) {
            uint32_t a[4][4], b[4][2];
            #pragma unroll
            for (int i = 0; i < 4; i++)
                ldsm4(a[i], a_off + boff + (uint32_t)((i * 16 * HP + ks * 16) * 2));
            #pragma unroll
            for (int j = 0; j < 4; j++)
                ldsm2(b[j], b_off + boff + (uint32_t)((j * 8 * HP + ks * 16) * 2));
            #pragma unroll
            for (int i = 0; i < 4; i++)
                #pragma unroll
                for (int j = 0; j < 4; j++)
                    mma_bf16(acc[i][j], a[i], b[j]);
        }

        if (t + NSTAGE - 1 < T) {
            const __nv_bfloat16* g = gbase + (t + NSTAGE - 1) * 32;
            uint32_t d = sdst + (uint32_t)(nbuf * BUFB);
            if (isA) {
                #pragma unroll
                for (int i = 0; i < 4; i++) cp16(d + i * 16, g + i * 8);
            } else {
                #pragma unroll
                for (int i = 0; i < 4; i++) cp16ca(d + i * 16, g + i * 8);
            }
        }
        asm volatile("cp.async.commit_group;");
        buf = (buf + 1) % NSTAGE;
        nbuf = (nbuf + 1) % NSTAGE;
    }

    const int er = bm + wm * 64 + (lane >> 2);
    const int ec = bn + wn * 32 + (lane & 3) * 2;
    #pragma unroll
    for (int i = 0; i < 4; i++) {
        const int r0 = er + i * 16, r1 = r0 + 8;
        float mk0 = 0.f, mk1 = 0.f;
        if (MODE == 1) { mk0 = maskf[r0]; mk1 = maskf[r1]; }
        #pragma unroll
        for (int j = 0; j < 4; j++) {
            const int c = ec + j * 8;
            float v0 = acc[i][j][0], v1 = acc[i][j][1];
            float v2 = acc[i][j][2], v3 = acc[i][j][3];
            if (MODE == 0) {
                *(uint32_t*)&Cb[(size_t)r0 * NC + c] = bf16x2(v0, v1);
                *(uint32_t*)&Cb[(size_t)r1 * NC + c] = bf16x2(v2, v3);
            } else {
                float b0 = bias[c], b1 = bias[c + 1];
                *(float2*)&Cf[(size_t)r0 * NC + c] =
                    make_float2((v0 + b0) * mk0, (v1 + b1) * mk0);
                *(float2*)&Cf[(size_t)r1 * NC + c] =
                    make_float2((v2 + b0) * mk1, (v3 + b1) * mk1);
            }
        }
    }
}

// ---------------- bf16 tensor-core flash attention (no-max softmax) --------
#define ATPH 40
#define AT_QW_B 2048
#define AT_K_B  (2048 + 8 * 2560)     // 22528
#define AT_V_B  (AT_K_B + 2 * 2560)   // 27648
#define AT_SMEM_B (AT_V_B + 2 * 2560) // 32768
__global__ __launch_bounds__(256, 2) void attn_mma_kernel(
    const __nv_bfloat16* __restrict__ qkvtok,
    const int* __restrict__ wbase, const int* __restrict__ wlenm1,
    const float* __restrict__ maskf, __nv_bfloat16* __restrict__ attn) {
    extern __shared__ char smc[];
    const uint32_t smb = (uint32_t)__cvta_generic_to_shared(smc);
    const int m = blockIdx.x >> 4;
    const int h = (blockIdx.x >> 1) & 7;
    const int qh = blockIdx.x & 1;
    const int tid = threadIdx.x, lane = tid & 31, wp = tid >> 5;

    const int base = __ldg(&wbase[m]);
    const int lenm1 = __ldg(&wlenm1[m]);

    float* maskA = (float*)smc;
    char* Qw = smc + AT_QW_B + wp * 2560;

    const __nv_bfloat16* qk = qkvtok + h * 32;
    const int qrow0 = qh * 256 + wp * 32;

    for (int w = tid; w < 512; w += 256)
        maskA[w] = (maskf[m * 512 + w] != 0.f) ? 0.f : -1e30f;

    for (int i = lane; i < 128; i += 32) {
        int row = i >> 2, seg = i & 3;
        int tok = base + min(qrow0 + row, lenm1);
        uint4 v = *(const uint4*)(qk + (size_t)tok * 768 + seg * 8);
        *(uint4*)(Qw + row * (ATPH * 2) + seg * 16) = v;
    }
    __syncwarp();
    uint32_t qf[2][2][4];
    {
        uint32_t qb = smb + (uint32_t)(AT_QW_B + wp * 2560) +
                      (uint32_t)((((lane & 15)) * ATPH + (lane >> 4) * 8) * 2);
        #pragma unroll
        for (int i = 0; i < 2; i++)
            #pragma unroll
            for (int ks = 0; ks < 2; ks++)
                ldsm4(qf[i][ks], qb + (uint32_t)((i * 16 * ATPH + ks * 16) * 2));
    }
    __syncwarp();

    {
        int t2 = tid & 127, row = t2 >> 2, seg = t2 & 3;
        int tok = base + min(row, lenm1);
        if (tid < 128) {
            uint4 kv = *(const uint4*)(qk + (size_t)tok * 768 + 256 + seg * 8);
            *(uint4*)(smc + AT_K_B + row * 80 + seg * 16) = kv;
        } else {
            uint4 vv = *(const uint4*)(qk + (size_t)tok * 768 + 512 + seg * 8);
            const __nv_bfloat16* vp = (const __nv_bfloat16*)&vv;
            #pragma unroll
            for (int u = 0; u < 8; u++)
                *(__nv_bfloat16*)(smc + AT_V_B + (seg * 8 + u) * 80 + row * 2) = vp[u];
        }
    }
    __syncthreads();

    float o[2][4][4];
    #pragma unroll
    for (int i = 0; i < 2; i++)
        #pragma unroll
        for (int j = 0; j < 4; j++)
            #pragma unroll
            for (int c = 0; c < 4; c++) o[i][j][c] = 0.f;
    float Ls[2][2];
    #pragma unroll
    for (int i = 0; i < 2; i++) { Ls[i][0] = 0.f; Ls[i][1] = 0.f; }
    const float SCL2 = 0.25503485900582243f;
    const int ldrow = (tid & 127) >> 2, ldseg = tid & 3;

    for (int kt = 0; kt < 16; kt++) {
        const int cb = kt & 1;
        uint4 vpre;
        if (kt < 15) {
            int tok = base + min((kt + 1) * 32 + ldrow, lenm1);
            if (tid < 128) {
                cp16(smb + (uint32_t)(AT_K_B + (1 - cb) * 2560 + ldrow * 80 + ldseg * 16),
                     qk + (size_t)tok * 768 + 256 + ldseg * 8);
            } else {
                vpre = *(const uint4*)(qk + (size_t)tok * 768 + 512 + ldseg * 8);
            }
            asm volatile("cp.async.commit_group;");
        }

        float s[2][4][4];
        #pragma unroll
        for (int i = 0; i < 2; i++)
            #pragma unroll
            for (int j = 0; j < 4; j++)
                #pragma unroll
                for (int c = 0; c < 4; c++) s[i][j][c] = 0.f;
        {
            uint32_t kb = smb + (uint32_t)(AT_K_B + cb * 2560) +
                          (uint32_t)((((lane & 7)) * ATPH + ((lane >> 3) & 1) * 8) * 2);
            #pragma unroll
            for (int ks = 0; ks < 2; ks++) {
                uint32_t bf[4][2];
                #pragma unroll
                for (int j = 0; j < 4; j++)
                    ldsm2(bf[j], kb + (uint32_t)((j * 8 * ATPH + ks * 16) * 2));
                #pragma unroll
                for (int i = 0; i < 2; i++)
                    #pragma unroll
                    for (int j = 0; j < 4; j++)
                        mma_bf16(s[i][j], qf[i][ks], bf[j]);
            }
        }

        float mk[4][2];
        #pragma unroll
        for (int j = 0; j < 4; j++) {
            float2 mm = *(const float2*)&maskA[kt * 32 + j * 8 + 2 * (lane & 3)];
            mk[j][0] = mm.x; mk[j][1] = mm.y;
        }
        #pragma unroll
        for (int i = 0; i < 2; i++)
            #pragma unroll
            for (int j = 0; j < 4; j++)
                #pragma unroll
                for (int c = 0; c < 4; c++) {
                    float p = ex2(s[i][j][c] * SCL2 + mk[j][c & 1]);
                    s[i][j][c] = p;
                    Ls[i][c >> 1] += p;
                }

        {
            int r = lane >> 2, q2 = 2 * (lane & 3);
            #pragma unroll
            for (int i = 0; i < 2; i++)
                #pragma unroll
                for (int j = 0; j < 4; j++) {
                    *(uint32_t*)(Qw + ((i * 16 + r) * ATPH + j * 8 + q2) * 2) =
                        bf16x2(s[i][j][0], s[i][j][1]);
                    *(uint32_t*)(Qw + ((i * 16 + r + 8) * ATPH + j * 8 + q2) * 2) =
                        bf16x2(s[i][j][2], s[i][j][3]);
                }
        }
        __syncwarp();

        {
            uint32_t pb = smb + (uint32_t)(AT_QW_B + wp * 2560) +
                          (uint32_t)((((lane & 15)) * ATPH + (lane >> 4) * 8) * 2);
            uint32_t vb = smb + (uint32_t)(AT_V_B + cb * 2560) +
                          (uint32_t)((((lane & 7)) * ATPH + ((lane >> 3) & 1) * 8) * 2);
            #pragma unroll
            for (int ks = 0; ks < 2; ks++) {
                uint32_t pf[2][4], vf[4][2];
                #pragma unroll
                for (int i = 0; i < 2; i++)
                    ldsm4(pf[i], pb + (uint32_t)((i * 16 * ATPH + ks * 16) * 2));
                #pragma unroll
                for (int jd = 0; jd < 4; jd++)
                    ldsm2(vf[jd], vb + (uint32_t)((jd * 8 * ATPH + ks * 16) * 2));
                #pragma unroll
                for (int i = 0; i < 2; i++)
                    #pragma unroll
                    for (int jd = 0; jd < 4; jd++)
                        mma_bf16(o[i][jd], pf[i], vf[jd]);
            }
        }
        __syncwarp();

        if (kt < 15) {
            if (tid >= 128) {
                const __nv_bfloat16* vp = (const __nv_bfloat16*)&vpre;
                char* vt = smc + AT_V_B + (1 - cb) * 2560;
                #pragma unroll
                for (int u = 0; u < 8; u++)
                    *(__nv_bfloat16*)(vt + (ldseg * 8 + u) * 80 + ldrow * 2) = vp[u];
            }
            asm volatile("cp.async.wait_group 0;");
        }
        __syncthreads();
    }

    #pragma unroll
    for (int i = 0; i < 2; i++)
        #pragma unroll
        for (int rh = 0; rh < 2; rh++) {
            float v = Ls[i][rh];
            v += __shfl_xor_sync(FULLMASK, v, 1);
            v += __shfl_xor_sync(FULLMASK, v, 2);
            Ls[i][rh] = v;
        }
    {
        int r = lane >> 2, q2 = 2 * (lane & 3);
        #pragma unroll
        for (int i = 0; i < 2; i++) {
            float inv0 = 1.f / Ls[i][0], inv1 = 1.f / Ls[i][1];
            int row0 = m * 512 + qrow0 + i * 16 + r;
            #pragma unroll
            for (int jd = 0; jd < 4; jd++) {
                int col = h * 32 + jd * 8 + q2;
                *(uint32_t*)&attn[(size_t)row0 * 256 + col] =
                    bf16x2(o[i][jd][0] * inv0, o[i][jd][1] * inv0);
                *(uint32_t*)&attn[(size_t)(row0 + 8) * 256 + col] =
                    bf16x2(o[i][jd][2] * inv1, o[i][jd][3] * inv1);
            }
        }
    }
}

// ---------------- BN final (reads fused partials) --------------------------
__global__ void bn_final_kernel(const float* __restrict__ part,
                                const float* __restrict__ bn_w,
                                const float* __restrict__ bn_b,
                                float* __restrict__ scale, float* __restrict__ beta) {
    int col = blockIdx.x * 256 + threadIdx.x;
    float s = 0.f, s2 = 0.f;
    for (int b = 0; b < 200; b++) {
        s += part[b * HIDD + col];
        s2 += part[200 * HIDD + b * HIDD + col];
    }
    float mu = s * (1.0f / 25600.0f);
    float var = s2 * (1.0f / 25600.0f) - mu * mu;
    float sc = bn_w[col] * rsqrtf(var + 1e-5f);
    scale[col] = sc;
    beta[col] = bn_b[col] - mu * sc;
}

// ---------------- launch ----------------------------------------------------
extern "C" void kernel_launch(void* const* d_in, const int* in_sizes, int n_in,
                              void* d_out, int out_size) {
    (void)in_sizes; (void)n_in; (void)out_size;
    const float* x      = (const float*)d_in[0];
    const int*   widx   = (const int*)d_in[1];
    const float* ln1_w  = (const float*)d_in[3];
    const float* ln1_b  = (const float*)d_in[4];
    const float* w_qkv  = (const float*)d_in[5];
    const float* w_proj = (const float*)d_in[6];
    const float* b_proj = (const float*)d_in[7];
    const float* ln2_w  = (const float*)d_in[8];
    const float* ln2_b  = (const float*)d_in[9];
    const float* w1     = (const float*)d_in[10];
    const float* b1     = (const float*)d_in[11];
    const float* bn_w   = (const float*)d_in[12];
    const float* bn_b   = (const float*)d_in[13];
    const float* w2     = (const float*)d_in[14];
    const float* b2     = (const float*)d_in[15];
    float* out = (float*)d_out;

    float *xin, *projbuf, *x1, *hbuf, *part, *scale, *beta, *maskf;
    float *tw1, *tw2;
    __nv_bfloat16 *xin16, *qkvtok, *attn16, *wq16, *wp16;
    int *cnt, *inv, *wbase, *wlenm1;
    cudaGetSymbolAddress((void**)&xin16,  g_xin16);
    cudaGetSymbolAddress((void**)&xin,    g_xin);
    cudaGetSymbolAddress((void**)&qkvtok, g_qkvtok);
    cudaGetSymbolAddress((void**)&attn16, g_attn16);
    cudaGetSymbolAddress((void**)&projbuf,g_projbuf);
    cudaGetSymbolAddress((void**)&x1,     g_x1);
    cudaGetSymbolAddress((void**)&hbuf,   g_hbuf);
    cudaGetSymbolAddress((void**)&part,   g_bnpart);
    cudaGetSymbolAddress((void**)&scale,  g_scale);
    cudaGetSymbolAddress((void**)&beta,   g_beta);
    cudaGetSymbolAddress((void**)&maskf,  g_maskf);
    cudaGetSymbolAddress((void**)&cnt,    g_cnt);
    cudaGetSymbolAddress((void**)&inv,    g_inv);
    cudaGetSymbolAddress((void**)&wbase,  g_wbase);
    cudaGetSymbolAddress((void**)&wlenm1, g_wlenm1);
    cudaGetSymbolAddress((void**)&wq16,   g_wq16);
    cudaGetSymbolAddress((void**)&wp16,   g_wp16);
    cudaGetSymbolAddress((void**)&tw1,    g_w1);
    cudaGetSymbolAddress((void**)&tw2,    g_w2);

    const int ffn_smem = 2 * BUFW * (int)sizeof(float);   // 73728 -> 2 CTAs/SM
    cudaFuncSetAttribute(mma_ffn1,
                         cudaFuncAttributeMaxDynamicSharedMemorySize, ffn_smem);
    cudaFuncSetAttribute(mma_ffn2,
                         cudaFuncAttributeMaxDynamicSharedMemorySize, ffn_smem);
    const int gemm16_smem = NSTAGE * BUFB;   // 61440
    cudaFuncSetAttribute(mma_gemm16<0, 768, 256>,
                         cudaFuncAttributeMaxDynamicSharedMemorySize, gemm16_smem);
    cudaFuncSetAttribute(mma_gemm16<1, 256, 256>,
                         cudaFuncAttributeMaxDynamicSharedMemorySize, gemm16_smem);
    cudaFuncSetAttribute(attn_mma_kernel,
                         cudaFuncAttributeMaxDynamicSharedMemorySize, AT_SMEM_B);

    cudaMemsetAsync(cnt, 0, N_TOK * sizeof(int));

    cvt_all_kernel<<<2048, 256>>>(w_qkv, wq16, w_proj, wp16, w1, tw1, w2, tw2);
    mask_count_kernel<<<MW / 256, 256>>>(widx, maskf, cnt, inv, wbase, wlenm1);
    ln_kernel<1><<<N_TOK / 8, 256>>>(x, ln1_w, ln1_b, nullptr, xin16, N_TOK);

    mma_gemm16<0, 768, 256><<<dim3(6, 200), 256, gemm16_smem>>>(
        xin16, wq16, nullptr, nullptr, nullptr, qkvtok);

    attn_mma_kernel<<<100 * HEADS * 2, 256, AT_SMEM_B>>>(
        qkvtok, wbase, wlenm1, maskf, attn16);

    mma_gemm16<1, 256, 256><<<dim3(2, 400), 256, gemm16_smem>>>(
        attn16, wp16, b_proj, maskf, projbuf, nullptr);

    x1ln2_kernel<<<N_TOK / 8, 256>>>(x, projbuf, cnt, inv, ln2_w, ln2_b, x1, xin);

    mma_ffn1<<<dim3(4, 200), 256, ffn_smem>>>(xin, tw1, b1, hbuf, part);

    bn_final_kernel<<<2, 256>>>(part, bn_w, bn_b, scale, beta);

    mma_ffn2<<<dim3(2, 200), 256, ffn_smem>>>(
        hbuf, tw2, b2, x1, scale, beta, out);
}